// round 1
// baseline (speedup 1.0000x reference)
#include <cuda_runtime.h>

// Problem constants (fixed by the reference)
#define B_  8
#define S_  2048
#define D_  512
#define H_  8
#define DH_ 64
#define M_  (B_ * S_)          // 16384 rows for all projections

// Scratch (allocation-free rule: __device__ globals)
__device__ float g_Qt[B_ * H_ * DH_ * S_];   // [b,h,d,s]  (d-major for attention)
__device__ float g_Kt[B_ * H_ * DH_ * S_];   // [b,h,d,s]
__device__ float g_V [B_ * H_ * S_ * DH_];   // [b,h,s,d]
__device__ float g_ctx[M_ * D_];             // [b,s, h*dh]

__device__ __forceinline__ float ex2f(float x) {
    float y;
    asm("ex2.approx.f32 %0, %1;" : "=f"(y) : "f"(x));
    return y;
}

// ---------------------------------------------------------------------------
// Projection GEMM:  C[M,512] = A[M,512] @ W[512,512]^T + bias, times scale.
// A row-major (K contiguous), W row-major [N,K] (K contiguous) -> "NT" gemm.
// 64x64 tile, BK=16, 256 threads, 4x4 microtile.
// mode 0: write [b,h,d,s]   (Q/K, d-major)
// mode 1: write [b,h,s,d]   (V)
// mode 2: write row-major [M,512]   (ctx / final output)
// ---------------------------------------------------------------------------
__global__ __launch_bounds__(256) void proj_gemm(
    const float* __restrict__ A, const float* __restrict__ W,
    const float* __restrict__ bias, float* __restrict__ out,
    float scale, int mode)
{
    __shared__ float sA[64][20];   // [m][k], stride 20 (16B-aligned rows)
    __shared__ float sW[16][68];   // [k][n], stride 68 (16B-aligned rows)

    const int m0 = blockIdx.x * 64;
    const int n0 = blockIdx.y * 64;
    const int tid = threadIdx.x;
    const int tx = tid & 15;       // 0..15  (n microtile)
    const int ty = tid >> 4;       // 0..15  (m microtile)
    const int lr = tid >> 2;       // 0..63  (load row)
    const int lk = (tid & 3) * 4;  // 0,4,8,12 (load k-offset, float4)

    float acc[4][4] = {};

    for (int kt = 0; kt < 512; kt += 16) {
        float4 av = *(const float4*)&A[(size_t)(m0 + lr) * 512 + kt + lk];
        float4 wv = *(const float4*)&W[(size_t)(n0 + lr) * 512 + kt + lk];
        *(float4*)&sA[lr][lk] = av;
        sW[lk + 0][lr] = wv.x;
        sW[lk + 1][lr] = wv.y;
        sW[lk + 2][lr] = wv.z;
        sW[lk + 3][lr] = wv.w;
        __syncthreads();

#pragma unroll
        for (int k = 0; k < 16; ++k) {
            float a0 = sA[ty * 4 + 0][k];
            float a1 = sA[ty * 4 + 1][k];
            float a2 = sA[ty * 4 + 2][k];
            float a3 = sA[ty * 4 + 3][k];
            float4 bb = *(const float4*)&sW[k][tx * 4];
            acc[0][0] += a0 * bb.x; acc[0][1] += a0 * bb.y; acc[0][2] += a0 * bb.z; acc[0][3] += a0 * bb.w;
            acc[1][0] += a1 * bb.x; acc[1][1] += a1 * bb.y; acc[1][2] += a1 * bb.z; acc[1][3] += a1 * bb.w;
            acc[2][0] += a2 * bb.x; acc[2][1] += a2 * bb.y; acc[2][2] += a2 * bb.z; acc[2][3] += a2 * bb.w;
            acc[3][0] += a3 * bb.x; acc[3][1] += a3 * bb.y; acc[3][2] += a3 * bb.z; acc[3][3] += a3 * bb.w;
        }
        __syncthreads();
    }

    // Epilogue
    float bv[4];
#pragma unroll
    for (int j = 0; j < 4; ++j) bv[j] = bias[n0 + tx * 4 + j];

    if (mode == 2) {
#pragma unroll
        for (int i = 0; i < 4; ++i) {
            int m = m0 + ty * 4 + i;
            float4 c;
            c.x = (acc[i][0] + bv[0]) * scale;
            c.y = (acc[i][1] + bv[1]) * scale;
            c.z = (acc[i][2] + bv[2]) * scale;
            c.w = (acc[i][3] + bv[3]) * scale;
            *(float4*)&out[(size_t)m * 512 + n0 + tx * 4] = c;
        }
    } else {
#pragma unroll
        for (int i = 0; i < 4; ++i) {
            int m = m0 + ty * 4 + i;
            int b = m / S_;
            int s = m - b * S_;
#pragma unroll
            for (int j = 0; j < 4; ++j) {
                int n = n0 + tx * 4 + j;
                int h = n >> 6;
                int d = n & 63;
                float c = (acc[i][j] + bv[j]) * scale;
                if (mode == 0) {
                    out[(((size_t)(b * H_ + h)) * DH_ + d) * S_ + s] = c;
                } else {
                    out[(((size_t)(b * H_ + h)) * S_ + s) * DH_ + d] = c;
                }
            }
        }
    }
}

// ---------------------------------------------------------------------------
// Flash attention: 64q x 64k tiles, DH=64, online softmax in registers.
// Q,K in [b,h,d,s] (d-major), V in [b,h,s,d]. ctx out: [b,s,h*dh].
// Q is pre-scaled by (1/sqrt(DH)) * log2(e), so exp == ex2.
// ---------------------------------------------------------------------------
#define LDS_ 68

__global__ __launch_bounds__(256) void attn_kernel(
    const float* __restrict__ Qt, const float* __restrict__ Kt,
    const float* __restrict__ V, const int* __restrict__ lens,
    float* __restrict__ ctx)
{
    extern __shared__ float sm[];
    float* sQ = sm;                 // [d][q]  64 x 68
    float* sK = sm + 64 * LDS_;     // [d][k]
    float* sV = sm + 2 * 64 * LDS_; // [k][d]
    float* sP = sm + 3 * 64 * LDS_; // [q][k]

    const int q0 = blockIdx.x * 64;
    const int h = blockIdx.y;
    const int b = blockIdx.z;
    const int len = lens[b];
    const int tid = threadIdx.x;
    const int tx = tid & 15;
    const int ty = tid >> 4;

    const float* Qbh = Qt + ((size_t)(b * H_ + h)) * DH_ * S_;
    const float* Kbh = Kt + ((size_t)(b * H_ + h)) * DH_ * S_;
    const float* Vbh = V  + ((size_t)(b * H_ + h)) * S_ * DH_;

    // Load Q tile [d=64][q=64]
#pragma unroll
    for (int r = 0; r < 4; ++r) {
        int idx = tid + r * 256;
        int d = idx >> 4;
        int c4 = (idx & 15) * 4;
        float4 v = *(const float4*)&Qbh[(size_t)d * S_ + q0 + c4];
        *(float4*)&sQ[d * LDS_ + c4] = v;
    }

    float o[4][4] = {};
    float mrow[4] = {-1e30f, -1e30f, -1e30f, -1e30f};
    float lrow[4] = {};

    const int nkt = (len + 63) >> 6;

    for (int t = 0; t < nkt; ++t) {
        const int kt0 = t * 64;

        // Load K tile [d][k] and V tile [k][d]
#pragma unroll
        for (int r = 0; r < 4; ++r) {
            int idx = tid + r * 256;
            int row = idx >> 4;
            int c4 = (idx & 15) * 4;
            float4 kv = *(const float4*)&Kbh[(size_t)row * S_ + kt0 + c4];
            *(float4*)&sK[row * LDS_ + c4] = kv;
            float4 vv = *(const float4*)&Vbh[(size_t)(kt0 + row) * DH_ + c4];
            *(float4*)&sV[row * LDS_ + c4] = vv;
        }
        __syncthreads();

        // Phase 1: S = Q^T K  (64x64, over d)
        float s[4][4] = {};
#pragma unroll 8
        for (int d = 0; d < 64; ++d) {
            float4 aa = *(const float4*)&sQ[d * LDS_ + ty * 4];
            float4 bb = *(const float4*)&sK[d * LDS_ + tx * 4];
            s[0][0] += aa.x * bb.x; s[0][1] += aa.x * bb.y; s[0][2] += aa.x * bb.z; s[0][3] += aa.x * bb.w;
            s[1][0] += aa.y * bb.x; s[1][1] += aa.y * bb.y; s[1][2] += aa.y * bb.z; s[1][3] += aa.y * bb.w;
            s[2][0] += aa.z * bb.x; s[2][1] += aa.z * bb.y; s[2][2] += aa.z * bb.z; s[2][3] += aa.z * bb.w;
            s[3][0] += aa.w * bb.x; s[3][1] += aa.w * bb.y; s[3][2] += aa.w * bb.z; s[3][3] += aa.w * bb.w;
        }

        // Mask tail keys (key index >= len)
        if (kt0 + 64 > len) {
#pragma unroll
            for (int j = 0; j < 4; ++j) {
                if (kt0 + tx * 4 + j >= len) {
#pragma unroll
                    for (int i = 0; i < 4; ++i) s[i][j] = -1e30f;
                }
            }
        }

        // Online softmax, per row (rows = ty*4+i). Row group = 16 lanes (same ty).
#pragma unroll
        for (int i = 0; i < 4; ++i) {
            float mx = fmaxf(fmaxf(s[i][0], s[i][1]), fmaxf(s[i][2], s[i][3]));
#pragma unroll
            for (int off = 8; off >= 1; off >>= 1)
                mx = fmaxf(mx, __shfl_xor_sync(0xffffffffu, mx, off));
            float mnew = fmaxf(mrow[i], mx);
            float esc = ex2f(mrow[i] - mnew);
            mrow[i] = mnew;

            float ls = 0.f;
#pragma unroll
            for (int j = 0; j < 4; ++j) {
                float p = ex2f(s[i][j] - mnew);
                s[i][j] = p;
                ls += p;
            }
#pragma unroll
            for (int off = 8; off >= 1; off >>= 1)
                ls += __shfl_xor_sync(0xffffffffu, ls, off);

            lrow[i] = lrow[i] * esc + ls;
#pragma unroll
            for (int j = 0; j < 4; ++j) o[i][j] *= esc;
        }

        // Store P tile [q][k]
#pragma unroll
        for (int i = 0; i < 4; ++i) {
            float4 p4 = make_float4(s[i][0], s[i][1], s[i][2], s[i][3]);
            *(float4*)&sP[(ty * 4 + i) * LDS_ + tx * 4] = p4;
        }
        __syncthreads();

        // Phase 3: O += P @ V  (over k)
#pragma unroll 8
        for (int k = 0; k < 64; ++k) {
            float a0 = sP[(ty * 4 + 0) * LDS_ + k];
            float a1 = sP[(ty * 4 + 1) * LDS_ + k];
            float a2 = sP[(ty * 4 + 2) * LDS_ + k];
            float a3 = sP[(ty * 4 + 3) * LDS_ + k];
            float4 bb = *(const float4*)&sV[k * LDS_ + tx * 4];
            o[0][0] += a0 * bb.x; o[0][1] += a0 * bb.y; o[0][2] += a0 * bb.z; o[0][3] += a0 * bb.w;
            o[1][0] += a1 * bb.x; o[1][1] += a1 * bb.y; o[1][2] += a1 * bb.z; o[1][3] += a1 * bb.w;
            o[2][0] += a2 * bb.x; o[2][1] += a2 * bb.y; o[2][2] += a2 * bb.z; o[2][3] += a2 * bb.w;
            o[3][0] += a3 * bb.x; o[3][1] += a3 * bb.y; o[3][2] += a3 * bb.z; o[3][3] += a3 * bb.w;
        }
        __syncthreads();
    }

    // Write ctx [b, s, h*64 + d]
#pragma unroll
    for (int i = 0; i < 4; ++i) {
        float inv = 1.0f / lrow[i];
        int sgl = q0 + ty * 4 + i;
        float4 c;
        c.x = o[i][0] * inv;
        c.y = o[i][1] * inv;
        c.z = o[i][2] * inv;
        c.w = o[i][3] * inv;
        *(float4*)&ctx[(size_t)(b * S_ + sgl) * 512 + h * 64 + tx * 4] = c;
    }
}

// ---------------------------------------------------------------------------

extern "C" void kernel_launch(void* const* d_in, const int* in_sizes, int n_in,
                              void* d_out, int out_size)
{
    const float* x_Q = (const float*)d_in[0];
    const float* x_K = (const float*)d_in[1];
    const float* x_V = (const float*)d_in[2];
    const float* Wq  = (const float*)d_in[3];
    const float* bq  = (const float*)d_in[4];
    const float* Wk  = (const float*)d_in[5];
    const float* bk  = (const float*)d_in[6];
    const float* Wv  = (const float*)d_in[7];
    const float* bv  = (const float*)d_in[8];
    const float* Wo  = (const float*)d_in[9];
    const float* bo  = (const float*)d_in[10];
    const int*   lens = (const int*)d_in[11];
    float* out = (float*)d_out;

    float *Qt, *Kt, *Vd, *ctx;
    cudaGetSymbolAddress((void**)&Qt,  g_Qt);
    cudaGetSymbolAddress((void**)&Kt,  g_Kt);
    cudaGetSymbolAddress((void**)&Vd,  g_V);
    cudaGetSymbolAddress((void**)&ctx, g_ctx);

    const int smem_attn = 4 * 64 * LDS_ * sizeof(float);
    cudaFuncSetAttribute(attn_kernel, cudaFuncAttributeMaxDynamicSharedMemorySize, smem_attn);

    // scale = 1/sqrt(DH) * log2(e), folded into Q projection (incl. bias)
    const float qscale = 0.125f * 1.4426950408889634f;

    dim3 gproj(M_ / 64, D_ / 64);
    proj_gemm<<<gproj, 256>>>(x_Q, Wq, bq, Qt, qscale, 0);
    proj_gemm<<<gproj, 256>>>(x_K, Wk, bk, Kt, 1.0f, 0);
    proj_gemm<<<gproj, 256>>>(x_V, Wv, bv, Vd, 1.0f, 1);

    dim3 gattn(S_ / 64, H_, B_);
    attn_kernel<<<gattn, 256, smem_attn>>>(Qt, Kt, Vd, lens, ctx);

    proj_gemm<<<gproj, 256>>>(ctx, Wo, bo, out, 1.0f, 2);
}

// round 5
// speedup vs baseline: 1.3549x; 1.3549x over previous
#include <cuda_runtime.h>
#include <cuda_bf16.h>
#include <cstdint>

// Problem constants (fixed by the reference)
#define B_  8
#define S_  2048
#define D_  512
#define H_  8
#define DH_ 64
#define M_  (B_ * S_)          // 16384 rows for all projections

// Scratch (allocation-free rule: __device__ globals)
__device__ float g_Qt[B_ * H_ * DH_ * S_];   // [b,h,d,s]  (d-major for attention)
__device__ float g_Kt[B_ * H_ * DH_ * S_];   // [b,h,d,s]
__device__ float g_V [B_ * H_ * S_ * DH_];   // [b,h,s,d]
__device__ float g_ctx[M_ * D_];             // [b,s, h*dh]

__device__ __forceinline__ float ex2f(float x) {
    float y;
    asm("ex2.approx.f32 %0, %1;" : "=f"(y) : "f"(x));
    return y;
}

__device__ __forceinline__ uint32_t smem_u32(const void* p) {
    uint32_t a;
    asm("{ .reg .u64 t; cvta.to.shared.u64 t, %1; cvt.u32.u64 %0, t; }" : "=r"(a) : "l"(p));
    return a;
}

__device__ __forceinline__ void ldmatrix4(uint32_t* r, uint32_t addr) {
    asm volatile("ldmatrix.sync.aligned.m8n8.x4.shared.b16 {%0,%1,%2,%3}, [%4];"
                 : "=r"(r[0]), "=r"(r[1]), "=r"(r[2]), "=r"(r[3]) : "r"(addr));
}

__device__ __forceinline__ void mma_bf16(float* d, const uint32_t* a,
                                         uint32_t b0, uint32_t b1) {
    asm volatile(
        "mma.sync.aligned.m16n8k16.row.col.f32.bf16.bf16.f32 "
        "{%0,%1,%2,%3}, {%4,%5,%6,%7}, {%8,%9}, {%0,%1,%2,%3};"
        : "+f"(d[0]), "+f"(d[1]), "+f"(d[2]), "+f"(d[3])
        : "r"(a[0]), "r"(a[1]), "r"(a[2]), "r"(a[3]), "r"(b0), "r"(b1));
}

// fp32 -> (hi, lo) bf16 pair packed in one u32 (hi in low half = k'=2k position)
__device__ __forceinline__ uint32_t bfsplit(float f) {
    __nv_bfloat16 h = __float2bfloat16_rn(f);
    float hf = __bfloat162float(h);
    __nv_bfloat16 l = __float2bfloat16_rn(f - hf);
    return (uint32_t)__bfloat16_as_ushort(h) | ((uint32_t)__bfloat16_as_ushort(l) << 16);
}

// swap 16-bit halves of a packed bf16x2 (hi<->lo) for cross-term MMA
__device__ __forceinline__ uint32_t swap16(uint32_t x) {
    return __byte_perm(x, x, 0x1032);
}

// ============================================================================
// Split-bf16 emulated-fp32 projection GEMM via mma.sync.m16n8k16
//   C[M,512] = A[M,512] @ W[512,512]^T,  out = (C + bias) * scale
//   a = hi + lo (bf16 each), interleaved along K -> effective K' = 1024.
//   Each fragment pair does TWO MMAs: normal (hi*hi + lo*lo) and half-swapped
//   B (hi*lo + lo*hi), recovering the exact (hi+lo)(hi'+lo') product.
//   CTA: 128m x 128n, chunk = 32 fp32 k, double-buffered, 512 threads.
//   mode 0: [b,h,d,s] (Q/K)  mode 1: [b,h,s,d] (V)  mode 2: row-major [M,512]
// ============================================================================
#define PJ_STAGE_B 32768                // A tile 16KB + W tile 16KB (bf16)
#define PJ_SMEM_B  (2 * PJ_STAGE_B)     // 65536 bytes

__global__ __launch_bounds__(512) void proj_mma(
    const float* __restrict__ A, const float* __restrict__ W,
    const float* __restrict__ bias, float* __restrict__ out,
    float scale, int mode)
{
    extern __shared__ __align__(16) char smem[];
    const uint32_t sbase = smem_u32(smem);

    const int tid = threadIdx.x;
    const int lane = tid & 31;
    const int warp = tid >> 5;
    const int wm = warp >> 2;          // 0..3
    const int wn = warp & 3;           // 0..3
    const int m0 = blockIdx.y * 128;
    const int n0 = blockIdx.x * 128;

    const int lrow = tid >> 2;         // 0..127 (loader row)
    const int lk8  = (tid & 3) * 8;    // fp32 k offset within 32-chunk

    float4 ra[2], rw[2];

    auto ldg = [&](int it) {
        const float* As = A + (size_t)(m0 + lrow) * 512 + it * 32 + lk8;
        const float* Ws = W + (size_t)(n0 + lrow) * 512 + it * 32 + lk8;
        ra[0] = *(const float4*)(As + 0);
        ra[1] = *(const float4*)(As + 4);
        rw[0] = *(const float4*)(Ws + 0);
        rw[1] = *(const float4*)(Ws + 4);
    };

    auto sts = [&](int st) {
        char* base = smem + st * PJ_STAGE_B + lrow * 128;
#pragma unroll
        for (int j = 0; j < 2; ++j) {
            int seg = (tid & 3) * 2 + j;
            uint32_t off = 16u * (uint32_t)(seg ^ (lrow & 7));
            uint4 pa, pw;
            pa.x = bfsplit(j ? ra[1].x : ra[0].x);
            pa.y = bfsplit(j ? ra[1].y : ra[0].y);
            pa.z = bfsplit(j ? ra[1].z : ra[0].z);
            pa.w = bfsplit(j ? ra[1].w : ra[0].w);
            pw.x = bfsplit(j ? rw[1].x : rw[0].x);
            pw.y = bfsplit(j ? rw[1].y : rw[0].y);
            pw.z = bfsplit(j ? rw[1].z : rw[0].z);
            pw.w = bfsplit(j ? rw[1].w : rw[0].w);
            *(uint4*)(base + off) = pa;
            *(uint4*)(base + 16384 + off) = pw;
        }
    };

    float d[2][4][4] = {};
    const int r8 = (lane & 7) + ((lane >> 3) & 1) * 8;   // 0..15 row-in-tile
    const int sh = lane >> 4;                            // 0/1 seg offset

    // ---- prologue ----
    ldg(0);
    sts(0);
    ldg(1);
    __syncthreads();

    for (int i = 0; i < 16; ++i) {
        // compute on stage i&1
        {
            const uint32_t aB = sbase + (i & 1) * PJ_STAGE_B;
            const uint32_t bB = aB + 16384;
#pragma unroll
            for (int ks = 0; ks < 4; ++ks) {
                uint32_t a[2][4], bfr[2][4];
                const int seg = 2 * ks + sh;
#pragma unroll
                for (int mt = 0; mt < 2; ++mt) {
                    int row = wm * 32 + mt * 16 + r8;
                    ldmatrix4(a[mt], aB + row * 128 + 16 * (seg ^ (row & 7)));
                }
#pragma unroll
                for (int g = 0; g < 2; ++g) {
                    int nrow = wn * 32 + g * 16 + r8;
                    ldmatrix4(bfr[g], bB + nrow * 128 + 16 * (seg ^ (nrow & 7)));
                }
#pragma unroll
                for (int g = 0; g < 2; ++g)
#pragma unroll
                    for (int q = 0; q < 2; ++q) {
                        const int nt = g * 2 + q;
                        const uint32_t b0 = bfr[g][q];
                        const uint32_t b1 = bfr[g][q + 2];
                        const uint32_t s0 = swap16(b0);
                        const uint32_t s1 = swap16(b1);
#pragma unroll
                        for (int mt = 0; mt < 2; ++mt) {
                            mma_bf16(d[mt][nt], a[mt], b0, b1);  // hi*hi + lo*lo
                            mma_bf16(d[mt][nt], a[mt], s0, s1);  // hi*lo + lo*hi
                        }
                    }
            }
        }
        __syncthreads();

        if (i < 15) {
            sts((i + 1) & 1);            // regs hold chunk i+1
            if (i < 14) ldg(i + 2);
            __syncthreads();
        }
    }

    // ---- epilogue (C frag: lane row = lane/4 (+8), col = (lane%4)*2 (+1)) ----
    const int rql = lane >> 2;
    const int cql = (lane & 3) * 2;
#pragma unroll
    for (int mt = 0; mt < 2; ++mt) {
        int mbase = m0 + wm * 32 + mt * 16 + rql;
#pragma unroll
        for (int nt = 0; nt < 4; ++nt) {
            int n = n0 + wn * 32 + nt * 8 + cql;
            float2 bv = *(const float2*)&bias[n];
#pragma unroll
            for (int rr = 0; rr < 2; ++rr) {
                int m = mbase + rr * 8;
                float v0 = (d[mt][nt][rr * 2 + 0] + bv.x) * scale;
                float v1 = (d[mt][nt][rr * 2 + 1] + bv.y) * scale;
                int b = m >> 11, s = m & 2047;
                if (mode == 0) {
                    int h = n >> 6, dd = n & 63;
                    float* p = out + (((size_t)(b * H_ + h)) * DH_ + dd) * S_ + s;
                    p[0] = v0;
                    p[S_] = v1;          // d and d+1 differ by S_ stride
                } else if (mode == 1) {
                    int h = n >> 6, dd = n & 63;
                    float2 v = make_float2(v0, v1);
                    *(float2*)&out[(((size_t)(b * H_ + h)) * S_ + s) * DH_ + dd] = v;
                } else {
                    float2 v = make_float2(v0, v1);
                    *(float2*)&out[(size_t)m * 512 + n] = v;
                }
            }
        }
    }
}

// ---------------------------------------------------------------------------
// Flash attention (unchanged, validated in R1): 64q x 64k tiles, fp32 SIMT.
// Q,K in [b,h,d,s] (d-major), V in [b,h,s,d]. ctx out: [b,s,h*dh].
// Q is pre-scaled by (1/sqrt(DH)) * log2(e), so exp == ex2.
// ---------------------------------------------------------------------------
#define LDS_ 68

__global__ __launch_bounds__(256) void attn_kernel(
    const float* __restrict__ Qt, const float* __restrict__ Kt,
    const float* __restrict__ V, const int* __restrict__ lens,
    float* __restrict__ ctx)
{
    extern __shared__ float sm[];
    float* sQ = sm;                 // [d][q]  64 x 68
    float* sK = sm + 64 * LDS_;     // [d][k]
    float* sV = sm + 2 * 64 * LDS_; // [k][d]
    float* sP = sm + 3 * 64 * LDS_; // [q][k]

    const int q0 = blockIdx.x * 64;
    const int h = blockIdx.y;
    const int b = blockIdx.z;
    const int len = lens[b];
    const int tid = threadIdx.x;
    const int tx = tid & 15;
    const int ty = tid >> 4;

    const float* Qbh = Qt + ((size_t)(b * H_ + h)) * DH_ * S_;
    const float* Kbh = Kt + ((size_t)(b * H_ + h)) * DH_ * S_;
    const float* Vbh = V  + ((size_t)(b * H_ + h)) * S_ * DH_;

#pragma unroll
    for (int r = 0; r < 4; ++r) {
        int idx = tid + r * 256;
        int d = idx >> 4;
        int c4 = (idx & 15) * 4;
        float4 v = *(const float4*)&Qbh[(size_t)d * S_ + q0 + c4];
        *(float4*)&sQ[d * LDS_ + c4] = v;
    }

    float o[4][4] = {};
    float mrow[4] = {-1e30f, -1e30f, -1e30f, -1e30f};
    float lrow[4] = {};

    const int nkt = (len + 63) >> 6;

    for (int t = 0; t < nkt; ++t) {
        const int kt0 = t * 64;

#pragma unroll
        for (int r = 0; r < 4; ++r) {
            int idx = tid + r * 256;
            int row = idx >> 4;
            int c4 = (idx & 15) * 4;
            float4 kv = *(const float4*)&Kbh[(size_t)row * S_ + kt0 + c4];
            *(float4*)&sK[row * LDS_ + c4] = kv;
            float4 vv = *(const float4*)&Vbh[(size_t)(kt0 + row) * DH_ + c4];
            *(float4*)&sV[row * LDS_ + c4] = vv;
        }
        __syncthreads();

        float s[4][4] = {};
#pragma unroll 8
        for (int d = 0; d < 64; ++d) {
            float4 aa = *(const float4*)&sQ[d * LDS_ + ty * 4];
            float4 bb = *(const float4*)&sK[d * LDS_ + tx * 4];
            s[0][0] += aa.x * bb.x; s[0][1] += aa.x * bb.y; s[0][2] += aa.x * bb.z; s[0][3] += aa.x * bb.w;
            s[1][0] += aa.y * bb.x; s[1][1] += aa.y * bb.y; s[1][2] += aa.y * bb.z; s[1][3] += aa.y * bb.w;
            s[2][0] += aa.z * bb.x; s[2][1] += aa.z * bb.y; s[2][2] += aa.z * bb.z; s[2][3] += aa.z * bb.w;
            s[3][0] += aa.w * bb.x; s[3][1] += aa.w * bb.y; s[3][2] += aa.w * bb.z; s[3][3] += aa.w * bb.w;
        }

        if (kt0 + 64 > len) {
#pragma unroll
            for (int j = 0; j < 4; ++j) {
                if (kt0 + tx * 4 + j >= len) {
#pragma unroll
                    for (int i = 0; i < 4; ++i) s[i][j] = -1e30f;
                }
            }
        }

#pragma unroll
        for (int i = 0; i < 4; ++i) {
            float mx = fmaxf(fmaxf(s[i][0], s[i][1]), fmaxf(s[i][2], s[i][3]));
#pragma unroll
            for (int off = 8; off >= 1; off >>= 1)
                mx = fmaxf(mx, __shfl_xor_sync(0xffffffffu, mx, off));
            float mnew = fmaxf(mrow[i], mx);
            float esc = ex2f(mrow[i] - mnew);
            mrow[i] = mnew;

            float ls = 0.f;
#pragma unroll
            for (int j = 0; j < 4; ++j) {
                float p = ex2f(s[i][j] - mnew);
                s[i][j] = p;
                ls += p;
            }
#pragma unroll
            for (int off = 8; off >= 1; off >>= 1)
                ls += __shfl_xor_sync(0xffffffffu, ls, off);

            lrow[i] = lrow[i] * esc + ls;
#pragma unroll
            for (int j = 0; j < 4; ++j) o[i][j] *= esc;
        }

#pragma unroll
        for (int i = 0; i < 4; ++i) {
            float4 p4 = make_float4(s[i][0], s[i][1], s[i][2], s[i][3]);
            *(float4*)&sP[(ty * 4 + i) * LDS_ + tx * 4] = p4;
        }
        __syncthreads();

#pragma unroll 8
        for (int k = 0; k < 64; ++k) {
            float a0 = sP[(ty * 4 + 0) * LDS_ + k];
            float a1 = sP[(ty * 4 + 1) * LDS_ + k];
            float a2 = sP[(ty * 4 + 2) * LDS_ + k];
            float a3 = sP[(ty * 4 + 3) * LDS_ + k];
            float4 bb = *(const float4*)&sV[k * LDS_ + tx * 4];
            o[0][0] += a0 * bb.x; o[0][1] += a0 * bb.y; o[0][2] += a0 * bb.z; o[0][3] += a0 * bb.w;
            o[1][0] += a1 * bb.x; o[1][1] += a1 * bb.y; o[1][2] += a1 * bb.z; o[1][3] += a1 * bb.w;
            o[2][0] += a2 * bb.x; o[2][1] += a2 * bb.y; o[2][2] += a2 * bb.z; o[2][3] += a2 * bb.w;
            o[3][0] += a3 * bb.x; o[3][1] += a3 * bb.y; o[3][2] += a3 * bb.z; o[3][3] += a3 * bb.w;
        }
        __syncthreads();
    }

#pragma unroll
    for (int i = 0; i < 4; ++i) {
        float inv = 1.0f / lrow[i];
        int sgl = q0 + ty * 4 + i;
        float4 c;
        c.x = o[i][0] * inv;
        c.y = o[i][1] * inv;
        c.z = o[i][2] * inv;
        c.w = o[i][3] * inv;
        *(float4*)&ctx[(size_t)(b * S_ + sgl) * 512 + h * 64 + tx * 4] = c;
    }
}

// ---------------------------------------------------------------------------

extern "C" void kernel_launch(void* const* d_in, const int* in_sizes, int n_in,
                              void* d_out, int out_size)
{
    const float* x_Q = (const float*)d_in[0];
    const float* x_K = (const float*)d_in[1];
    const float* x_V = (const float*)d_in[2];
    const float* Wq  = (const float*)d_in[3];
    const float* bq  = (const float*)d_in[4];
    const float* Wk  = (const float*)d_in[5];
    const float* bk  = (const float*)d_in[6];
    const float* Wv  = (const float*)d_in[7];
    const float* bv  = (const float*)d_in[8];
    const float* Wo  = (const float*)d_in[9];
    const float* bo  = (const float*)d_in[10];
    const int*   lens = (const int*)d_in[11];
    float* out = (float*)d_out;

    float *Qt, *Kt, *Vd, *ctx;
    cudaGetSymbolAddress((void**)&Qt,  g_Qt);
    cudaGetSymbolAddress((void**)&Kt,  g_Kt);
    cudaGetSymbolAddress((void**)&Vd,  g_V);
    cudaGetSymbolAddress((void**)&ctx, g_ctx);

    cudaFuncSetAttribute(proj_mma, cudaFuncAttributeMaxDynamicSharedMemorySize, PJ_SMEM_B);
    const int smem_attn = 4 * 64 * LDS_ * sizeof(float);
    cudaFuncSetAttribute(attn_kernel, cudaFuncAttributeMaxDynamicSharedMemorySize, smem_attn);

    // scale = 1/sqrt(DH) * log2(e), folded into Q projection (incl. bias)
    const float qscale = 0.125f * 1.4426950408889634f;

    dim3 gproj(D_ / 128, M_ / 128);   // x = n-tiles (4), y = m-tiles (128)
    proj_mma<<<gproj, 512, PJ_SMEM_B>>>(x_Q, Wq, bq, Qt, qscale, 0);
    proj_mma<<<gproj, 512, PJ_SMEM_B>>>(x_K, Wk, bk, Kt, 1.0f, 0);
    proj_mma<<<gproj, 512, PJ_SMEM_B>>>(x_V, Wv, bv, Vd, 1.0f, 1);

    dim3 gattn(S_ / 64, H_, B_);
    attn_kernel<<<gattn, 256, smem_attn>>>(Qt, Kt, Vd, lens, ctx);

    proj_mma<<<gproj, 512, PJ_SMEM_B>>>(ctx, Wo, bo, out, 1.0f, 2);
}

// round 6
// speedup vs baseline: 2.0379x; 1.5040x over previous
#include <cuda_runtime.h>
#include <cuda_bf16.h>
#include <cstdint>

// Problem constants (fixed by the reference)
#define B_  8
#define S_  2048
#define D_  512
#define H_  8
#define DH_ 64
#define M_  (B_ * S_)          // 16384 rows for all projections

// Scratch (allocation-free rule: __device__ globals)
__device__ uint32_t       g_Qp[B_ * H_ * S_ * DH_];      // [b,h,s,d] packed (hi,lo) bf16
__device__ uint32_t       g_Kp[B_ * H_ * S_ * DH_];      // [b,h,s,d] packed (hi,lo) bf16
__device__ unsigned short g_Vb[B_ * H_ * DH_ * 2 * S_];  // [b,h,d,k'] blocked hi8|lo8
__device__ float          g_ctx[M_ * D_];                // [b,s, h*dh]

__device__ __forceinline__ float ex2f(float x) {
    float y;
    asm("ex2.approx.f32 %0, %1;" : "=f"(y) : "f"(x));
    return y;
}

__device__ __forceinline__ uint32_t smem_u32(const void* p) {
    uint32_t a;
    asm("{ .reg .u64 t; cvta.to.shared.u64 t, %1; cvt.u32.u64 %0, t; }" : "=r"(a) : "l"(p));
    return a;
}

__device__ __forceinline__ void cp16(uint32_t dst, const void* src) {
    asm volatile("cp.async.cg.shared.global [%0], [%1], 16;" :: "r"(dst), "l"(src) : "memory");
}
#define CP_COMMIT() asm volatile("cp.async.commit_group;" ::: "memory")
template <int N>
__device__ __forceinline__ void cp_wait() {
    asm volatile("cp.async.wait_group %0;" :: "n"(N) : "memory");
}

__device__ __forceinline__ void ldmatrix4(uint32_t* r, uint32_t addr) {
    asm volatile("ldmatrix.sync.aligned.m8n8.x4.shared.b16 {%0,%1,%2,%3}, [%4];"
                 : "=r"(r[0]), "=r"(r[1]), "=r"(r[2]), "=r"(r[3]) : "r"(addr));
}

__device__ __forceinline__ void mma_bf16(float* d, uint32_t a0, uint32_t a1,
                                         uint32_t a2, uint32_t a3,
                                         uint32_t b0, uint32_t b1) {
    asm volatile(
        "mma.sync.aligned.m16n8k16.row.col.f32.bf16.bf16.f32 "
        "{%0,%1,%2,%3}, {%4,%5,%6,%7}, {%8,%9}, {%0,%1,%2,%3};"
        : "+f"(d[0]), "+f"(d[1]), "+f"(d[2]), "+f"(d[3])
        : "r"(a0), "r"(a1), "r"(a2), "r"(a3), "r"(b0), "r"(b1));
}

// fp32 -> (hi, lo) bf16 pair packed in one u32 (hi in low half)
__device__ __forceinline__ uint32_t bfsplit(float f) {
    __nv_bfloat16 h = __float2bfloat16_rn(f);
    float hf = __bfloat162float(h);
    __nv_bfloat16 l = __float2bfloat16_rn(f - hf);
    return (uint32_t)__bfloat16_as_ushort(h) | ((uint32_t)__bfloat16_as_ushort(l) << 16);
}

// swap 16-bit halves of a packed bf16x2 (hi<->lo) for cross-term MMA
__device__ __forceinline__ uint32_t swap16(uint32_t x) {
    return __byte_perm(x, x, 0x1032);
}

// ============================================================================
// Split-bf16 emulated-fp32 projection GEMM via mma.sync.m16n8k16 (validated)
//   C[M,512] = A[M,512] @ W[512,512]^T,  out = (C + bias) * scale
//   mode 0: packed u32 [b,h,s,d] (Q and K)
//   mode 2: row-major fp32 [M,512]  (final output)
//   mode 3: blocked u16 [b,h,d,k']  (V: hi8|lo8 key blocks)
// ============================================================================
#define PJ_STAGE_B 32768                // A tile 16KB + W tile 16KB (bf16)
#define PJ_SMEM_B  (2 * PJ_STAGE_B)     // 65536 bytes

__global__ __launch_bounds__(512) void proj_mma(
    const float* __restrict__ A, const float* __restrict__ W,
    const float* __restrict__ bias, void* __restrict__ outv,
    float scale, int mode)
{
    extern __shared__ __align__(16) char smem[];
    const uint32_t sbase = smem_u32(smem);

    const int tid = threadIdx.x;
    const int lane = tid & 31;
    const int warp = tid >> 5;
    const int wm = warp >> 2;          // 0..3
    const int wn = warp & 3;           // 0..3
    const int m0 = blockIdx.y * 128;
    const int n0 = blockIdx.x * 128;

    const int lrow = tid >> 2;         // 0..127 (loader row)
    const int lk8  = (tid & 3) * 8;    // fp32 k offset within 32-chunk

    float4 ra[2], rw[2];

    auto ldg = [&](int it) {
        const float* As = A + (size_t)(m0 + lrow) * 512 + it * 32 + lk8;
        const float* Ws = W + (size_t)(n0 + lrow) * 512 + it * 32 + lk8;
        ra[0] = *(const float4*)(As + 0);
        ra[1] = *(const float4*)(As + 4);
        rw[0] = *(const float4*)(Ws + 0);
        rw[1] = *(const float4*)(Ws + 4);
    };

    auto sts = [&](int st) {
        char* base = smem + st * PJ_STAGE_B + lrow * 128;
#pragma unroll
        for (int j = 0; j < 2; ++j) {
            int seg = (tid & 3) * 2 + j;
            uint32_t off = 16u * (uint32_t)(seg ^ (lrow & 7));
            uint4 pa, pw;
            pa.x = bfsplit(j ? ra[1].x : ra[0].x);
            pa.y = bfsplit(j ? ra[1].y : ra[0].y);
            pa.z = bfsplit(j ? ra[1].z : ra[0].z);
            pa.w = bfsplit(j ? ra[1].w : ra[0].w);
            pw.x = bfsplit(j ? rw[1].x : rw[0].x);
            pw.y = bfsplit(j ? rw[1].y : rw[0].y);
            pw.z = bfsplit(j ? rw[1].z : rw[0].z);
            pw.w = bfsplit(j ? rw[1].w : rw[0].w);
            *(uint4*)(base + off) = pa;
            *(uint4*)(base + 16384 + off) = pw;
        }
    };

    float d[2][4][4] = {};
    const int r8 = (lane & 7) + ((lane >> 3) & 1) * 8;   // 0..15 row-in-tile
    const int sh = lane >> 4;                            // 0/1 seg offset

    // ---- prologue ----
    ldg(0);
    sts(0);
    ldg(1);
    __syncthreads();

    for (int i = 0; i < 16; ++i) {
        // compute on stage i&1
        {
            const uint32_t aB = sbase + (i & 1) * PJ_STAGE_B;
            const uint32_t bB = aB + 16384;
#pragma unroll
            for (int ks = 0; ks < 4; ++ks) {
                uint32_t a[2][4], bfr[2][4];
                const int seg = 2 * ks + sh;
#pragma unroll
                for (int mt = 0; mt < 2; ++mt) {
                    int row = wm * 32 + mt * 16 + r8;
                    ldmatrix4(a[mt], aB + row * 128 + 16 * (seg ^ (row & 7)));
                }
#pragma unroll
                for (int g = 0; g < 2; ++g) {
                    int nrow = wn * 32 + g * 16 + r8;
                    ldmatrix4(bfr[g], bB + nrow * 128 + 16 * (seg ^ (nrow & 7)));
                }
#pragma unroll
                for (int g = 0; g < 2; ++g)
#pragma unroll
                    for (int q = 0; q < 2; ++q) {
                        const int nt = g * 2 + q;
                        const uint32_t b0 = bfr[g][q];
                        const uint32_t b1 = bfr[g][q + 2];
                        const uint32_t s0 = swap16(b0);
                        const uint32_t s1 = swap16(b1);
#pragma unroll
                        for (int mt = 0; mt < 2; ++mt) {
                            mma_bf16(d[mt][nt], a[mt][0], a[mt][1], a[mt][2], a[mt][3], b0, b1);
                            mma_bf16(d[mt][nt], a[mt][0], a[mt][1], a[mt][2], a[mt][3], s0, s1);
                        }
                    }
            }
        }
        __syncthreads();

        if (i < 15) {
            sts((i + 1) & 1);            // regs hold chunk i+1
            if (i < 14) ldg(i + 2);
            __syncthreads();
        }
    }

    // ---- epilogue (C frag: lane row = lane/4 (+8), col = (lane%4)*2 (+1)) ----
    const int rql = lane >> 2;
    const int cql = (lane & 3) * 2;
#pragma unroll
    for (int mt = 0; mt < 2; ++mt) {
        int mbase = m0 + wm * 32 + mt * 16 + rql;
#pragma unroll
        for (int nt = 0; nt < 4; ++nt) {
            int n = n0 + wn * 32 + nt * 8 + cql;
            float2 bv = *(const float2*)&bias[n];
#pragma unroll
            for (int rr = 0; rr < 2; ++rr) {
                int m = mbase + rr * 8;
                float v0 = (d[mt][nt][rr * 2 + 0] + bv.x) * scale;
                float v1 = (d[mt][nt][rr * 2 + 1] + bv.y) * scale;
                int b = m >> 11, s = m & 2047;
                int h = n >> 6, dd = n & 63;
                if (mode == 0) {
                    uint2 pv;
                    pv.x = bfsplit(v0);
                    pv.y = bfsplit(v1);
                    *(uint2*)&((uint32_t*)outv)[(((size_t)(b * H_ + h)) * S_ + s) * 64 + dd] = pv;
                } else if (mode == 3) {
                    unsigned short* o16 = (unsigned short*)outv;
                    int blk = ((s >> 3) << 4) + (s & 7);
                    uint32_t p0 = bfsplit(v0), p1 = bfsplit(v1);
                    size_t rb0 = (((size_t)(b * H_ + h)) * DH_ + dd) * (2 * S_);
                    size_t rb1 = rb0 + 2 * S_;
                    o16[rb0 + blk]     = (unsigned short)(p0 & 0xffff);
                    o16[rb0 + blk + 8] = (unsigned short)(p0 >> 16);
                    o16[rb1 + blk]     = (unsigned short)(p1 & 0xffff);
                    o16[rb1 + blk + 8] = (unsigned short)(p1 >> 16);
                } else {
                    float2 v = make_float2(v0, v1);
                    *(float2*)&((float*)outv)[(size_t)m * 512 + n] = v;
                }
            }
        }
    }
}

// ============================================================================
// Tensor-core flash attention, split-bf16 exact-product MMAs.
//   CTA: 128q x 64k per tile, 8 warps x 16q (full-k rows -> intra-quad softmax).
//   Q,K: packed u32 (hi,lo interleaved along d'). V: u16 [d][k'] hi8|lo8 blocks.
//   S C-frags reused in place as P A-frags; PV cross term = register reorder.
//   Q pre-scaled by (1/sqrt(DH))*log2(e) in proj -> exp == ex2.
// ============================================================================
#define AT_SQ   0
#define AT_SK   32768
#define AT_SV   (32768 + 2 * 16384)
#define AT_SMEM (32768 + 4 * 16384)    // 98304

__global__ __launch_bounds__(256) void attn_mma(
    const uint32_t* __restrict__ Qp, const uint32_t* __restrict__ Kp,
    const unsigned short* __restrict__ Vb, const int* __restrict__ lens,
    float* __restrict__ ctx)
{
    extern __shared__ __align__(16) char smem[];
    const uint32_t sb = smem_u32(smem);

    const int tid = threadIdx.x;
    const int lane = tid & 31;
    const int warp = tid >> 5;
    const int q0 = blockIdx.x * 128;
    const int h = blockIdx.y;
    const int b = blockIdx.z;
    const int len = lens[b];

    const size_t bh = (size_t)(b * H_ + h);
    const uint32_t* Qg = Qp + (bh * S_ + q0) * 64;
    const uint32_t* Kg = Kp + bh * S_ * 64;
    const unsigned short* Vg = Vb + bh * (size_t)DH_ * 2 * S_;

    const int r8 = (lane & 7) + ((lane >> 3) & 1) * 8;   // 0..15
    const int sh = lane >> 4;                            // 0/1
    const int u2 = (lane & 3) * 2;                       // col pair base

    // ---- load Q tile (128 rows x 256B), one commit group ----
#pragma unroll
    for (int j = 0; j < 8; ++j) {
        int idx = j * 256 + tid;
        int row = idx >> 4, seg = idx & 15;
        cp16(sb + AT_SQ + row * 256 + 16 * (seg ^ (row & 7)), Qg + (size_t)row * 64 + seg * 4);
    }
    CP_COMMIT();

    // ---- K/V tile loader (8 cp16/thread, one group) ----
    auto loadKV = [&](int kt0, int buf) {
        const uint32_t dk = sb + AT_SK + buf * 16384;
        const uint32_t dv = sb + AT_SV + buf * 16384;
#pragma unroll
        for (int j = 0; j < 4; ++j) {
            int idx = j * 256 + tid;
            int row = idx >> 4, seg = idx & 15;
            uint32_t off = row * 256 + 16 * (seg ^ (row & 7));
            cp16(dk + off, Kg + ((size_t)(kt0 + row)) * 64 + seg * 4);
            cp16(dv + off, Vg + (size_t)row * 2 * S_ + kt0 * 2 + seg * 8);
        }
        CP_COMMIT();
    };

    loadKV(0, 0);
    cp_wait<0>();
    __syncthreads();

    // ---- extract Q A-frags (register resident; frees nothing but read once) ----
    uint32_t qa[8][4];
    {
        const int qrow = 16 * warp + r8;
        const uint32_t qb = sb + AT_SQ + qrow * 256;
        const int rx = qrow & 7;
#pragma unroll
        for (int t = 0; t < 8; ++t)
            ldmatrix4(qa[t], qb + 16 * ((2 * t + sh) ^ rx));
    }

    float oacc[8][4] = {};
    float m0 = -1e30f, m1 = -1e30f, l0 = 0.f, l1 = 0.f;

    const int nkt = (len + 63) >> 6;

    for (int t = 0; t < nkt; ++t) {
        if (t + 1 < nkt) loadKV((t + 1) * 64, (t + 1) & 1);

        const uint32_t kb = sb + AT_SK + (t & 1) * 16384;
        const uint32_t vb = sb + AT_SV + (t & 1) * 16384;
        const int rx = r8 & 7;

        // ---- S = Q K^T (split-bf16 exact) ----
        float sacc[8][4] = {};
#pragma unroll
        for (int ks = 0; ks < 8; ++ks) {
            const uint32_t soff = 16 * ((2 * ks + sh) ^ rx);
#pragma unroll
            for (int g = 0; g < 4; ++g) {
                uint32_t bf[4];
                ldmatrix4(bf, kb + (16 * g + r8) * 256 + soff);
#pragma unroll
                for (int q = 0; q < 2; ++q) {
                    const int nt = 2 * g + q;
                    const uint32_t b0 = bf[q], b1 = bf[q + 2];
                    mma_bf16(sacc[nt], qa[ks][0], qa[ks][1], qa[ks][2], qa[ks][3], b0, b1);
                    mma_bf16(sacc[nt], qa[ks][0], qa[ks][1], qa[ks][2], qa[ks][3],
                             swap16(b0), swap16(b1));
                }
            }
        }

        // ---- mask tail keys ----
        const int kt0 = t * 64;
        if (kt0 + 64 > len) {
#pragma unroll
            for (int nt = 0; nt < 8; ++nt) {
                int c0 = kt0 + nt * 8 + u2;
                if (c0 >= len)     { sacc[nt][0] = -1e30f; sacc[nt][2] = -1e30f; }
                if (c0 + 1 >= len) { sacc[nt][1] = -1e30f; sacc[nt][3] = -1e30f; }
            }
        }

        // ---- online softmax (rows l/4 and l/4+8; quad shfl reductions) ----
        float mx0 = -1e30f, mx1 = -1e30f;
#pragma unroll
        for (int nt = 0; nt < 8; ++nt) {
            mx0 = fmaxf(mx0, fmaxf(sacc[nt][0], sacc[nt][1]));
            mx1 = fmaxf(mx1, fmaxf(sacc[nt][2], sacc[nt][3]));
        }
        mx0 = fmaxf(mx0, __shfl_xor_sync(0xffffffffu, mx0, 1));
        mx0 = fmaxf(mx0, __shfl_xor_sync(0xffffffffu, mx0, 2));
        mx1 = fmaxf(mx1, __shfl_xor_sync(0xffffffffu, mx1, 1));
        mx1 = fmaxf(mx1, __shfl_xor_sync(0xffffffffu, mx1, 2));

        const float mn0 = fmaxf(m0, mx0), mn1 = fmaxf(m1, mx1);
        const float e0 = ex2f(m0 - mn0), e1 = ex2f(m1 - mn1);
        m0 = mn0; m1 = mn1;

        float s0 = 0.f, s1 = 0.f;
#pragma unroll
        for (int nt = 0; nt < 8; ++nt) {
            float p;
            p = ex2f(sacc[nt][0] - mn0); sacc[nt][0] = p; s0 += p;
            p = ex2f(sacc[nt][1] - mn0); sacc[nt][1] = p; s0 += p;
            p = ex2f(sacc[nt][2] - mn1); sacc[nt][2] = p; s1 += p;
            p = ex2f(sacc[nt][3] - mn1); sacc[nt][3] = p; s1 += p;
        }
        s0 += __shfl_xor_sync(0xffffffffu, s0, 1);
        s0 += __shfl_xor_sync(0xffffffffu, s0, 2);
        s1 += __shfl_xor_sync(0xffffffffu, s1, 1);
        s1 += __shfl_xor_sync(0xffffffffu, s1, 2);
        l0 = l0 * e0 + s0;
        l1 = l1 * e1 + s1;

#pragma unroll
        for (int nt = 0; nt < 8; ++nt) {
            oacc[nt][0] *= e0; oacc[nt][1] *= e0;
            oacc[nt][2] *= e1; oacc[nt][3] *= e1;
        }

        // ---- O += P V (P frags from S C-frags; hi8|lo8 V blocks) ----
#pragma unroll
        for (int g = 0; g < 8; ++g) {
            // split P into bf16 hi/lo A-frags
            __nv_bfloat16 h0 = __float2bfloat16_rn(sacc[g][0]);
            __nv_bfloat16 h1 = __float2bfloat16_rn(sacc[g][1]);
            __nv_bfloat16 h2 = __float2bfloat16_rn(sacc[g][2]);
            __nv_bfloat16 h3 = __float2bfloat16_rn(sacc[g][3]);
            __nv_bfloat16 lo0 = __float2bfloat16_rn(sacc[g][0] - __bfloat162float(h0));
            __nv_bfloat16 lo1 = __float2bfloat16_rn(sacc[g][1] - __bfloat162float(h1));
            __nv_bfloat16 lo2 = __float2bfloat16_rn(sacc[g][2] - __bfloat162float(h2));
            __nv_bfloat16 lo3 = __float2bfloat16_rn(sacc[g][3] - __bfloat162float(h3));
            uint32_t a0 = (uint32_t)__bfloat16_as_ushort(h0) | ((uint32_t)__bfloat16_as_ushort(h1) << 16);
            uint32_t a1 = (uint32_t)__bfloat16_as_ushort(h2) | ((uint32_t)__bfloat16_as_ushort(h3) << 16);
            uint32_t a2 = (uint32_t)__bfloat16_as_ushort(lo0) | ((uint32_t)__bfloat16_as_ushort(lo1) << 16);
            uint32_t a3 = (uint32_t)__bfloat16_as_ushort(lo2) | ((uint32_t)__bfloat16_as_ushort(lo3) << 16);

            const uint32_t soff = 16 * ((2 * g + sh) ^ rx);
#pragma unroll
            for (int dt = 0; dt < 4; ++dt) {
                uint32_t vf[4];
                ldmatrix4(vf, vb + (16 * dt + r8) * 256 + soff);
#pragma unroll
                for (int q = 0; q < 2; ++q) {
                    const int nt = 2 * dt + q;
                    mma_bf16(oacc[nt], a0, a1, a2, a3, vf[q], vf[q + 2]);  // hi*hi + lo*lo
                    mma_bf16(oacc[nt], a2, a3, a0, a1, vf[q], vf[q + 2]);  // hi*lo + lo*hi
                }
            }
        }

        if (t + 1 < nkt) cp_wait<0>();
        __syncthreads();
    }

    // ---- write ctx [b, q, h*64+d] ----
    const float inv0 = 1.0f / l0;
    const float inv1 = 1.0f / l1;
    const int qg0 = q0 + 16 * warp + (lane >> 2);
    const int qg1 = qg0 + 8;
    float* c0 = ctx + ((size_t)b * S_ + qg0) * 512 + h * 64 + u2;
    float* c1 = ctx + ((size_t)b * S_ + qg1) * 512 + h * 64 + u2;
#pragma unroll
    for (int nt = 0; nt < 8; ++nt) {
        *(float2*)(c0 + nt * 8) = make_float2(oacc[nt][0] * inv0, oacc[nt][1] * inv0);
        *(float2*)(c1 + nt * 8) = make_float2(oacc[nt][2] * inv1, oacc[nt][3] * inv1);
    }
}

// ---------------------------------------------------------------------------

extern "C" void kernel_launch(void* const* d_in, const int* in_sizes, int n_in,
                              void* d_out, int out_size)
{
    const float* x_Q = (const float*)d_in[0];
    const float* x_K = (const float*)d_in[1];
    const float* x_V = (const float*)d_in[2];
    const float* Wq  = (const float*)d_in[3];
    const float* bq  = (const float*)d_in[4];
    const float* Wk  = (const float*)d_in[5];
    const float* bk  = (const float*)d_in[6];
    const float* Wv  = (const float*)d_in[7];
    const float* bv  = (const float*)d_in[8];
    const float* Wo  = (const float*)d_in[9];
    const float* bo  = (const float*)d_in[10];
    const int*   lens = (const int*)d_in[11];
    float* out = (float*)d_out;

    uint32_t *Qp, *Kp;
    unsigned short* Vb;
    float* ctx;
    cudaGetSymbolAddress((void**)&Qp,  g_Qp);
    cudaGetSymbolAddress((void**)&Kp,  g_Kp);
    cudaGetSymbolAddress((void**)&Vb,  g_Vb);
    cudaGetSymbolAddress((void**)&ctx, g_ctx);

    cudaFuncSetAttribute(proj_mma, cudaFuncAttributeMaxDynamicSharedMemorySize, PJ_SMEM_B);
    cudaFuncSetAttribute(attn_mma, cudaFuncAttributeMaxDynamicSharedMemorySize, AT_SMEM);

    // scale = 1/sqrt(DH) * log2(e), folded into Q projection (incl. bias)
    const float qscale = 0.125f * 1.4426950408889634f;

    dim3 gproj(D_ / 128, M_ / 128);   // x = n-tiles (4), y = m-tiles (128)
    proj_mma<<<gproj, 512, PJ_SMEM_B>>>(x_Q, Wq, bq, Qp, qscale, 0);
    proj_mma<<<gproj, 512, PJ_SMEM_B>>>(x_K, Wk, bk, Kp, 1.0f, 0);
    proj_mma<<<gproj, 512, PJ_SMEM_B>>>(x_V, Wv, bv, Vb, 1.0f, 3);

    dim3 gattn(S_ / 128, H_, B_);
    attn_mma<<<gattn, 256, AT_SMEM>>>(Qp, Kp, Vb, lens, ctx);

    proj_mma<<<gproj, 512, PJ_SMEM_B>>>(ctx, Wo, bo, out, 1.0f, 2);
}

// round 7
// speedup vs baseline: 2.2485x; 1.1034x over previous
#include <cuda_runtime.h>
#include <cuda_bf16.h>
#include <cstdint>

// Problem constants (fixed by the reference)
#define B_  8
#define S_  2048
#define D_  512
#define H_  8
#define DH_ 64
#define M_  (B_ * S_)          // 16384 rows for all projections

// Scratch (allocation-free rule: __device__ globals)
__device__ uint32_t       g_xQp[M_ * D_];                // packed split-bf16 inputs
__device__ uint32_t       g_xKp[M_ * D_];
__device__ uint32_t       g_xVp[M_ * D_];
__device__ uint32_t       g_Wqp[D_ * D_];
__device__ uint32_t       g_Wkp[D_ * D_];
__device__ uint32_t       g_Wvp[D_ * D_];
__device__ uint32_t       g_Wop[D_ * D_];
__device__ uint32_t       g_Qp[B_ * H_ * S_ * DH_];      // [b,h,s,d] packed (hi,lo)
__device__ uint32_t       g_Kp[B_ * H_ * S_ * DH_];      // [b,h,s,d] packed (hi,lo)
__device__ unsigned short g_Vb[B_ * H_ * DH_ * 2 * S_];  // [b,h,d,k'] blocked hi8|lo8
__device__ uint32_t       g_ctxp[M_ * D_];               // packed ctx [b,s, h*dh]

__device__ __forceinline__ float ex2f(float x) {
    float y;
    asm("ex2.approx.f32 %0, %1;" : "=f"(y) : "f"(x));
    return y;
}

__device__ __forceinline__ uint32_t smem_u32(const void* p) {
    uint32_t a;
    asm("{ .reg .u64 t; cvta.to.shared.u64 t, %1; cvt.u32.u64 %0, t; }" : "=r"(a) : "l"(p));
    return a;
}

__device__ __forceinline__ void cp16(uint32_t dst, const void* src) {
    asm volatile("cp.async.cg.shared.global [%0], [%1], 16;" :: "r"(dst), "l"(src) : "memory");
}
#define CP_COMMIT() asm volatile("cp.async.commit_group;" ::: "memory")
template <int N>
__device__ __forceinline__ void cp_wait() {
    asm volatile("cp.async.wait_group %0;" :: "n"(N) : "memory");
}

__device__ __forceinline__ void ldmatrix4(uint32_t* r, uint32_t addr) {
    asm volatile("ldmatrix.sync.aligned.m8n8.x4.shared.b16 {%0,%1,%2,%3}, [%4];"
                 : "=r"(r[0]), "=r"(r[1]), "=r"(r[2]), "=r"(r[3]) : "r"(addr));
}

__device__ __forceinline__ void mma_bf16(float* d, uint32_t a0, uint32_t a1,
                                         uint32_t a2, uint32_t a3,
                                         uint32_t b0, uint32_t b1) {
    asm volatile(
        "mma.sync.aligned.m16n8k16.row.col.f32.bf16.bf16.f32 "
        "{%0,%1,%2,%3}, {%4,%5,%6,%7}, {%8,%9}, {%0,%1,%2,%3};"
        : "+f"(d[0]), "+f"(d[1]), "+f"(d[2]), "+f"(d[3])
        : "r"(a0), "r"(a1), "r"(a2), "r"(a3), "r"(b0), "r"(b1));
}

// fp32 -> (hi, lo) bf16 pair packed in one u32 (hi in low half)
__device__ __forceinline__ uint32_t bfsplit(float f) {
    __nv_bfloat16 h = __float2bfloat16_rn(f);
    float hf = __bfloat162float(h);
    __nv_bfloat16 l = __float2bfloat16_rn(f - hf);
    return (uint32_t)__bfloat16_as_ushort(h) | ((uint32_t)__bfloat16_as_ushort(l) << 16);
}

// swap 16-bit halves of a packed bf16x2 (hi<->lo) for cross-term MMA
__device__ __forceinline__ uint32_t swap16(uint32_t x) {
    return __byte_perm(x, x, 0x1032);
}

// ============================================================================
// Pack pass: fp32 -> packed split-bf16 u32 (streaming, float4)
// ============================================================================
__global__ __launch_bounds__(256) void pack_f32(
    const float4* __restrict__ in, uint4* __restrict__ out, int n4)
{
    int i = blockIdx.x * blockDim.x + threadIdx.x;
    if (i < n4) {
        float4 v = in[i];
        uint4 p;
        p.x = bfsplit(v.x);
        p.y = bfsplit(v.y);
        p.z = bfsplit(v.z);
        p.w = bfsplit(v.w);
        out[i] = p;
    }
}

// ============================================================================
// Pure split-bf16 projection GEMM (pre-packed operands, cp.async 4-stage)
//   C[M,512] = A[M,512] @ W[512,512]^T in fp32-equivalent precision.
//   mode 0: packed u32 [b,h,s,d] (Q and K)
//   mode 2: row-major fp32 [M,512] (final output)
//   mode 3: blocked u16 [b,h,d,k'] (V: hi8|lo8 key blocks)
// ============================================================================
#define PJ_STAGE_B 32768                 // A tile 16KB + W tile 16KB
#define PJ_SMEM_B  (4 * PJ_STAGE_B)      // 131072 bytes, 4 stages

__global__ __launch_bounds__(512) void proj_mma(
    const uint32_t* __restrict__ Ap, const uint32_t* __restrict__ Wp,
    const float* __restrict__ bias, void* __restrict__ outv,
    float scale, int mode)
{
    extern __shared__ __align__(16) char smem[];
    const uint32_t sbase = smem_u32(smem);

    const int tid = threadIdx.x;
    const int lane = tid & 31;
    const int warp = tid >> 5;
    const int wm = warp >> 2;          // 0..3
    const int wn = warp & 3;           // 0..3
    const int m0 = blockIdx.y * 128;
    const int n0 = blockIdx.x * 128;

    const int lrow = tid >> 2;         // 0..127 (loader row)
    const int ls0  = (tid & 3) * 2;    // first 16B seg (of 8 per 128B row)

    auto loadc = [&](int c, int st) {
        const uint32_t* As = Ap + (size_t)(m0 + lrow) * 512 + c * 32;
        const uint32_t* Ws = Wp + (size_t)(n0 + lrow) * 512 + c * 32;
        const uint32_t base = sbase + st * PJ_STAGE_B + lrow * 128;
        const int rx = lrow & 7;
#pragma unroll
        for (int j = 0; j < 2; ++j) {
            int seg = ls0 + j;
            uint32_t off = 16u * (uint32_t)(seg ^ rx);
            cp16(base + off,         As + seg * 4);
            cp16(base + 16384 + off, Ws + seg * 4);
        }
        CP_COMMIT();
    };

    float d[2][4][4] = {};
    const int r8 = (lane & 7) + ((lane >> 3) & 1) * 8;   // 0..15 row-in-tile
    const int sh = lane >> 4;                            // 0/1 seg offset

    // ---- prologue: 3 chunks in flight ----
    loadc(0, 0);
    loadc(1, 1);
    loadc(2, 2);

    for (int i = 0; i < 16; ++i) {
        cp_wait<2>();
        __syncthreads();

        // compute on stage i%4
        {
            const uint32_t aB = sbase + (i & 3) * PJ_STAGE_B;
            const uint32_t bB = aB + 16384;
#pragma unroll
            for (int ks = 0; ks < 4; ++ks) {
                uint32_t a[2][4], bfr[2][4];
                const int seg = 2 * ks + sh;
#pragma unroll
                for (int mt = 0; mt < 2; ++mt) {
                    int row = wm * 32 + mt * 16 + r8;
                    ldmatrix4(a[mt], aB + row * 128 + 16 * (seg ^ (row & 7)));
                }
#pragma unroll
                for (int g = 0; g < 2; ++g) {
                    int nrow = wn * 32 + g * 16 + r8;
                    ldmatrix4(bfr[g], bB + nrow * 128 + 16 * (seg ^ (nrow & 7)));
                }
#pragma unroll
                for (int g = 0; g < 2; ++g)
#pragma unroll
                    for (int q = 0; q < 2; ++q) {
                        const int nt = g * 2 + q;
                        const uint32_t b0 = bfr[g][q];
                        const uint32_t b1 = bfr[g][q + 2];
                        const uint32_t s0 = swap16(b0);
                        const uint32_t s1 = swap16(b1);
#pragma unroll
                        for (int mt = 0; mt < 2; ++mt) {
                            mma_bf16(d[mt][nt], a[mt][0], a[mt][1], a[mt][2], a[mt][3], b0, b1);
                            mma_bf16(d[mt][nt], a[mt][0], a[mt][1], a[mt][2], a[mt][3], s0, s1);
                        }
                    }
            }
        }

        if (i + 3 < 16) loadc(i + 3, (i + 3) & 3);
    }

    // ---- epilogue (C frag: lane row = lane/4 (+8), col = (lane%4)*2 (+1)) ----
    const int rql = lane >> 2;
    const int cql = (lane & 3) * 2;
#pragma unroll
    for (int mt = 0; mt < 2; ++mt) {
        int mbase = m0 + wm * 32 + mt * 16 + rql;
#pragma unroll
        for (int nt = 0; nt < 4; ++nt) {
            int n = n0 + wn * 32 + nt * 8 + cql;
            float2 bv = *(const float2*)&bias[n];
#pragma unroll
            for (int rr = 0; rr < 2; ++rr) {
                int m = mbase + rr * 8;
                float v0 = (d[mt][nt][rr * 2 + 0] + bv.x) * scale;
                float v1 = (d[mt][nt][rr * 2 + 1] + bv.y) * scale;
                int b = m >> 11, s = m & 2047;
                int h = n >> 6, dd = n & 63;
                if (mode == 0) {
                    uint2 pv;
                    pv.x = bfsplit(v0);
                    pv.y = bfsplit(v1);
                    *(uint2*)&((uint32_t*)outv)[(((size_t)(b * H_ + h)) * S_ + s) * 64 + dd] = pv;
                } else if (mode == 3) {
                    unsigned short* o16 = (unsigned short*)outv;
                    int blk = ((s >> 3) << 4) + (s & 7);
                    uint32_t p0 = bfsplit(v0), p1 = bfsplit(v1);
                    size_t rb0 = (((size_t)(b * H_ + h)) * DH_ + dd) * (2 * S_);
                    size_t rb1 = rb0 + 2 * S_;
                    o16[rb0 + blk]     = (unsigned short)(p0 & 0xffff);
                    o16[rb0 + blk + 8] = (unsigned short)(p0 >> 16);
                    o16[rb1 + blk]     = (unsigned short)(p1 & 0xffff);
                    o16[rb1 + blk + 8] = (unsigned short)(p1 >> 16);
                } else {
                    float2 v = make_float2(v0, v1);
                    *(float2*)&((float*)outv)[(size_t)m * 512 + n] = v;
                }
            }
        }
    }
}

// ============================================================================
// Tensor-core flash attention (validated R6), split-bf16 exact-product MMAs.
//   CTA: 128q x 64k per tile, 8 warps x 16q. Epilogue now writes PACKED ctx.
// ============================================================================
#define AT_SQ   0
#define AT_SK   32768
#define AT_SV   (32768 + 2 * 16384)
#define AT_SMEM (32768 + 4 * 16384)    // 98304

__global__ __launch_bounds__(256) void attn_mma(
    const uint32_t* __restrict__ Qp, const uint32_t* __restrict__ Kp,
    const unsigned short* __restrict__ Vb, const int* __restrict__ lens,
    uint32_t* __restrict__ ctxp)
{
    extern __shared__ __align__(16) char smem[];
    const uint32_t sb = smem_u32(smem);

    const int tid = threadIdx.x;
    const int lane = tid & 31;
    const int warp = tid >> 5;
    const int q0 = blockIdx.x * 128;
    const int h = blockIdx.y;
    const int b = blockIdx.z;
    const int len = lens[b];

    const size_t bh = (size_t)(b * H_ + h);
    const uint32_t* Qg = Qp + (bh * S_ + q0) * 64;
    const uint32_t* Kg = Kp + bh * S_ * 64;
    const unsigned short* Vg = Vb + bh * (size_t)DH_ * 2 * S_;

    const int r8 = (lane & 7) + ((lane >> 3) & 1) * 8;   // 0..15
    const int sh = lane >> 4;                            // 0/1
    const int u2 = (lane & 3) * 2;                       // col pair base

    // ---- load Q tile (128 rows x 256B), one commit group ----
#pragma unroll
    for (int j = 0; j < 8; ++j) {
        int idx = j * 256 + tid;
        int row = idx >> 4, seg = idx & 15;
        cp16(sb + AT_SQ + row * 256 + 16 * (seg ^ (row & 7)), Qg + (size_t)row * 64 + seg * 4);
    }
    CP_COMMIT();

    // ---- K/V tile loader (8 cp16/thread, one group) ----
    auto loadKV = [&](int kt0, int buf) {
        const uint32_t dk = sb + AT_SK + buf * 16384;
        const uint32_t dv = sb + AT_SV + buf * 16384;
#pragma unroll
        for (int j = 0; j < 4; ++j) {
            int idx = j * 256 + tid;
            int row = idx >> 4, seg = idx & 15;
            uint32_t off = row * 256 + 16 * (seg ^ (row & 7));
            cp16(dk + off, Kg + ((size_t)(kt0 + row)) * 64 + seg * 4);
            cp16(dv + off, Vg + (size_t)row * 2 * S_ + kt0 * 2 + seg * 8);
        }
        CP_COMMIT();
    };

    loadKV(0, 0);
    cp_wait<0>();
    __syncthreads();

    // ---- extract Q A-frags (register resident) ----
    uint32_t qa[8][4];
    {
        const int qrow = 16 * warp + r8;
        const uint32_t qb = sb + AT_SQ + qrow * 256;
        const int rx = qrow & 7;
#pragma unroll
        for (int t = 0; t < 8; ++t)
            ldmatrix4(qa[t], qb + 16 * ((2 * t + sh) ^ rx));
    }

    float oacc[8][4] = {};
    float m0 = -1e30f, m1 = -1e30f, l0 = 0.f, l1 = 0.f;

    const int nkt = (len + 63) >> 6;

    for (int t = 0; t < nkt; ++t) {
        if (t + 1 < nkt) loadKV((t + 1) * 64, (t + 1) & 1);

        const uint32_t kb = sb + AT_SK + (t & 1) * 16384;
        const uint32_t vb = sb + AT_SV + (t & 1) * 16384;
        const int rx = r8 & 7;

        // ---- S = Q K^T (split-bf16 exact) ----
        float sacc[8][4] = {};
#pragma unroll
        for (int ks = 0; ks < 8; ++ks) {
            const uint32_t soff = 16 * ((2 * ks + sh) ^ rx);
#pragma unroll
            for (int g = 0; g < 4; ++g) {
                uint32_t bf[4];
                ldmatrix4(bf, kb + (16 * g + r8) * 256 + soff);
#pragma unroll
                for (int q = 0; q < 2; ++q) {
                    const int nt = 2 * g + q;
                    const uint32_t b0 = bf[q], b1 = bf[q + 2];
                    mma_bf16(sacc[nt], qa[ks][0], qa[ks][1], qa[ks][2], qa[ks][3], b0, b1);
                    mma_bf16(sacc[nt], qa[ks][0], qa[ks][1], qa[ks][2], qa[ks][3],
                             swap16(b0), swap16(b1));
                }
            }
        }

        // ---- mask tail keys ----
        const int kt0 = t * 64;
        if (kt0 + 64 > len) {
#pragma unroll
            for (int nt = 0; nt < 8; ++nt) {
                int c0 = kt0 + nt * 8 + u2;
                if (c0 >= len)     { sacc[nt][0] = -1e30f; sacc[nt][2] = -1e30f; }
                if (c0 + 1 >= len) { sacc[nt][1] = -1e30f; sacc[nt][3] = -1e30f; }
            }
        }

        // ---- online softmax (rows l/4 and l/4+8; quad shfl reductions) ----
        float mx0 = -1e30f, mx1 = -1e30f;
#pragma unroll
        for (int nt = 0; nt < 8; ++nt) {
            mx0 = fmaxf(mx0, fmaxf(sacc[nt][0], sacc[nt][1]));
            mx1 = fmaxf(mx1, fmaxf(sacc[nt][2], sacc[nt][3]));
        }
        mx0 = fmaxf(mx0, __shfl_xor_sync(0xffffffffu, mx0, 1));
        mx0 = fmaxf(mx0, __shfl_xor_sync(0xffffffffu, mx0, 2));
        mx1 = fmaxf(mx1, __shfl_xor_sync(0xffffffffu, mx1, 1));
        mx1 = fmaxf(mx1, __shfl_xor_sync(0xffffffffu, mx1, 2));

        const float mn0 = fmaxf(m0, mx0), mn1 = fmaxf(m1, mx1);
        const float e0 = ex2f(m0 - mn0), e1 = ex2f(m1 - mn1);
        m0 = mn0; m1 = mn1;

        float s0 = 0.f, s1 = 0.f;
#pragma unroll
        for (int nt = 0; nt < 8; ++nt) {
            float p;
            p = ex2f(sacc[nt][0] - mn0); sacc[nt][0] = p; s0 += p;
            p = ex2f(sacc[nt][1] - mn0); sacc[nt][1] = p; s0 += p;
            p = ex2f(sacc[nt][2] - mn1); sacc[nt][2] = p; s1 += p;
            p = ex2f(sacc[nt][3] - mn1); sacc[nt][3] = p; s1 += p;
        }
        s0 += __shfl_xor_sync(0xffffffffu, s0, 1);
        s0 += __shfl_xor_sync(0xffffffffu, s0, 2);
        s1 += __shfl_xor_sync(0xffffffffu, s1, 1);
        s1 += __shfl_xor_sync(0xffffffffu, s1, 2);
        l0 = l0 * e0 + s0;
        l1 = l1 * e1 + s1;

#pragma unroll
        for (int nt = 0; nt < 8; ++nt) {
            oacc[nt][0] *= e0; oacc[nt][1] *= e0;
            oacc[nt][2] *= e1; oacc[nt][3] *= e1;
        }

        // ---- O += P V (P frags from S C-frags; hi8|lo8 V blocks) ----
#pragma unroll
        for (int g = 0; g < 8; ++g) {
            __nv_bfloat16 h0 = __float2bfloat16_rn(sacc[g][0]);
            __nv_bfloat16 h1 = __float2bfloat16_rn(sacc[g][1]);
            __nv_bfloat16 h2 = __float2bfloat16_rn(sacc[g][2]);
            __nv_bfloat16 h3 = __float2bfloat16_rn(sacc[g][3]);
            __nv_bfloat16 lo0 = __float2bfloat16_rn(sacc[g][0] - __bfloat162float(h0));
            __nv_bfloat16 lo1 = __float2bfloat16_rn(sacc[g][1] - __bfloat162float(h1));
            __nv_bfloat16 lo2 = __float2bfloat16_rn(sacc[g][2] - __bfloat162float(h2));
            __nv_bfloat16 lo3 = __float2bfloat16_rn(sacc[g][3] - __bfloat162float(h3));
            uint32_t a0 = (uint32_t)__bfloat16_as_ushort(h0) | ((uint32_t)__bfloat16_as_ushort(h1) << 16);
            uint32_t a1 = (uint32_t)__bfloat16_as_ushort(h2) | ((uint32_t)__bfloat16_as_ushort(h3) << 16);
            uint32_t a2 = (uint32_t)__bfloat16_as_ushort(lo0) | ((uint32_t)__bfloat16_as_ushort(lo1) << 16);
            uint32_t a3 = (uint32_t)__bfloat16_as_ushort(lo2) | ((uint32_t)__bfloat16_as_ushort(lo3) << 16);

            const uint32_t soff = 16 * ((2 * g + sh) ^ rx);
#pragma unroll
            for (int dt = 0; dt < 4; ++dt) {
                uint32_t vf[4];
                ldmatrix4(vf, vb + (16 * dt + r8) * 256 + soff);
#pragma unroll
                for (int q = 0; q < 2; ++q) {
                    const int nt = 2 * dt + q;
                    mma_bf16(oacc[nt], a0, a1, a2, a3, vf[q], vf[q + 2]);  // hi*hi + lo*lo
                    mma_bf16(oacc[nt], a2, a3, a0, a1, vf[q], vf[q + 2]);  // hi*lo + lo*hi
                }
            }
        }

        if (t + 1 < nkt) cp_wait<0>();
        __syncthreads();
    }

    // ---- write packed ctx [b, q, h*64+d] ----
    const float inv0 = 1.0f / l0;
    const float inv1 = 1.0f / l1;
    const int qg0 = q0 + 16 * warp + (lane >> 2);
    const int qg1 = qg0 + 8;
    uint32_t* c0 = ctxp + ((size_t)b * S_ + qg0) * 512 + h * 64 + u2;
    uint32_t* c1 = ctxp + ((size_t)b * S_ + qg1) * 512 + h * 64 + u2;
#pragma unroll
    for (int nt = 0; nt < 8; ++nt) {
        *(uint2*)(c0 + nt * 8) = make_uint2(bfsplit(oacc[nt][0] * inv0), bfsplit(oacc[nt][1] * inv0));
        *(uint2*)(c1 + nt * 8) = make_uint2(bfsplit(oacc[nt][2] * inv1), bfsplit(oacc[nt][3] * inv1));
    }
}

// ---------------------------------------------------------------------------

extern "C" void kernel_launch(void* const* d_in, const int* in_sizes, int n_in,
                              void* d_out, int out_size)
{
    const float* x_Q = (const float*)d_in[0];
    const float* x_K = (const float*)d_in[1];
    const float* x_V = (const float*)d_in[2];
    const float* Wq  = (const float*)d_in[3];
    const float* bq  = (const float*)d_in[4];
    const float* Wk  = (const float*)d_in[5];
    const float* bk  = (const float*)d_in[6];
    const float* Wv  = (const float*)d_in[7];
    const float* bv  = (const float*)d_in[8];
    const float* Wo  = (const float*)d_in[9];
    const float* bo  = (const float*)d_in[10];
    const int*   lens = (const int*)d_in[11];
    float* out = (float*)d_out;

    uint32_t *xQp, *xKp, *xVp, *Wqp, *Wkp, *Wvp, *Wop, *Qp, *Kp, *ctxp;
    unsigned short* Vb;
    cudaGetSymbolAddress((void**)&xQp, g_xQp);
    cudaGetSymbolAddress((void**)&xKp, g_xKp);
    cudaGetSymbolAddress((void**)&xVp, g_xVp);
    cudaGetSymbolAddress((void**)&Wqp, g_Wqp);
    cudaGetSymbolAddress((void**)&Wkp, g_Wkp);
    cudaGetSymbolAddress((void**)&Wvp, g_Wvp);
    cudaGetSymbolAddress((void**)&Wop, g_Wop);
    cudaGetSymbolAddress((void**)&Qp,  g_Qp);
    cudaGetSymbolAddress((void**)&Kp,  g_Kp);
    cudaGetSymbolAddress((void**)&Vb,  g_Vb);
    cudaGetSymbolAddress((void**)&ctxp, g_ctxp);

    cudaFuncSetAttribute(proj_mma, cudaFuncAttributeMaxDynamicSharedMemorySize, PJ_SMEM_B);
    cudaFuncSetAttribute(attn_mma, cudaFuncAttributeMaxDynamicSharedMemorySize, AT_SMEM);

    // ---- pack pass ----
    const int nx4 = M_ * D_ / 4;      // 2M vec4
    const int nw4 = D_ * D_ / 4;      // 64K vec4
    pack_f32<<<(nx4 + 255) / 256, 256>>>((const float4*)x_Q, (uint4*)xQp, nx4);
    pack_f32<<<(nx4 + 255) / 256, 256>>>((const float4*)x_K, (uint4*)xKp, nx4);
    pack_f32<<<(nx4 + 255) / 256, 256>>>((const float4*)x_V, (uint4*)xVp, nx4);
    pack_f32<<<(nw4 + 255) / 256, 256>>>((const float4*)Wq, (uint4*)Wqp, nw4);
    pack_f32<<<(nw4 + 255) / 256, 256>>>((const float4*)Wk, (uint4*)Wkp, nw4);
    pack_f32<<<(nw4 + 255) / 256, 256>>>((const float4*)Wv, (uint4*)Wvp, nw4);
    pack_f32<<<(nw4 + 255) / 256, 256>>>((const float4*)Wo, (uint4*)Wop, nw4);

    // scale = 1/sqrt(DH) * log2(e), folded into Q projection (incl. bias)
    const float qscale = 0.125f * 1.4426950408889634f;

    dim3 gproj(D_ / 128, M_ / 128);   // x = n-tiles (4), y = m-tiles (128)
    proj_mma<<<gproj, 512, PJ_SMEM_B>>>(xQp, Wqp, bq, Qp, qscale, 0);
    proj_mma<<<gproj, 512, PJ_SMEM_B>>>(xKp, Wkp, bk, Kp, 1.0f, 0);
    proj_mma<<<gproj, 512, PJ_SMEM_B>>>(xVp, Wvp, bv, Vb, 1.0f, 3);

    dim3 gattn(S_ / 128, H_, B_);
    attn_mma<<<gattn, 256, AT_SMEM>>>(Qp, Kp, Vb, lens, ctxp);

    proj_mma<<<gproj, 512, PJ_SMEM_B>>>(ctxp, Wop, bo, out, 1.0f, 2);
}

// round 8
// speedup vs baseline: 2.3573x; 1.0484x over previous
#include <cuda_runtime.h>
#include <cuda_bf16.h>
#include <cuda_fp16.h>
#include <cstdint>

// Problem constants (fixed by the reference)
#define B_  8
#define S_  2048
#define D_  512
#define H_  8
#define DH_ 64
#define M_  (B_ * S_)          // 16384 rows for all projections

// Scratch (allocation-free rule: __device__ globals)
// Plane-packed fp16 operands: per row of 512 fp32 -> 16 chunks x [32 hi fp16 | 32 lo fp16]
__device__ unsigned short g_xQp[M_ * 1024];
__device__ unsigned short g_xKp[M_ * 1024];
__device__ unsigned short g_xVp[M_ * 1024];
__device__ unsigned short g_Wqp[D_ * 1024];
__device__ unsigned short g_Wkp[D_ * 1024];
__device__ unsigned short g_Wvp[D_ * 1024];
__device__ unsigned short g_Wop[D_ * 1024];
__device__ unsigned short g_ctxp[M_ * 1024];             // fp16 planes (for final proj)
__device__ uint32_t       g_Qp[B_ * H_ * S_ * DH_];      // [b,h,s,d] packed (hi,lo) bf16
__device__ uint32_t       g_Kp[B_ * H_ * S_ * DH_];      // [b,h,s,d] packed (hi,lo) bf16
__device__ unsigned short g_Vb[B_ * H_ * DH_ * 2 * S_];  // [b,h,d,k'] blocked hi8|lo8 bf16

__device__ __forceinline__ float ex2f(float x) {
    float y;
    asm("ex2.approx.f32 %0, %1;" : "=f"(y) : "f"(x));
    return y;
}

__device__ __forceinline__ uint32_t smem_u32(const void* p) {
    uint32_t a;
    asm("{ .reg .u64 t; cvta.to.shared.u64 t, %1; cvt.u32.u64 %0, t; }" : "=r"(a) : "l"(p));
    return a;
}

__device__ __forceinline__ void cp16(uint32_t dst, const void* src) {
    asm volatile("cp.async.cg.shared.global [%0], [%1], 16;" :: "r"(dst), "l"(src) : "memory");
}
#define CP_COMMIT() asm volatile("cp.async.commit_group;" ::: "memory")
template <int N>
__device__ __forceinline__ void cp_wait() {
    asm volatile("cp.async.wait_group %0;" :: "n"(N) : "memory");
}

__device__ __forceinline__ void ldmatrix4(uint32_t* r, uint32_t addr) {
    asm volatile("ldmatrix.sync.aligned.m8n8.x4.shared.b16 {%0,%1,%2,%3}, [%4];"
                 : "=r"(r[0]), "=r"(r[1]), "=r"(r[2]), "=r"(r[3]) : "r"(addr));
}

__device__ __forceinline__ void mma_bf16(float* d, uint32_t a0, uint32_t a1,
                                         uint32_t a2, uint32_t a3,
                                         uint32_t b0, uint32_t b1) {
    asm volatile(
        "mma.sync.aligned.m16n8k16.row.col.f32.bf16.bf16.f32 "
        "{%0,%1,%2,%3}, {%4,%5,%6,%7}, {%8,%9}, {%0,%1,%2,%3};"
        : "+f"(d[0]), "+f"(d[1]), "+f"(d[2]), "+f"(d[3])
        : "r"(a0), "r"(a1), "r"(a2), "r"(a3), "r"(b0), "r"(b1));
}

__device__ __forceinline__ void mma_f16(float* d, const uint32_t* a,
                                        uint32_t b0, uint32_t b1) {
    asm volatile(
        "mma.sync.aligned.m16n8k16.row.col.f32.f16.f16.f32 "
        "{%0,%1,%2,%3}, {%4,%5,%6,%7}, {%8,%9}, {%0,%1,%2,%3};"
        : "+f"(d[0]), "+f"(d[1]), "+f"(d[2]), "+f"(d[3])
        : "r"(a[0]), "r"(a[1]), "r"(a[2]), "r"(a[3]), "r"(b0), "r"(b1));
}

// fp32 -> (hi, lo) bf16 pair packed in one u32 (attn operand format)
__device__ __forceinline__ uint32_t bfsplit(float f) {
    __nv_bfloat16 h = __float2bfloat16_rn(f);
    float hf = __bfloat162float(h);
    __nv_bfloat16 l = __float2bfloat16_rn(f - hf);
    return (uint32_t)__bfloat16_as_ushort(h) | ((uint32_t)__bfloat16_as_ushort(l) << 16);
}

// swap 16-bit halves of a packed bf16x2 (hi<->lo) for cross-term MMA
__device__ __forceinline__ uint32_t swap16(uint32_t x) {
    return __byte_perm(x, x, 0x1032);
}

// fp32 -> fp16 hi/lo bits
__device__ __forceinline__ void hsplit(float f, unsigned short& hi, unsigned short& lo) {
    __half h = __float2half_rn(f);
    float hf = __half2float(h);
    __half l = __float2half_rn(f - hf);
    hi = __half_as_ushort(h);
    lo = __half_as_ushort(l);
}

// ============================================================================
// Pack pass: fp32 row-major [rows,512] -> fp16 planes:
//   per row: 16 chunks of 32 values -> [32 hi fp16 | 32 lo fp16] (128B/chunk)
// ============================================================================
struct PackArgs {
    const float*    src[4];
    unsigned short* dst[4];
    int n;
};

__global__ __launch_bounds__(256) void pack_planes(PackArgs pa)
{
    const float* src = pa.src[blockIdx.y];
    unsigned short* dst = pa.dst[blockIdx.y];
    int e = (blockIdx.x * 256 + threadIdx.x) * 8;
    if (e >= pa.n) return;

    float4 v0 = *(const float4*)(src + e);
    float4 v1 = *(const float4*)(src + e + 4);
    int row = e >> 9;
    int k = e & 511;
    int c = k >> 5;
    int j = k & 31;
    unsigned short hb[8], lb[8];
    hsplit(v0.x, hb[0], lb[0]); hsplit(v0.y, hb[1], lb[1]);
    hsplit(v0.z, hb[2], lb[2]); hsplit(v0.w, hb[3], lb[3]);
    hsplit(v1.x, hb[4], lb[4]); hsplit(v1.y, hb[5], lb[5]);
    hsplit(v1.z, hb[6], lb[6]); hsplit(v1.w, hb[7], lb[7]);
    unsigned short* base = dst + (size_t)row * 1024 + c * 64 + j;
    *(uint4*)(base)      = *(uint4*)hb;
    *(uint4*)(base + 32) = *(uint4*)lb;
}

// ============================================================================
// 3-term split-fp16 projection GEMM (plane-packed operands, cp.async 4-stage)
//   C = A @ W^T with (hi+lo) fp16 planes; MMAs: hi*hi + hi*lo + lo*hi.
//   CTA 128m x 128n, 512 threads, 16 warps (32x32 warp tiles), chunk = 32 k.
//   mode 0: packed bf16 u32 [b,h,s,d] (Q/K)   mode 2: fp32 [M,512]
//   mode 3: blocked bf16 u16 [b,h,d,k'] hi8|lo8 (V)
//   Batched over blockIdx.z via ProjArgs.
// ============================================================================
struct ProjArgs {
    const unsigned short* A[3];
    const unsigned short* W[3];
    const float* bias[3];
    void* out[3];
    float scale[3];
    int mode[3];
};

#define PJ_STAGE_B 32768                 // A tile 16KB + W tile 16KB (fp16)
#define PJ_SMEM_B  (4 * PJ_STAGE_B)      // 131072 bytes, 4 stages

__global__ __launch_bounds__(512) void proj_mma(ProjArgs pa)
{
    const int z = blockIdx.z;
    const unsigned short* Ap = pa.A[z];
    const unsigned short* Wp = pa.W[z];
    const float* bias = pa.bias[z];
    void* outv = pa.out[z];
    const float scale = pa.scale[z];
    const int mode = pa.mode[z];

    extern __shared__ __align__(16) char smem[];
    const uint32_t sbase = smem_u32(smem);

    const int tid = threadIdx.x;
    const int lane = tid & 31;
    const int warp = tid >> 5;
    const int wm = warp >> 2;          // 0..3
    const int wn = warp & 3;           // 0..3
    const int m0 = blockIdx.y * 128;
    const int n0 = blockIdx.x * 128;

    const int lrow = tid >> 2;         // 0..127 (loader row)
    const int ls0  = (tid & 3) * 2;    // first 16B seg (of 8 per 128B chunk-row)

    auto loadc = [&](int c, int st) {
        const unsigned short* As = Ap + (size_t)(m0 + lrow) * 1024 + c * 64;
        const unsigned short* Ws = Wp + (size_t)(n0 + lrow) * 1024 + c * 64;
        const uint32_t base = sbase + st * PJ_STAGE_B + lrow * 128;
        const int rx = lrow & 7;
#pragma unroll
        for (int j = 0; j < 2; ++j) {
            int seg = ls0 + j;
            uint32_t off = 16u * (uint32_t)(seg ^ rx);
            cp16(base + off,         As + seg * 8);
            cp16(base + 16384 + off, Ws + seg * 8);
        }
        CP_COMMIT();
    };

    float d[2][4][4] = {};
    const int r8 = (lane & 7) + ((lane >> 3) & 1) * 8;   // 0..15 row-in-tile
    const int sh = lane >> 4;                            // 0/1 seg offset

    // ---- prologue: 3 chunks in flight ----
    loadc(0, 0);
    loadc(1, 1);
    loadc(2, 2);

    for (int i = 0; i < 16; ++i) {
        if (i < 14) cp_wait<2>();
        else if (i == 14) cp_wait<1>();
        else cp_wait<0>();
        __syncthreads();

        // compute on stage i%4 (chunk = 32 fp32 k: segs 0-3 hi, 4-7 lo)
        {
            const uint32_t aB = sbase + (i & 3) * PJ_STAGE_B;
            const uint32_t bB = aB + 16384;
#pragma unroll
            for (int s = 0; s < 2; ++s) {
                uint32_t ah[2][4], al[2][4], bh[2][4], bl[2][4];
                const int segh = 2 * s + sh;
                const int segl = segh + 4;
#pragma unroll
                for (int mt = 0; mt < 2; ++mt) {
                    int row = wm * 32 + mt * 16 + r8;
                    int rx = row & 7;
                    ldmatrix4(ah[mt], aB + row * 128 + 16 * (segh ^ rx));
                    ldmatrix4(al[mt], aB + row * 128 + 16 * (segl ^ rx));
                }
#pragma unroll
                for (int g = 0; g < 2; ++g) {
                    int nrow = wn * 32 + g * 16 + r8;
                    int rx = nrow & 7;
                    ldmatrix4(bh[g], bB + nrow * 128 + 16 * (segh ^ rx));
                    ldmatrix4(bl[g], bB + nrow * 128 + 16 * (segl ^ rx));
                }
#pragma unroll
                for (int g = 0; g < 2; ++g)
#pragma unroll
                    for (int q = 0; q < 2; ++q) {
                        const int nt = g * 2 + q;
                        const uint32_t bh0 = bh[g][q], bh1 = bh[g][q + 2];
                        const uint32_t bl0 = bl[g][q], bl1 = bl[g][q + 2];
#pragma unroll
                        for (int mt = 0; mt < 2; ++mt) {
                            mma_f16(d[mt][nt], ah[mt], bh0, bh1);   // hi*hi
                            mma_f16(d[mt][nt], ah[mt], bl0, bl1);   // hi*lo
                            mma_f16(d[mt][nt], al[mt], bh0, bh1);   // lo*hi
                        }
                    }
            }
        }

        if (i + 3 < 16) loadc(i + 3, (i + 3) & 3);
    }

    // ---- epilogue (C frag: lane row = lane/4 (+8), col = (lane%4)*2 (+1)) ----
    const int rql = lane >> 2;
    const int cql = (lane & 3) * 2;
#pragma unroll
    for (int mt = 0; mt < 2; ++mt) {
        int mbase = m0 + wm * 32 + mt * 16 + rql;
#pragma unroll
        for (int nt = 0; nt < 4; ++nt) {
            int n = n0 + wn * 32 + nt * 8 + cql;
            float2 bv = *(const float2*)&bias[n];
#pragma unroll
            for (int rr = 0; rr < 2; ++rr) {
                int m = mbase + rr * 8;
                float v0 = (d[mt][nt][rr * 2 + 0] + bv.x) * scale;
                float v1 = (d[mt][nt][rr * 2 + 1] + bv.y) * scale;
                int b = m >> 11, s = m & 2047;
                int h = n >> 6, dd = n & 63;
                if (mode == 0) {
                    uint2 pv;
                    pv.x = bfsplit(v0);
                    pv.y = bfsplit(v1);
                    *(uint2*)&((uint32_t*)outv)[(((size_t)(b * H_ + h)) * S_ + s) * 64 + dd] = pv;
                } else if (mode == 3) {
                    unsigned short* o16 = (unsigned short*)outv;
                    int blk = ((s >> 3) << 4) + (s & 7);
                    uint32_t p0 = bfsplit(v0), p1 = bfsplit(v1);
                    size_t rb0 = (((size_t)(b * H_ + h)) * DH_ + dd) * (2 * S_);
                    size_t rb1 = rb0 + 2 * S_;
                    o16[rb0 + blk]     = (unsigned short)(p0 & 0xffff);
                    o16[rb0 + blk + 8] = (unsigned short)(p0 >> 16);
                    o16[rb1 + blk]     = (unsigned short)(p1 & 0xffff);
                    o16[rb1 + blk + 8] = (unsigned short)(p1 >> 16);
                } else {
                    float2 v = make_float2(v0, v1);
                    *(float2*)&((float*)outv)[(size_t)m * 512 + n] = v;
                }
            }
        }
    }
}

// ============================================================================
// Tensor-core flash attention (validated R6), split-bf16 exact-product MMAs.
//   CTA: 128q x 64k per tile, 8 warps x 16q. Epilogue writes fp16-plane ctx.
// ============================================================================
#define AT_SQ   0
#define AT_SK   32768
#define AT_SV   (32768 + 2 * 16384)
#define AT_SMEM (32768 + 4 * 16384)    // 98304

__global__ __launch_bounds__(256) void attn_mma(
    const uint32_t* __restrict__ Qp, const uint32_t* __restrict__ Kp,
    const unsigned short* __restrict__ Vb, const int* __restrict__ lens,
    unsigned short* __restrict__ ctxp)
{
    extern __shared__ __align__(16) char smem[];
    const uint32_t sb = smem_u32(smem);

    const int tid = threadIdx.x;
    const int lane = tid & 31;
    const int warp = tid >> 5;
    const int q0 = blockIdx.x * 128;
    const int h = blockIdx.y;
    const int b = blockIdx.z;
    const int len = lens[b];

    const size_t bh = (size_t)(b * H_ + h);
    const uint32_t* Qg = Qp + (bh * S_ + q0) * 64;
    const uint32_t* Kg = Kp + bh * S_ * 64;
    const unsigned short* Vg = Vb + bh * (size_t)DH_ * 2 * S_;

    const int r8 = (lane & 7) + ((lane >> 3) & 1) * 8;   // 0..15
    const int sh = lane >> 4;                            // 0/1
    const int u2 = (lane & 3) * 2;                       // col pair base

    // ---- load Q tile (128 rows x 256B), one commit group ----
#pragma unroll
    for (int j = 0; j < 8; ++j) {
        int idx = j * 256 + tid;
        int row = idx >> 4, seg = idx & 15;
        cp16(sb + AT_SQ + row * 256 + 16 * (seg ^ (row & 7)), Qg + (size_t)row * 64 + seg * 4);
    }
    CP_COMMIT();

    // ---- K/V tile loader (8 cp16/thread, one group) ----
    auto loadKV = [&](int kt0, int buf) {
        const uint32_t dk = sb + AT_SK + buf * 16384;
        const uint32_t dv = sb + AT_SV + buf * 16384;
#pragma unroll
        for (int j = 0; j < 4; ++j) {
            int idx = j * 256 + tid;
            int row = idx >> 4, seg = idx & 15;
            uint32_t off = row * 256 + 16 * (seg ^ (row & 7));
            cp16(dk + off, Kg + ((size_t)(kt0 + row)) * 64 + seg * 4);
            cp16(dv + off, Vg + (size_t)row * 2 * S_ + kt0 * 2 + seg * 8);
        }
        CP_COMMIT();
    };

    loadKV(0, 0);
    cp_wait<0>();
    __syncthreads();

    // ---- extract Q A-frags (register resident) ----
    uint32_t qa[8][4];
    {
        const int qrow = 16 * warp + r8;
        const uint32_t qb = sb + AT_SQ + qrow * 256;
        const int rx = qrow & 7;
#pragma unroll
        for (int t = 0; t < 8; ++t)
            ldmatrix4(qa[t], qb + 16 * ((2 * t + sh) ^ rx));
    }

    float oacc[8][4] = {};
    float m0 = -1e30f, m1 = -1e30f, l0 = 0.f, l1 = 0.f;

    const int nkt = (len + 63) >> 6;

    for (int t = 0; t < nkt; ++t) {
        if (t + 1 < nkt) loadKV((t + 1) * 64, (t + 1) & 1);

        const uint32_t kb = sb + AT_SK + (t & 1) * 16384;
        const uint32_t vb = sb + AT_SV + (t & 1) * 16384;
        const int rx = r8 & 7;

        // ---- S = Q K^T (split-bf16 exact) ----
        float sacc[8][4] = {};
#pragma unroll
        for (int ks = 0; ks < 8; ++ks) {
            const uint32_t soff = 16 * ((2 * ks + sh) ^ rx);
#pragma unroll
            for (int g = 0; g < 4; ++g) {
                uint32_t bf[4];
                ldmatrix4(bf, kb + (16 * g + r8) * 256 + soff);
#pragma unroll
                for (int q = 0; q < 2; ++q) {
                    const int nt = 2 * g + q;
                    const uint32_t b0 = bf[q], b1 = bf[q + 2];
                    mma_bf16(sacc[nt], qa[ks][0], qa[ks][1], qa[ks][2], qa[ks][3], b0, b1);
                    mma_bf16(sacc[nt], qa[ks][0], qa[ks][1], qa[ks][2], qa[ks][3],
                             swap16(b0), swap16(b1));
                }
            }
        }

        // ---- mask tail keys ----
        const int kt0 = t * 64;
        if (kt0 + 64 > len) {
#pragma unroll
            for (int nt = 0; nt < 8; ++nt) {
                int c0 = kt0 + nt * 8 + u2;
                if (c0 >= len)     { sacc[nt][0] = -1e30f; sacc[nt][2] = -1e30f; }
                if (c0 + 1 >= len) { sacc[nt][1] = -1e30f; sacc[nt][3] = -1e30f; }
            }
        }

        // ---- online softmax (rows l/4 and l/4+8; quad shfl reductions) ----
        float mx0 = -1e30f, mx1 = -1e30f;
#pragma unroll
        for (int nt = 0; nt < 8; ++nt) {
            mx0 = fmaxf(mx0, fmaxf(sacc[nt][0], sacc[nt][1]));
            mx1 = fmaxf(mx1, fmaxf(sacc[nt][2], sacc[nt][3]));
        }
        mx0 = fmaxf(mx0, __shfl_xor_sync(0xffffffffu, mx0, 1));
        mx0 = fmaxf(mx0, __shfl_xor_sync(0xffffffffu, mx0, 2));
        mx1 = fmaxf(mx1, __shfl_xor_sync(0xffffffffu, mx1, 1));
        mx1 = fmaxf(mx1, __shfl_xor_sync(0xffffffffu, mx1, 2));

        const float mn0 = fmaxf(m0, mx0), mn1 = fmaxf(m1, mx1);
        const float e0 = ex2f(m0 - mn0), e1 = ex2f(m1 - mn1);
        m0 = mn0; m1 = mn1;

        float s0 = 0.f, s1 = 0.f;
#pragma unroll
        for (int nt = 0; nt < 8; ++nt) {
            float p;
            p = ex2f(sacc[nt][0] - mn0); sacc[nt][0] = p; s0 += p;
            p = ex2f(sacc[nt][1] - mn0); sacc[nt][1] = p; s0 += p;
            p = ex2f(sacc[nt][2] - mn1); sacc[nt][2] = p; s1 += p;
            p = ex2f(sacc[nt][3] - mn1); sacc[nt][3] = p; s1 += p;
        }
        s0 += __shfl_xor_sync(0xffffffffu, s0, 1);
        s0 += __shfl_xor_sync(0xffffffffu, s0, 2);
        s1 += __shfl_xor_sync(0xffffffffu, s1, 1);
        s1 += __shfl_xor_sync(0xffffffffu, s1, 2);
        l0 = l0 * e0 + s0;
        l1 = l1 * e1 + s1;

#pragma unroll
        for (int nt = 0; nt < 8; ++nt) {
            oacc[nt][0] *= e0; oacc[nt][1] *= e0;
            oacc[nt][2] *= e1; oacc[nt][3] *= e1;
        }

        // ---- O += P V (P frags from S C-frags; hi8|lo8 V blocks) ----
#pragma unroll
        for (int g = 0; g < 8; ++g) {
            __nv_bfloat16 h0 = __float2bfloat16_rn(sacc[g][0]);
            __nv_bfloat16 h1 = __float2bfloat16_rn(sacc[g][1]);
            __nv_bfloat16 h2 = __float2bfloat16_rn(sacc[g][2]);
            __nv_bfloat16 h3 = __float2bfloat16_rn(sacc[g][3]);
            __nv_bfloat16 lo0 = __float2bfloat16_rn(sacc[g][0] - __bfloat162float(h0));
            __nv_bfloat16 lo1 = __float2bfloat16_rn(sacc[g][1] - __bfloat162float(h1));
            __nv_bfloat16 lo2 = __float2bfloat16_rn(sacc[g][2] - __bfloat162float(h2));
            __nv_bfloat16 lo3 = __float2bfloat16_rn(sacc[g][3] - __bfloat162float(h3));
            uint32_t a0 = (uint32_t)__bfloat16_as_ushort(h0) | ((uint32_t)__bfloat16_as_ushort(h1) << 16);
            uint32_t a1 = (uint32_t)__bfloat16_as_ushort(h2) | ((uint32_t)__bfloat16_as_ushort(h3) << 16);
            uint32_t a2 = (uint32_t)__bfloat16_as_ushort(lo0) | ((uint32_t)__bfloat16_as_ushort(lo1) << 16);
            uint32_t a3 = (uint32_t)__bfloat16_as_ushort(lo2) | ((uint32_t)__bfloat16_as_ushort(lo3) << 16);

            const uint32_t soff = 16 * ((2 * g + sh) ^ rx);
#pragma unroll
            for (int dt = 0; dt < 4; ++dt) {
                uint32_t vf[4];
                ldmatrix4(vf, vb + (16 * dt + r8) * 256 + soff);
#pragma unroll
                for (int q = 0; q < 2; ++q) {
                    const int nt = 2 * dt + q;
                    mma_bf16(oacc[nt], a0, a1, a2, a3, vf[q], vf[q + 2]);  // hi*hi + lo*lo
                    mma_bf16(oacc[nt], a2, a3, a0, a1, vf[q], vf[q + 2]);  // hi*lo + lo*hi
                }
            }
        }

        if (t + 1 < nkt) cp_wait<0>();
        __syncthreads();
    }

    // ---- write fp16-plane ctx [b, q, n=h*64+d] ----
    const float inv0 = 1.0f / l0;
    const float inv1 = 1.0f / l1;
    const int qg0 = q0 + 16 * warp + (lane >> 2);
    const int qg1 = qg0 + 8;
    const size_t rb0 = ((size_t)b * S_ + qg0) * 1024;
    const size_t rb1 = ((size_t)b * S_ + qg1) * 1024;
#pragma unroll
    for (int nt = 0; nt < 8; ++nt) {
        int n = h * 64 + nt * 8 + u2;
        int c = n >> 5, j = n & 31;
        unsigned short h0, l0b, h1, l1b;
        hsplit(oacc[nt][0] * inv0, h0, l0b);
        hsplit(oacc[nt][1] * inv0, h1, l1b);
        *(uint32_t*)&ctxp[rb0 + c * 64 + j]      = (uint32_t)h0 | ((uint32_t)h1 << 16);
        *(uint32_t*)&ctxp[rb0 + c * 64 + 32 + j] = (uint32_t)l0b | ((uint32_t)l1b << 16);
        hsplit(oacc[nt][2] * inv1, h0, l0b);
        hsplit(oacc[nt][3] * inv1, h1, l1b);
        *(uint32_t*)&ctxp[rb1 + c * 64 + j]      = (uint32_t)h0 | ((uint32_t)h1 << 16);
        *(uint32_t*)&ctxp[rb1 + c * 64 + 32 + j] = (uint32_t)l0b | ((uint32_t)l1b << 16);
    }
}

// ---------------------------------------------------------------------------

extern "C" void kernel_launch(void* const* d_in, const int* in_sizes, int n_in,
                              void* d_out, int out_size)
{
    const float* x_Q = (const float*)d_in[0];
    const float* x_K = (const float*)d_in[1];
    const float* x_V = (const float*)d_in[2];
    const float* Wq  = (const float*)d_in[3];
    const float* bq  = (const float*)d_in[4];
    const float* Wk  = (const float*)d_in[5];
    const float* bk  = (const float*)d_in[6];
    const float* Wv  = (const float*)d_in[7];
    const float* bv  = (const float*)d_in[8];
    const float* Wo  = (const float*)d_in[9];
    const float* bo  = (const float*)d_in[10];
    const int*   lens = (const int*)d_in[11];
    float* out = (float*)d_out;

    unsigned short *xQp, *xKp, *xVp, *Wqp, *Wkp, *Wvp, *Wop, *ctxp, *Vb;
    uint32_t *Qp, *Kp;
    cudaGetSymbolAddress((void**)&xQp, g_xQp);
    cudaGetSymbolAddress((void**)&xKp, g_xKp);
    cudaGetSymbolAddress((void**)&xVp, g_xVp);
    cudaGetSymbolAddress((void**)&Wqp, g_Wqp);
    cudaGetSymbolAddress((void**)&Wkp, g_Wkp);
    cudaGetSymbolAddress((void**)&Wvp, g_Wvp);
    cudaGetSymbolAddress((void**)&Wop, g_Wop);
    cudaGetSymbolAddress((void**)&ctxp, g_ctxp);
    cudaGetSymbolAddress((void**)&Qp,  g_Qp);
    cudaGetSymbolAddress((void**)&Kp,  g_Kp);
    cudaGetSymbolAddress((void**)&Vb,  g_Vb);

    cudaFuncSetAttribute(proj_mma, cudaFuncAttributeMaxDynamicSharedMemorySize, PJ_SMEM_B);
    cudaFuncSetAttribute(attn_mma, cudaFuncAttributeMaxDynamicSharedMemorySize, AT_SMEM);

    // ---- pack passes (2 launches) ----
    {
        PackArgs px;
        px.src[0] = x_Q; px.dst[0] = xQp;
        px.src[1] = x_K; px.dst[1] = xKp;
        px.src[2] = x_V; px.dst[2] = xVp;
        px.src[3] = x_Q; px.dst[3] = xQp;   // unused lane
        px.n = M_ * D_;
        dim3 gx((M_ * D_ / 8 + 255) / 256, 3);
        pack_planes<<<gx, 256>>>(px);

        PackArgs pw;
        pw.src[0] = Wq; pw.dst[0] = Wqp;
        pw.src[1] = Wk; pw.dst[1] = Wkp;
        pw.src[2] = Wv; pw.dst[2] = Wvp;
        pw.src[3] = Wo; pw.dst[3] = Wop;
        pw.n = D_ * D_;
        dim3 gw((D_ * D_ / 8 + 255) / 256, 4);
        pack_planes<<<gw, 256>>>(pw);
    }

    // scale = 1/sqrt(DH) * log2(e), folded into Q projection (incl. bias)
    const float qscale = 0.125f * 1.4426950408889634f;

    // ---- batched Q/K/V projections (one launch) ----
    {
        ProjArgs pa;
        pa.A[0] = xQp; pa.W[0] = Wqp; pa.bias[0] = bq; pa.out[0] = Qp; pa.scale[0] = qscale; pa.mode[0] = 0;
        pa.A[1] = xKp; pa.W[1] = Wkp; pa.bias[1] = bk; pa.out[1] = Kp; pa.scale[1] = 1.0f;   pa.mode[1] = 0;
        pa.A[2] = xVp; pa.W[2] = Wvp; pa.bias[2] = bv; pa.out[2] = Vb; pa.scale[2] = 1.0f;   pa.mode[2] = 3;
        dim3 g(D_ / 128, M_ / 128, 3);
        proj_mma<<<g, 512, PJ_SMEM_B>>>(pa);
    }

    dim3 gattn(S_ / 128, H_, B_);
    attn_mma<<<gattn, 256, AT_SMEM>>>(Qp, Kp, Vb, lens, ctxp);

    // ---- final projection ----
    {
        ProjArgs pa;
        pa.A[0] = ctxp; pa.W[0] = Wop; pa.bias[0] = bo; pa.out[0] = out; pa.scale[0] = 1.0f; pa.mode[0] = 2;
        pa.A[1] = ctxp; pa.W[1] = Wop; pa.bias[1] = bo; pa.out[1] = out; pa.scale[1] = 1.0f; pa.mode[1] = 2;
        pa.A[2] = ctxp; pa.W[2] = Wop; pa.bias[2] = bo; pa.out[2] = out; pa.scale[2] = 1.0f; pa.mode[2] = 2;
        dim3 g(D_ / 128, M_ / 128, 1);
        proj_mma<<<g, 512, PJ_SMEM_B>>>(pa);
    }
}

// round 9
// speedup vs baseline: 2.7137x; 1.1512x over previous
#include <cuda_runtime.h>
#include <cuda_fp16.h>
#include <cstdint>

// Problem constants (fixed by the reference)
#define B_  8
#define S_  2048
#define D_  512
#define H_  8
#define DH_ 64
#define M_  (B_ * S_)          // 16384 rows for all projections

// Scratch (allocation-free rule: __device__ globals)
// Plane-packed fp16: per row of 512 fp32 -> 16 chunks x [32 hi fp16 | 32 lo fp16]
__device__ unsigned short g_xQp[M_ * 1024];
__device__ unsigned short g_xKp[M_ * 1024];
__device__ unsigned short g_xVp[M_ * 1024];
__device__ unsigned short g_Wqp[D_ * 1024];
__device__ unsigned short g_Wkp[D_ * 1024];
__device__ unsigned short g_Wvp[D_ * 1024];
__device__ unsigned short g_Wop[D_ * 1024];
__device__ unsigned short g_ctxp[M_ * 1024];             // fp16 planes (final proj A)
// Attention operands, fp16 planes:
__device__ unsigned short g_Qf[B_ * H_ * S_ * 128];      // [b,h,s, d-planes(128)]
__device__ unsigned short g_Kf[B_ * H_ * S_ * 128];      // [b,h,s, d-planes(128)]
__device__ unsigned short g_Vf[B_ * H_ * DH_ * 4096];    // [b,h,d, k-planes(4096)]

__device__ __forceinline__ float ex2f(float x) {
    float y;
    asm("ex2.approx.f32 %0, %1;" : "=f"(y) : "f"(x));
    return y;
}

__device__ __forceinline__ uint32_t smem_u32(const void* p) {
    uint32_t a;
    asm("{ .reg .u64 t; cvta.to.shared.u64 t, %1; cvt.u32.u64 %0, t; }" : "=r"(a) : "l"(p));
    return a;
}

__device__ __forceinline__ void cp16(uint32_t dst, const void* src) {
    asm volatile("cp.async.cg.shared.global [%0], [%1], 16;" :: "r"(dst), "l"(src) : "memory");
}
#define CP_COMMIT() asm volatile("cp.async.commit_group;" ::: "memory")
template <int N>
__device__ __forceinline__ void cp_wait() {
    asm volatile("cp.async.wait_group %0;" :: "n"(N) : "memory");
}

__device__ __forceinline__ void ldmatrix4(uint32_t* r, uint32_t addr) {
    asm volatile("ldmatrix.sync.aligned.m8n8.x4.shared.b16 {%0,%1,%2,%3}, [%4];"
                 : "=r"(r[0]), "=r"(r[1]), "=r"(r[2]), "=r"(r[3]) : "r"(addr));
}

__device__ __forceinline__ void mma_f16(float* d, const uint32_t* a,
                                        uint32_t b0, uint32_t b1) {
    asm volatile(
        "mma.sync.aligned.m16n8k16.row.col.f32.f16.f16.f32 "
        "{%0,%1,%2,%3}, {%4,%5,%6,%7}, {%8,%9}, {%0,%1,%2,%3};"
        : "+f"(d[0]), "+f"(d[1]), "+f"(d[2]), "+f"(d[3])
        : "r"(a[0]), "r"(a[1]), "r"(a[2]), "r"(a[3]), "r"(b0), "r"(b1));
}

// fp32 -> fp16 hi/lo bits (scalar)
__device__ __forceinline__ void hsplit(float f, unsigned short& hi, unsigned short& lo) {
    __half h = __float2half_rn(f);
    float hf = __half2float(h);
    __half l = __float2half_rn(f - hf);
    hi = __half_as_ushort(h);
    lo = __half_as_ushort(l);
}

// two fp32 -> packed fp16x2 hi pair + lo pair
__device__ __forceinline__ void hsplit2(float x, float y, uint32_t& hi2, uint32_t& lo2) {
    __half2 h = __floats2half2_rn(x, y);
    float2 hf = __half22float2(h);
    __half2 l = __floats2half2_rn(x - hf.x, y - hf.y);
    hi2 = *reinterpret_cast<uint32_t*>(&h);
    lo2 = *reinterpret_cast<uint32_t*>(&l);
}

// ============================================================================
// Pack pass: fp32 row-major [rows,512] -> fp16 planes (16 chunks x [32hi|32lo])
// ============================================================================
struct PackArgs {
    const float*    src[4];
    unsigned short* dst[4];
    int n;
};

__global__ __launch_bounds__(256) void pack_planes(PackArgs pa)
{
    const float* src = pa.src[blockIdx.y];
    unsigned short* dst = pa.dst[blockIdx.y];
    int e = (blockIdx.x * 256 + threadIdx.x) * 8;
    if (e >= pa.n) return;

    float4 v0 = *(const float4*)(src + e);
    float4 v1 = *(const float4*)(src + e + 4);
    int row = e >> 9;
    int k = e & 511;
    int c = k >> 5;
    int j = k & 31;
    unsigned short hb[8], lb[8];
    hsplit(v0.x, hb[0], lb[0]); hsplit(v0.y, hb[1], lb[1]);
    hsplit(v0.z, hb[2], lb[2]); hsplit(v0.w, hb[3], lb[3]);
    hsplit(v1.x, hb[4], lb[4]); hsplit(v1.y, hb[5], lb[5]);
    hsplit(v1.z, hb[6], lb[6]); hsplit(v1.w, hb[7], lb[7]);
    unsigned short* base = dst + (size_t)row * 1024 + c * 64 + j;
    *(uint4*)(base)      = *(uint4*)hb;
    *(uint4*)(base + 32) = *(uint4*)lb;
}

// ============================================================================
// 3-term split-fp16 projection GEMM (plane-packed operands, cp.async 4-stage)
//   C = A @ W^T; MMAs: hi*hi + hi*lo + lo*hi.
//   mode 0: fp16 planes [b,h,s, d-planes] (Q/K for attention)
//   mode 2: fp32 row-major [M,512] (final output)
//   mode 3: fp16 planes [b,h,d, k-planes] (V for attention)
// ============================================================================
struct ProjArgs {
    const unsigned short* A[3];
    const unsigned short* W[3];
    const float* bias[3];
    void* out[3];
    float scale[3];
    int mode[3];
};

#define PJ_STAGE_B 32768                 // A tile 16KB + W tile 16KB (fp16)
#define PJ_SMEM_B  (4 * PJ_STAGE_B)      // 131072 bytes, 4 stages

__global__ __launch_bounds__(512) void proj_mma(ProjArgs pa)
{
    const int z = blockIdx.z;
    const unsigned short* Ap = pa.A[z];
    const unsigned short* Wp = pa.W[z];
    const float* bias = pa.bias[z];
    void* outv = pa.out[z];
    const float scale = pa.scale[z];
    const int mode = pa.mode[z];

    extern __shared__ __align__(16) char smem[];
    const uint32_t sbase = smem_u32(smem);

    const int tid = threadIdx.x;
    const int lane = tid & 31;
    const int warp = tid >> 5;
    const int wm = warp >> 2;          // 0..3
    const int wn = warp & 3;           // 0..3
    const int m0 = blockIdx.y * 128;
    const int n0 = blockIdx.x * 128;

    const int lrow = tid >> 2;         // 0..127 (loader row)
    const int ls0  = (tid & 3) * 2;    // first 16B seg (of 8 per 128B chunk-row)

    auto loadc = [&](int c, int st) {
        const unsigned short* As = Ap + (size_t)(m0 + lrow) * 1024 + c * 64;
        const unsigned short* Ws = Wp + (size_t)(n0 + lrow) * 1024 + c * 64;
        const uint32_t base = sbase + st * PJ_STAGE_B + lrow * 128;
        const int rx = lrow & 7;
#pragma unroll
        for (int j = 0; j < 2; ++j) {
            int seg = ls0 + j;
            uint32_t off = 16u * (uint32_t)(seg ^ rx);
            cp16(base + off,         As + seg * 8);
            cp16(base + 16384 + off, Ws + seg * 8);
        }
        CP_COMMIT();
    };

    float d[2][4][4] = {};
    const int r8 = (lane & 7) + ((lane >> 3) & 1) * 8;   // 0..15 row-in-tile
    const int sh = lane >> 4;                            // 0/1 seg offset

    // ---- prologue: 3 chunks in flight ----
    loadc(0, 0);
    loadc(1, 1);
    loadc(2, 2);

    for (int i = 0; i < 16; ++i) {
        if (i < 14) cp_wait<2>();
        else if (i == 14) cp_wait<1>();
        else cp_wait<0>();
        __syncthreads();

        // compute on stage i%4 (chunk = 32 fp32 k: segs 0-3 hi, 4-7 lo)
        {
            const uint32_t aB = sbase + (i & 3) * PJ_STAGE_B;
            const uint32_t bB = aB + 16384;
#pragma unroll
            for (int s = 0; s < 2; ++s) {
                uint32_t ah[2][4], al[2][4], bh[2][4], bl[2][4];
                const int segh = 2 * s + sh;
                const int segl = segh + 4;
#pragma unroll
                for (int mt = 0; mt < 2; ++mt) {
                    int row = wm * 32 + mt * 16 + r8;
                    int rx = row & 7;
                    ldmatrix4(ah[mt], aB + row * 128 + 16 * (segh ^ rx));
                    ldmatrix4(al[mt], aB + row * 128 + 16 * (segl ^ rx));
                }
#pragma unroll
                for (int g = 0; g < 2; ++g) {
                    int nrow = wn * 32 + g * 16 + r8;
                    int rx = nrow & 7;
                    ldmatrix4(bh[g], bB + nrow * 128 + 16 * (segh ^ rx));
                    ldmatrix4(bl[g], bB + nrow * 128 + 16 * (segl ^ rx));
                }
#pragma unroll
                for (int g = 0; g < 2; ++g)
#pragma unroll
                    for (int q = 0; q < 2; ++q) {
                        const int nt = g * 2 + q;
                        const uint32_t bh0 = bh[g][q], bh1 = bh[g][q + 2];
                        const uint32_t bl0 = bl[g][q], bl1 = bl[g][q + 2];
#pragma unroll
                        for (int mt = 0; mt < 2; ++mt) {
                            mma_f16(d[mt][nt], ah[mt], bh0, bh1);   // hi*hi
                            mma_f16(d[mt][nt], ah[mt], bl0, bl1);   // hi*lo
                            mma_f16(d[mt][nt], al[mt], bh0, bh1);   // lo*hi
                        }
                    }
            }
        }

        if (i + 3 < 16) loadc(i + 3, (i + 3) & 3);
    }

    // ---- epilogue (C frag: lane row = lane/4 (+8), col = (lane%4)*2 (+1)) ----
    const int rql = lane >> 2;
    const int cql = (lane & 3) * 2;
#pragma unroll
    for (int mt = 0; mt < 2; ++mt) {
        int mbase = m0 + wm * 32 + mt * 16 + rql;
#pragma unroll
        for (int nt = 0; nt < 4; ++nt) {
            int n = n0 + wn * 32 + nt * 8 + cql;
            float2 bv = *(const float2*)&bias[n];
#pragma unroll
            for (int rr = 0; rr < 2; ++rr) {
                int m = mbase + rr * 8;
                float v0 = (d[mt][nt][rr * 2 + 0] + bv.x) * scale;
                float v1 = (d[mt][nt][rr * 2 + 1] + bv.y) * scale;
                int b = m >> 11, s = m & 2047;
                int h = n >> 6, dd = n & 63;
                if (mode == 0) {
                    // Q/K fp16 planes: row (b,h,s) of 128: [32hi|32lo] x2 d-chunks
                    unsigned short* o16 = (unsigned short*)outv;
                    uint32_t hi2, lo2;
                    hsplit2(v0, v1, hi2, lo2);
                    size_t rb = (((size_t)(b * H_ + h)) * S_ + s) * 128;
                    int c2 = dd >> 5, j = dd & 31;
                    *(uint32_t*)&o16[rb + c2 * 64 + j]      = hi2;
                    *(uint32_t*)&o16[rb + c2 * 64 + 32 + j] = lo2;
                } else if (mode == 3) {
                    // V fp16 planes: row (b,h,d) of 4096 k': chunk(s>>5): [32hi|32lo]
                    unsigned short* o16 = (unsigned short*)outv;
                    unsigned short h0, l0, h1, l1;
                    hsplit(v0, h0, l0);
                    hsplit(v1, h1, l1);
                    int ck = s >> 5, j = s & 31;
                    size_t rb0 = (((size_t)(b * H_ + h)) * DH_ + dd) * 4096;
                    o16[rb0 + ck * 64 + j]             = h0;
                    o16[rb0 + ck * 64 + 32 + j]        = l0;
                    o16[rb0 + 4096 + ck * 64 + j]      = h1;
                    o16[rb0 + 4096 + ck * 64 + 32 + j] = l1;
                } else {
                    float2 v = make_float2(v0, v1);
                    *(float2*)&((float*)outv)[(size_t)m * 512 + n] = v;
                }
            }
        }
    }
}

// ============================================================================
// Tensor-core flash attention, 3-term split-fp16 MMAs (planes).
//   CTA: 128q x 64k per tile, 8 warps x 16q.
//   Q,K rows: 128 fp16 = 2 d-chunks x [32hi|32lo]. V rows: k-chunks [32hi|32lo].
//   S = Qh*Kh + Qh*Kl + Ql*Kh ; O += Ph*Vh + Ph*Vl + Pl*Vh.
//   Q pre-scaled by (1/sqrt(DH))*log2(e) -> exp == ex2.
// ============================================================================
#define AT_SQ   0
#define AT_SK   32768
#define AT_SV   (32768 + 2 * 16384)
#define AT_SMEM (32768 + 4 * 16384)    // 98304

__global__ __launch_bounds__(256) void attn_mma(
    const unsigned short* __restrict__ Qf, const unsigned short* __restrict__ Kf,
    const unsigned short* __restrict__ Vf, const int* __restrict__ lens,
    unsigned short* __restrict__ ctxp)
{
    extern __shared__ __align__(16) char smem[];
    const uint32_t sb = smem_u32(smem);

    const int tid = threadIdx.x;
    const int lane = tid & 31;
    const int warp = tid >> 5;
    const int q0 = blockIdx.x * 128;
    const int h = blockIdx.y;
    const int b = blockIdx.z;
    const int len = lens[b];

    const size_t bh = (size_t)(b * H_ + h);
    const unsigned short* Qg = Qf + (bh * S_ + q0) * 128;
    const unsigned short* Kg = Kf + bh * S_ * 128;
    const unsigned short* Vg = Vf + bh * (size_t)DH_ * 4096;

    const int r8 = (lane & 7) + ((lane >> 3) & 1) * 8;   // 0..15
    const int sh = lane >> 4;                            // 0/1
    const int u2 = (lane & 3) * 2;                       // col pair base
    const int rx = r8 & 7;

    // d-group seg bases for Q/K planes: kg -> hi seg {0,2,8,10}; lo = +4
    // (chunk c = kg>>1 contributes 8 segs; half hh = kg&1 contributes 2)

    // ---- load Q tile (128 rows x 256B), one commit group ----
#pragma unroll
    for (int j = 0; j < 8; ++j) {
        int idx = j * 256 + tid;
        int row = idx >> 4, seg = idx & 15;
        cp16(sb + AT_SQ + row * 256 + 16 * (seg ^ (row & 7)), Qg + (size_t)row * 128 + seg * 8);
    }
    CP_COMMIT();

    // ---- K/V tile loader (8 cp16/thread, one group) ----
    auto loadKV = [&](int kt0, int buf) {
        const uint32_t dk = sb + AT_SK + buf * 16384;
        const uint32_t dv = sb + AT_SV + buf * 16384;
#pragma unroll
        for (int j = 0; j < 4; ++j) {
            int idx = j * 256 + tid;
            int row = idx >> 4, seg = idx & 15;
            uint32_t off = row * 256 + 16 * (seg ^ (row & 7));
            cp16(dk + off, Kg + ((size_t)(kt0 + row)) * 128 + seg * 8);
            cp16(dv + off, Vg + (size_t)row * 4096 + kt0 * 2 + seg * 8);
        }
        CP_COMMIT();
    };

    loadKV(0, 0);
    cp_wait<0>();
    __syncthreads();

    // ---- extract Q A-frags (register resident): qa[kg][plane] ----
    uint32_t qa[4][2][4];
    {
        const int qrow = 16 * warp + r8;
        const uint32_t qb = sb + AT_SQ + qrow * 256;
#pragma unroll
        for (int kg = 0; kg < 4; ++kg) {
            const int segh = (kg >> 1) * 8 + (kg & 1) * 2 + sh;
            ldmatrix4(qa[kg][0], qb + 16 * (segh ^ rx));
            ldmatrix4(qa[kg][1], qb + 16 * ((segh + 4) ^ rx));
        }
    }

    float oacc[8][4] = {};
    float m0 = -1e30f, m1 = -1e30f, l0 = 0.f, l1 = 0.f;

    const int nkt = (len + 63) >> 6;

    for (int t = 0; t < nkt; ++t) {
        if (t + 1 < nkt) loadKV((t + 1) * 64, (t + 1) & 1);

        const uint32_t kb = sb + AT_SK + (t & 1) * 16384;
        const uint32_t vbuf = sb + AT_SV + (t & 1) * 16384;

        // ---- S = Q K^T (3-term fp16 planes) ----
        float sacc[8][4] = {};
#pragma unroll
        for (int kg = 0; kg < 4; ++kg) {
            const int segh = (kg >> 1) * 8 + (kg & 1) * 2 + sh;
            const uint32_t offh = 16u * (uint32_t)(segh ^ rx);
            const uint32_t offl = 16u * (uint32_t)((segh + 4) ^ rx);
#pragma unroll
            for (int g = 0; g < 4; ++g) {
                uint32_t kh[4], kl[4];
                const uint32_t rowb = kb + (16 * g + r8) * 256;
                ldmatrix4(kh, rowb + offh);
                ldmatrix4(kl, rowb + offl);
#pragma unroll
                for (int q = 0; q < 2; ++q) {
                    const int nt = 2 * g + q;
                    mma_f16(sacc[nt], qa[kg][0], kh[q], kh[q + 2]);  // hi*hi
                    mma_f16(sacc[nt], qa[kg][0], kl[q], kl[q + 2]);  // hi*lo
                    mma_f16(sacc[nt], qa[kg][1], kh[q], kh[q + 2]);  // lo*hi
                }
            }
        }

        // ---- mask tail keys ----
        const int kt0 = t * 64;
        if (kt0 + 64 > len) {
#pragma unroll
            for (int nt = 0; nt < 8; ++nt) {
                int c0 = kt0 + nt * 8 + u2;
                if (c0 >= len)     { sacc[nt][0] = -1e30f; sacc[nt][2] = -1e30f; }
                if (c0 + 1 >= len) { sacc[nt][1] = -1e30f; sacc[nt][3] = -1e30f; }
            }
        }

        // ---- online softmax (rows l/4 and l/4+8; quad shfl reductions) ----
        float mx0 = -1e30f, mx1 = -1e30f;
#pragma unroll
        for (int nt = 0; nt < 8; ++nt) {
            mx0 = fmaxf(mx0, fmaxf(sacc[nt][0], sacc[nt][1]));
            mx1 = fmaxf(mx1, fmaxf(sacc[nt][2], sacc[nt][3]));
        }
        mx0 = fmaxf(mx0, __shfl_xor_sync(0xffffffffu, mx0, 1));
        mx0 = fmaxf(mx0, __shfl_xor_sync(0xffffffffu, mx0, 2));
        mx1 = fmaxf(mx1, __shfl_xor_sync(0xffffffffu, mx1, 1));
        mx1 = fmaxf(mx1, __shfl_xor_sync(0xffffffffu, mx1, 2));

        const float mn0 = fmaxf(m0, mx0), mn1 = fmaxf(m1, mx1);
        const float e0 = ex2f(m0 - mn0), e1 = ex2f(m1 - mn1);
        m0 = mn0; m1 = mn1;

        float s0 = 0.f, s1 = 0.f;
#pragma unroll
        for (int nt = 0; nt < 8; ++nt) {
            float p;
            p = ex2f(sacc[nt][0] - mn0); sacc[nt][0] = p; s0 += p;
            p = ex2f(sacc[nt][1] - mn0); sacc[nt][1] = p; s0 += p;
            p = ex2f(sacc[nt][2] - mn1); sacc[nt][2] = p; s1 += p;
            p = ex2f(sacc[nt][3] - mn1); sacc[nt][3] = p; s1 += p;
        }
        s0 += __shfl_xor_sync(0xffffffffu, s0, 1);
        s0 += __shfl_xor_sync(0xffffffffu, s0, 2);
        s1 += __shfl_xor_sync(0xffffffffu, s1, 1);
        s1 += __shfl_xor_sync(0xffffffffu, s1, 2);
        l0 = l0 * e0 + s0;
        l1 = l1 * e1 + s1;

#pragma unroll
        for (int nt = 0; nt < 8; ++nt) {
            oacc[nt][0] *= e0; oacc[nt][1] *= e0;
            oacc[nt][2] *= e1; oacc[nt][3] *= e1;
        }

        // ---- O += P V (3-term fp16 planes; P split to hi/lo A-frags) ----
#pragma unroll
        for (int kc = 0; kc < 2; ++kc) {          // 32-key chunk
#pragma unroll
            for (int sg = 0; sg < 2; ++sg) {      // k16 subgroup
                const int g0 = 4 * kc + 2 * sg;
                uint32_t ph[4], pl[4];
                hsplit2(sacc[g0][0],     sacc[g0][1],     ph[0], pl[0]);
                hsplit2(sacc[g0][2],     sacc[g0][3],     ph[1], pl[1]);
                hsplit2(sacc[g0 + 1][0], sacc[g0 + 1][1], ph[2], pl[2]);
                hsplit2(sacc[g0 + 1][2], sacc[g0 + 1][3], ph[3], pl[3]);

                const int segh = kc * 8 + sg * 2 + sh;
                const uint32_t offh = 16u * (uint32_t)(segh ^ rx);
                const uint32_t offl = 16u * (uint32_t)((segh + 4) ^ rx);
#pragma unroll
                for (int dt = 0; dt < 4; ++dt) {
                    uint32_t vh[4], vl[4];
                    const uint32_t rowb = vbuf + (16 * dt + r8) * 256;
                    ldmatrix4(vh, rowb + offh);
                    ldmatrix4(vl, rowb + offl);
#pragma unroll
                    for (int q = 0; q < 2; ++q) {
                        const int nt = 2 * dt + q;
                        mma_f16(oacc[nt], ph, vh[q], vh[q + 2]);  // hi*hi
                        mma_f16(oacc[nt], ph, vl[q], vl[q + 2]);  // hi*lo
                        mma_f16(oacc[nt], pl, vh[q], vh[q + 2]);  // lo*hi
                    }
                }
            }
        }

        if (t + 1 < nkt) cp_wait<0>();
        __syncthreads();
    }

    // ---- write fp16-plane ctx [b, q, n=h*64+d] ----
    const float inv0 = 1.0f / l0;
    const float inv1 = 1.0f / l1;
    const int qg0 = q0 + 16 * warp + (lane >> 2);
    const int qg1 = qg0 + 8;
    const size_t rb0 = ((size_t)b * S_ + qg0) * 1024;
    const size_t rb1 = ((size_t)b * S_ + qg1) * 1024;
#pragma unroll
    for (int nt = 0; nt < 8; ++nt) {
        int n = h * 64 + nt * 8 + u2;
        int c = n >> 5, j = n & 31;
        uint32_t hi2, lo2;
        hsplit2(oacc[nt][0] * inv0, oacc[nt][1] * inv0, hi2, lo2);
        *(uint32_t*)&ctxp[rb0 + c * 64 + j]      = hi2;
        *(uint32_t*)&ctxp[rb0 + c * 64 + 32 + j] = lo2;
        hsplit2(oacc[nt][2] * inv1, oacc[nt][3] * inv1, hi2, lo2);
        *(uint32_t*)&ctxp[rb1 + c * 64 + j]      = hi2;
        *(uint32_t*)&ctxp[rb1 + c * 64 + 32 + j] = lo2;
    }
}

// ---------------------------------------------------------------------------

extern "C" void kernel_launch(void* const* d_in, const int* in_sizes, int n_in,
                              void* d_out, int out_size)
{
    const float* x_Q = (const float*)d_in[0];
    const float* x_K = (const float*)d_in[1];
    const float* x_V = (const float*)d_in[2];
    const float* Wq  = (const float*)d_in[3];
    const float* bq  = (const float*)d_in[4];
    const float* Wk  = (const float*)d_in[5];
    const float* bk  = (const float*)d_in[6];
    const float* Wv  = (const float*)d_in[7];
    const float* bv  = (const float*)d_in[8];
    const float* Wo  = (const float*)d_in[9];
    const float* bo  = (const float*)d_in[10];
    const int*   lens = (const int*)d_in[11];
    float* out = (float*)d_out;

    unsigned short *xQp, *xKp, *xVp, *Wqp, *Wkp, *Wvp, *Wop, *ctxp, *Qf, *Kf, *Vf;
    cudaGetSymbolAddress((void**)&xQp, g_xQp);
    cudaGetSymbolAddress((void**)&xKp, g_xKp);
    cudaGetSymbolAddress((void**)&xVp, g_xVp);
    cudaGetSymbolAddress((void**)&Wqp, g_Wqp);
    cudaGetSymbolAddress((void**)&Wkp, g_Wkp);
    cudaGetSymbolAddress((void**)&Wvp, g_Wvp);
    cudaGetSymbolAddress((void**)&Wop, g_Wop);
    cudaGetSymbolAddress((void**)&ctxp, g_ctxp);
    cudaGetSymbolAddress((void**)&Qf,  g_Qf);
    cudaGetSymbolAddress((void**)&Kf,  g_Kf);
    cudaGetSymbolAddress((void**)&Vf,  g_Vf);

    cudaFuncSetAttribute(proj_mma, cudaFuncAttributeMaxDynamicSharedMemorySize, PJ_SMEM_B);
    cudaFuncSetAttribute(attn_mma, cudaFuncAttributeMaxDynamicSharedMemorySize, AT_SMEM);

    // ---- pack passes (2 launches) ----
    {
        PackArgs px;
        px.src[0] = x_Q; px.dst[0] = xQp;
        px.src[1] = x_K; px.dst[1] = xKp;
        px.src[2] = x_V; px.dst[2] = xVp;
        px.src[3] = x_Q; px.dst[3] = xQp;   // unused lane
        px.n = M_ * D_;
        dim3 gx((M_ * D_ / 8 + 255) / 256, 3);
        pack_planes<<<gx, 256>>>(px);

        PackArgs pw;
        pw.src[0] = Wq; pw.dst[0] = Wqp;
        pw.src[1] = Wk; pw.dst[1] = Wkp;
        pw.src[2] = Wv; pw.dst[2] = Wvp;
        pw.src[3] = Wo; pw.dst[3] = Wop;
        pw.n = D_ * D_;
        dim3 gw((D_ * D_ / 8 + 255) / 256, 4);
        pack_planes<<<gw, 256>>>(pw);
    }

    // scale = 1/sqrt(DH) * log2(e), folded into Q projection (incl. bias)
    const float qscale = 0.125f * 1.4426950408889634f;

    // ---- batched Q/K/V projections (one launch) ----
    {
        ProjArgs pa;
        pa.A[0] = xQp; pa.W[0] = Wqp; pa.bias[0] = bq; pa.out[0] = Qf; pa.scale[0] = qscale; pa.mode[0] = 0;
        pa.A[1] = xKp; pa.W[1] = Wkp; pa.bias[1] = bk; pa.out[1] = Kf; pa.scale[1] = 1.0f;   pa.mode[1] = 0;
        pa.A[2] = xVp; pa.W[2] = Wvp; pa.bias[2] = bv; pa.out[2] = Vf; pa.scale[2] = 1.0f;   pa.mode[2] = 3;
        dim3 g(D_ / 128, M_ / 128, 3);
        proj_mma<<<g, 512, PJ_SMEM_B>>>(pa);
    }

    dim3 gattn(S_ / 128, H_, B_);
    attn_mma<<<gattn, 256, AT_SMEM>>>(Qf, Kf, Vf, lens, ctxp);

    // ---- final projection ----
    {
        ProjArgs pa;
        pa.A[0] = ctxp; pa.W[0] = Wop; pa.bias[0] = bo; pa.out[0] = out; pa.scale[0] = 1.0f; pa.mode[0] = 2;
        pa.A[1] = ctxp; pa.W[1] = Wop; pa.bias[1] = bo; pa.out[1] = out; pa.scale[1] = 1.0f; pa.mode[1] = 2;
        pa.A[2] = ctxp; pa.W[2] = Wop; pa.bias[2] = bo; pa.out[2] = out; pa.scale[2] = 1.0f; pa.mode[2] = 2;
        dim3 g(D_ / 128, M_ / 128, 1);
        proj_mma<<<g, 512, PJ_SMEM_B>>>(pa);
    }
}

// round 10
// speedup vs baseline: 3.4303x; 1.2641x over previous
#include <cuda_runtime.h>
#include <cuda_fp16.h>
#include <cstdint>

// Problem constants (fixed by the reference)
#define B_  8
#define S_  2048
#define D_  512
#define H_  8
#define DH_ 64
#define M_  (B_ * S_)          // 16384 rows for all projections

// Scratch (allocation-free rule: __device__ globals)
// Plane-packed fp16: per row of 512 fp32 -> 16 chunks x [32 hi fp16 | 32 lo fp16]
__device__ unsigned short g_xQp[M_ * 1024];
__device__ unsigned short g_xKp[M_ * 1024];
__device__ unsigned short g_xVp[M_ * 1024];
__device__ unsigned short g_Wqp[D_ * 1024];
__device__ unsigned short g_Wkp[D_ * 1024];
__device__ unsigned short g_Wvp[D_ * 1024];
__device__ unsigned short g_Wop[D_ * 1024];
__device__ unsigned short g_ctxp[M_ * 1024];             // fp16 planes (final proj A)
// Attention operands, pure fp16:
__device__ unsigned short g_Qf[B_ * H_ * S_ * DH_];      // [b,h,s,d] fp16
__device__ unsigned short g_Kf[B_ * H_ * S_ * DH_];      // [b,h,s,d] fp16
__device__ unsigned short g_Vf[B_ * H_ * DH_ * S_];      // [b,h,d,s] fp16

__device__ __forceinline__ float ex2f(float x) {
    float y;
    asm("ex2.approx.f32 %0, %1;" : "=f"(y) : "f"(x));
    return y;
}

__device__ __forceinline__ uint32_t smem_u32(const void* p) {
    uint32_t a;
    asm("{ .reg .u64 t; cvta.to.shared.u64 t, %1; cvt.u32.u64 %0, t; }" : "=r"(a) : "l"(p));
    return a;
}

__device__ __forceinline__ void cp16(uint32_t dst, const void* src) {
    asm volatile("cp.async.cg.shared.global [%0], [%1], 16;" :: "r"(dst), "l"(src) : "memory");
}
#define CP_COMMIT() asm volatile("cp.async.commit_group;" ::: "memory")
template <int N>
__device__ __forceinline__ void cp_wait() {
    asm volatile("cp.async.wait_group %0;" :: "n"(N) : "memory");
}

__device__ __forceinline__ void ldmatrix4(uint32_t* r, uint32_t addr) {
    asm volatile("ldmatrix.sync.aligned.m8n8.x4.shared.b16 {%0,%1,%2,%3}, [%4];"
                 : "=r"(r[0]), "=r"(r[1]), "=r"(r[2]), "=r"(r[3]) : "r"(addr));
}

__device__ __forceinline__ void mma_f16(float* d, const uint32_t* a,
                                        uint32_t b0, uint32_t b1) {
    asm volatile(
        "mma.sync.aligned.m16n8k16.row.col.f32.f16.f16.f32 "
        "{%0,%1,%2,%3}, {%4,%5,%6,%7}, {%8,%9}, {%0,%1,%2,%3};"
        : "+f"(d[0]), "+f"(d[1]), "+f"(d[2]), "+f"(d[3])
        : "r"(a[0]), "r"(a[1]), "r"(a[2]), "r"(a[3]), "r"(b0), "r"(b1));
}

// fp32 -> fp16 hi/lo bits (scalar)
__device__ __forceinline__ void hsplit(float f, unsigned short& hi, unsigned short& lo) {
    __half h = __float2half_rn(f);
    float hf = __half2float(h);
    __half l = __float2half_rn(f - hf);
    hi = __half_as_ushort(h);
    lo = __half_as_ushort(l);
}

// two fp32 -> packed fp16x2 hi pair + lo pair
__device__ __forceinline__ void hsplit2(float x, float y, uint32_t& hi2, uint32_t& lo2) {
    __half2 h = __floats2half2_rn(x, y);
    float2 hf = __half22float2(h);
    __half2 l = __floats2half2_rn(x - hf.x, y - hf.y);
    hi2 = *reinterpret_cast<uint32_t*>(&h);
    lo2 = *reinterpret_cast<uint32_t*>(&l);
}

// ============================================================================
// Pack pass: fp32 row-major [rows,512] -> fp16 planes (16 chunks x [32hi|32lo])
// ============================================================================
struct PackArgs {
    const float*    src[4];
    unsigned short* dst[4];
    int n;
};

__global__ __launch_bounds__(256) void pack_planes(PackArgs pa)
{
    const float* src = pa.src[blockIdx.y];
    unsigned short* dst = pa.dst[blockIdx.y];
    int e = (blockIdx.x * 256 + threadIdx.x) * 8;
    if (e >= pa.n) return;

    float4 v0 = *(const float4*)(src + e);
    float4 v1 = *(const float4*)(src + e + 4);
    int row = e >> 9;
    int k = e & 511;
    int c = k >> 5;
    int j = k & 31;
    unsigned short hb[8], lb[8];
    hsplit(v0.x, hb[0], lb[0]); hsplit(v0.y, hb[1], lb[1]);
    hsplit(v0.z, hb[2], lb[2]); hsplit(v0.w, hb[3], lb[3]);
    hsplit(v1.x, hb[4], lb[4]); hsplit(v1.y, hb[5], lb[5]);
    hsplit(v1.z, hb[6], lb[6]); hsplit(v1.w, hb[7], lb[7]);
    unsigned short* base = dst + (size_t)row * 1024 + c * 64 + j;
    *(uint4*)(base)      = *(uint4*)hb;
    *(uint4*)(base + 32) = *(uint4*)lb;
}

// ============================================================================
// Split-fp16 projection GEMM (plane-packed operands, cp.async 4-stage)
//   C = A @ W^T; 3-term: Ah*Wh + Ah*Wl + Al*Wh; 2-term drops Al*Wh.
//   mode 0: fp16 [b,h,s,d] (Q/K for attention)
//   mode 2: fp32 row-major [M,512] (final output)
//   mode 3: fp16 [b,h,d,s] (V for attention)
// ============================================================================
struct ProjArgs {
    const unsigned short* A[3];
    const unsigned short* W[3];
    const float* bias[3];
    void* out[3];
    float scale[3];
    int mode[3];
    int t3[3];      // 1 = 3-term (exact), 0 = 2-term (A fp16-rounded)
};

#define PJ_STAGE_B 32768                 // A tile 16KB + W tile 16KB (fp16)
#define PJ_SMEM_B  (4 * PJ_STAGE_B)      // 131072 bytes, 4 stages

__global__ __launch_bounds__(512) void proj_mma(ProjArgs pa)
{
    const int z = blockIdx.z;
    const unsigned short* Ap = pa.A[z];
    const unsigned short* Wp = pa.W[z];
    const float* bias = pa.bias[z];
    void* outv = pa.out[z];
    const float scale = pa.scale[z];
    const int mode = pa.mode[z];
    const int three = pa.t3[z];

    extern __shared__ __align__(16) char smem[];
    const uint32_t sbase = smem_u32(smem);

    const int tid = threadIdx.x;
    const int lane = tid & 31;
    const int warp = tid >> 5;
    const int wm = warp >> 2;          // 0..3
    const int wn = warp & 3;           // 0..3
    const int m0 = blockIdx.y * 128;
    const int n0 = blockIdx.x * 128;

    const int lrow = tid >> 2;         // 0..127 (loader row)
    const int ls0  = (tid & 3) * 2;    // first 16B seg (of 8 per 128B chunk-row)

    auto loadc = [&](int c, int st) {
        const unsigned short* As = Ap + (size_t)(m0 + lrow) * 1024 + c * 64;
        const unsigned short* Ws = Wp + (size_t)(n0 + lrow) * 1024 + c * 64;
        const uint32_t base = sbase + st * PJ_STAGE_B + lrow * 128;
        const int rx = lrow & 7;
#pragma unroll
        for (int j = 0; j < 2; ++j) {
            int seg = ls0 + j;
            uint32_t off = 16u * (uint32_t)(seg ^ rx);
            cp16(base + off,         As + seg * 8);
            cp16(base + 16384 + off, Ws + seg * 8);
        }
        CP_COMMIT();
    };

    float d[2][4][4] = {};
    const int r8 = (lane & 7) + ((lane >> 3) & 1) * 8;   // 0..15 row-in-tile
    const int sh = lane >> 4;                            // 0/1 seg offset

    // ---- prologue: 3 chunks in flight ----
    loadc(0, 0);
    loadc(1, 1);
    loadc(2, 2);

    for (int i = 0; i < 16; ++i) {
        if (i < 14) cp_wait<2>();
        else if (i == 14) cp_wait<1>();
        else cp_wait<0>();
        __syncthreads();

        // compute on stage i%4 (chunk = 32 fp32 k: segs 0-3 hi, 4-7 lo)
        {
            const uint32_t aB = sbase + (i & 3) * PJ_STAGE_B;
            const uint32_t bB = aB + 16384;
#pragma unroll
            for (int s = 0; s < 2; ++s) {
                uint32_t ah[2][4], al[2][4], bh[2][4], bl[2][4];
                const int segh = 2 * s + sh;
                const int segl = segh + 4;
#pragma unroll
                for (int mt = 0; mt < 2; ++mt) {
                    int row = wm * 32 + mt * 16 + r8;
                    int rx = row & 7;
                    ldmatrix4(ah[mt], aB + row * 128 + 16 * (segh ^ rx));
                    if (three)
                        ldmatrix4(al[mt], aB + row * 128 + 16 * (segl ^ rx));
                }
#pragma unroll
                for (int g = 0; g < 2; ++g) {
                    int nrow = wn * 32 + g * 16 + r8;
                    int rx = nrow & 7;
                    ldmatrix4(bh[g], bB + nrow * 128 + 16 * (segh ^ rx));
                    ldmatrix4(bl[g], bB + nrow * 128 + 16 * (segl ^ rx));
                }
#pragma unroll
                for (int g = 0; g < 2; ++g)
#pragma unroll
                    for (int q = 0; q < 2; ++q) {
                        const int nt = g * 2 + q;
                        const uint32_t bh0 = bh[g][q], bh1 = bh[g][q + 2];
                        const uint32_t bl0 = bl[g][q], bl1 = bl[g][q + 2];
#pragma unroll
                        for (int mt = 0; mt < 2; ++mt) {
                            mma_f16(d[mt][nt], ah[mt], bh0, bh1);      // hi*hi
                            mma_f16(d[mt][nt], ah[mt], bl0, bl1);      // hi*lo
                            if (three)
                                mma_f16(d[mt][nt], al[mt], bh0, bh1);  // lo*hi
                        }
                    }
            }
        }

        if (i + 3 < 16) loadc(i + 3, (i + 3) & 3);
    }

    // ---- epilogue (C frag: lane row = lane/4 (+8), col = (lane%4)*2 (+1)) ----
    const int rql = lane >> 2;
    const int cql = (lane & 3) * 2;
#pragma unroll
    for (int mt = 0; mt < 2; ++mt) {
        int mbase = m0 + wm * 32 + mt * 16 + rql;
#pragma unroll
        for (int nt = 0; nt < 4; ++nt) {
            int n = n0 + wn * 32 + nt * 8 + cql;
            float2 bv = *(const float2*)&bias[n];
#pragma unroll
            for (int rr = 0; rr < 2; ++rr) {
                int m = mbase + rr * 8;
                float v0 = (d[mt][nt][rr * 2 + 0] + bv.x) * scale;
                float v1 = (d[mt][nt][rr * 2 + 1] + bv.y) * scale;
                int b = m >> 11, s = m & 2047;
                int h = n >> 6, dd = n & 63;
                if (mode == 0) {
                    // Q/K fp16 [b,h,s,d]
                    unsigned short* o16 = (unsigned short*)outv;
                    __half2 hv = __floats2half2_rn(v0, v1);
                    *(uint32_t*)&o16[(((size_t)(b * H_ + h)) * S_ + s) * 64 + dd] =
                        *reinterpret_cast<uint32_t*>(&hv);
                } else if (mode == 3) {
                    // V fp16 [b,h,d,s]
                    unsigned short* o16 = (unsigned short*)outv;
                    size_t rb = (((size_t)(b * H_ + h)) * DH_ + dd) * S_ + s;
                    o16[rb]      = __half_as_ushort(__float2half_rn(v0));
                    o16[rb + S_] = __half_as_ushort(__float2half_rn(v1));
                } else {
                    float2 v = make_float2(v0, v1);
                    *(float2*)&((float*)outv)[(size_t)m * 512 + n] = v;
                }
            }
        }
    }
}

// ============================================================================
// Tensor-core flash attention, fp16 S-phase + (Ph+Pl)*Vh PV phase.
//   CTA: 128q x 64k per tile, 8 warps x 16q.
//   Q,K fp16 [b,h,s,64] rows (128B). V fp16 [b,h,d,2048] rows.
//   Q pre-scaled by (1/sqrt(DH))*log2(e) -> exp == ex2.
// ============================================================================
#define AT_SQ   0
#define AT_SK   16384
#define AT_SV   (16384 + 2 * 8192)
#define AT_SMEM (16384 + 4 * 8192)     // 49152

__global__ __launch_bounds__(256) void attn_mma(
    const unsigned short* __restrict__ Qf, const unsigned short* __restrict__ Kf,
    const unsigned short* __restrict__ Vf, const int* __restrict__ lens,
    unsigned short* __restrict__ ctxp)
{
    extern __shared__ __align__(16) char smem[];
    const uint32_t sb = smem_u32(smem);

    const int tid = threadIdx.x;
    const int lane = tid & 31;
    const int warp = tid >> 5;
    const int q0 = blockIdx.x * 128;
    const int h = blockIdx.y;
    const int b = blockIdx.z;
    const int len = lens[b];

    const size_t bh = (size_t)(b * H_ + h);
    const unsigned short* Qg = Qf + (bh * S_ + q0) * 64;
    const unsigned short* Kg = Kf + bh * S_ * 64;
    const unsigned short* Vg = Vf + bh * (size_t)DH_ * S_;

    const int r8 = (lane & 7) + ((lane >> 3) & 1) * 8;   // 0..15
    const int sh = lane >> 4;                            // 0/1
    const int u2 = (lane & 3) * 2;                       // col pair base
    const int rx = r8 & 7;

    // ---- load Q tile (128 rows x 128B), one commit group ----
#pragma unroll
    for (int j = 0; j < 4; ++j) {
        int idx = j * 256 + tid;
        int row = idx >> 3, seg = idx & 7;
        cp16(sb + AT_SQ + row * 128 + 16 * (seg ^ (row & 7)), Qg + (size_t)row * 64 + seg * 8);
    }
    CP_COMMIT();

    // ---- K/V tile loader (4 cp16/thread, one group) ----
    auto loadKV = [&](int kt0, int buf) {
        const uint32_t dk = sb + AT_SK + buf * 8192;
        const uint32_t dv = sb + AT_SV + buf * 8192;
#pragma unroll
        for (int j = 0; j < 2; ++j) {
            int idx = j * 256 + tid;
            int row = idx >> 3, seg = idx & 7;
            uint32_t off = row * 128 + 16 * (seg ^ (row & 7));
            cp16(dk + off, Kg + ((size_t)(kt0 + row)) * 64 + seg * 8);
            cp16(dv + off, Vg + (size_t)row * S_ + kt0 + seg * 8);
        }
        CP_COMMIT();
    };

    loadKV(0, 0);
    cp_wait<0>();
    __syncthreads();

    // ---- extract Q A-frags (register resident): qa[kg] ----
    uint32_t qa[4][4];
    {
        const int qrow = 16 * warp + r8;
        const uint32_t qb = sb + AT_SQ + qrow * 128;
#pragma unroll
        for (int kg = 0; kg < 4; ++kg)
            ldmatrix4(qa[kg], qb + 16 * ((2 * kg + sh) ^ rx));
    }

    float oacc[8][4] = {};
    float m0 = -1e30f, m1 = -1e30f, l0 = 0.f, l1 = 0.f;

    const int nkt = (len + 63) >> 6;

    for (int t = 0; t < nkt; ++t) {
        if (t + 1 < nkt) loadKV((t + 1) * 64, (t + 1) & 1);

        const uint32_t kb = sb + AT_SK + (t & 1) * 8192;
        const uint32_t vbuf = sb + AT_SV + (t & 1) * 8192;

        // ---- S = Q K^T (pure fp16) ----
        float sacc[8][4] = {};
#pragma unroll
        for (int kg = 0; kg < 4; ++kg) {
            const uint32_t off = 16u * (uint32_t)((2 * kg + sh) ^ rx);
#pragma unroll
            for (int g = 0; g < 4; ++g) {
                uint32_t kh[4];
                ldmatrix4(kh, kb + (16 * g + r8) * 128 + off);
#pragma unroll
                for (int q = 0; q < 2; ++q)
                    mma_f16(sacc[2 * g + q], qa[kg], kh[q], kh[q + 2]);
            }
        }

        // ---- mask tail keys ----
        const int kt0 = t * 64;
        if (kt0 + 64 > len) {
#pragma unroll
            for (int nt = 0; nt < 8; ++nt) {
                int c0 = kt0 + nt * 8 + u2;
                if (c0 >= len)     { sacc[nt][0] = -1e30f; sacc[nt][2] = -1e30f; }
                if (c0 + 1 >= len) { sacc[nt][1] = -1e30f; sacc[nt][3] = -1e30f; }
            }
        }

        // ---- online softmax (rows l/4 and l/4+8; quad shfl reductions) ----
        float mx0 = -1e30f, mx1 = -1e30f;
#pragma unroll
        for (int nt = 0; nt < 8; ++nt) {
            mx0 = fmaxf(mx0, fmaxf(sacc[nt][0], sacc[nt][1]));
            mx1 = fmaxf(mx1, fmaxf(sacc[nt][2], sacc[nt][3]));
        }
        mx0 = fmaxf(mx0, __shfl_xor_sync(0xffffffffu, mx0, 1));
        mx0 = fmaxf(mx0, __shfl_xor_sync(0xffffffffu, mx0, 2));
        mx1 = fmaxf(mx1, __shfl_xor_sync(0xffffffffu, mx1, 1));
        mx1 = fmaxf(mx1, __shfl_xor_sync(0xffffffffu, mx1, 2));

        const float mn0 = fmaxf(m0, mx0), mn1 = fmaxf(m1, mx1);
        const float e0 = ex2f(m0 - mn0), e1 = ex2f(m1 - mn1);
        m0 = mn0; m1 = mn1;

        float s0 = 0.f, s1 = 0.f;
#pragma unroll
        for (int nt = 0; nt < 8; ++nt) {
            float p;
            p = ex2f(sacc[nt][0] - mn0); sacc[nt][0] = p; s0 += p;
            p = ex2f(sacc[nt][1] - mn0); sacc[nt][1] = p; s0 += p;
            p = ex2f(sacc[nt][2] - mn1); sacc[nt][2] = p; s1 += p;
            p = ex2f(sacc[nt][3] - mn1); sacc[nt][3] = p; s1 += p;
        }
        s0 += __shfl_xor_sync(0xffffffffu, s0, 1);
        s0 += __shfl_xor_sync(0xffffffffu, s0, 2);
        s1 += __shfl_xor_sync(0xffffffffu, s1, 1);
        s1 += __shfl_xor_sync(0xffffffffu, s1, 2);
        l0 = l0 * e0 + s0;
        l1 = l1 * e1 + s1;

#pragma unroll
        for (int nt = 0; nt < 8; ++nt) {
            oacc[nt][0] *= e0; oacc[nt][1] *= e0;
            oacc[nt][2] *= e1; oacc[nt][3] *= e1;
        }

        // ---- O += (Ph + Pl) Vh ----
#pragma unroll
        for (int u = 0; u < 4; ++u) {          // k16 subgroup
            const int g0 = 2 * u;
            uint32_t ph[4], pl[4];
            hsplit2(sacc[g0][0],     sacc[g0][1],     ph[0], pl[0]);
            hsplit2(sacc[g0][2],     sacc[g0][3],     ph[1], pl[1]);
            hsplit2(sacc[g0 + 1][0], sacc[g0 + 1][1], ph[2], pl[2]);
            hsplit2(sacc[g0 + 1][2], sacc[g0 + 1][3], ph[3], pl[3]);

            const uint32_t off = 16u * (uint32_t)((2 * u + sh) ^ rx);
#pragma unroll
            for (int dt = 0; dt < 4; ++dt) {
                uint32_t vh[4];
                ldmatrix4(vh, vbuf + (16 * dt + r8) * 128 + off);
#pragma unroll
                for (int q = 0; q < 2; ++q) {
                    const int nt = 2 * dt + q;
                    mma_f16(oacc[nt], ph, vh[q], vh[q + 2]);
                    mma_f16(oacc[nt], pl, vh[q], vh[q + 2]);
                }
            }
        }

        if (t + 1 < nkt) cp_wait<0>();
        __syncthreads();
    }

    // ---- write fp16-plane ctx [b, q, n=h*64+d] ----
    const float inv0 = 1.0f / l0;
    const float inv1 = 1.0f / l1;
    const int qg0 = q0 + 16 * warp + (lane >> 2);
    const int qg1 = qg0 + 8;
    const size_t rb0 = ((size_t)b * S_ + qg0) * 1024;
    const size_t rb1 = ((size_t)b * S_ + qg1) * 1024;
#pragma unroll
    for (int nt = 0; nt < 8; ++nt) {
        int n = h * 64 + nt * 8 + u2;
        int c = n >> 5, j = n & 31;
        uint32_t hi2, lo2;
        hsplit2(oacc[nt][0] * inv0, oacc[nt][1] * inv0, hi2, lo2);
        *(uint32_t*)&ctxp[rb0 + c * 64 + j]      = hi2;
        *(uint32_t*)&ctxp[rb0 + c * 64 + 32 + j] = lo2;
        hsplit2(oacc[nt][2] * inv1, oacc[nt][3] * inv1, hi2, lo2);
        *(uint32_t*)&ctxp[rb1 + c * 64 + j]      = hi2;
        *(uint32_t*)&ctxp[rb1 + c * 64 + 32 + j] = lo2;
    }
}

// ---------------------------------------------------------------------------

extern "C" void kernel_launch(void* const* d_in, const int* in_sizes, int n_in,
                              void* d_out, int out_size)
{
    const float* x_Q = (const float*)d_in[0];
    const float* x_K = (const float*)d_in[1];
    const float* x_V = (const float*)d_in[2];
    const float* Wq  = (const float*)d_in[3];
    const float* bq  = (const float*)d_in[4];
    const float* Wk  = (const float*)d_in[5];
    const float* bk  = (const float*)d_in[6];
    const float* Wv  = (const float*)d_in[7];
    const float* bv  = (const float*)d_in[8];
    const float* Wo  = (const float*)d_in[9];
    const float* bo  = (const float*)d_in[10];
    const int*   lens = (const int*)d_in[11];
    float* out = (float*)d_out;

    unsigned short *xQp, *xKp, *xVp, *Wqp, *Wkp, *Wvp, *Wop, *ctxp, *Qf, *Kf, *Vf;
    cudaGetSymbolAddress((void**)&xQp, g_xQp);
    cudaGetSymbolAddress((void**)&xKp, g_xKp);
    cudaGetSymbolAddress((void**)&xVp, g_xVp);
    cudaGetSymbolAddress((void**)&Wqp, g_Wqp);
    cudaGetSymbolAddress((void**)&Wkp, g_Wkp);
    cudaGetSymbolAddress((void**)&Wvp, g_Wvp);
    cudaGetSymbolAddress((void**)&Wop, g_Wop);
    cudaGetSymbolAddress((void**)&ctxp, g_ctxp);
    cudaGetSymbolAddress((void**)&Qf,  g_Qf);
    cudaGetSymbolAddress((void**)&Kf,  g_Kf);
    cudaGetSymbolAddress((void**)&Vf,  g_Vf);

    cudaFuncSetAttribute(proj_mma, cudaFuncAttributeMaxDynamicSharedMemorySize, PJ_SMEM_B);
    cudaFuncSetAttribute(attn_mma, cudaFuncAttributeMaxDynamicSharedMemorySize, AT_SMEM);

    // ---- pack passes (2 launches) ----
    {
        PackArgs px;
        px.src[0] = x_Q; px.dst[0] = xQp;
        px.src[1] = x_K; px.dst[1] = xKp;
        px.src[2] = x_V; px.dst[2] = xVp;
        px.src[3] = x_Q; px.dst[3] = xQp;   // unused lane
        px.n = M_ * D_;
        dim3 gx((M_ * D_ / 8 + 255) / 256, 3);
        pack_planes<<<gx, 256>>>(px);

        PackArgs pw;
        pw.src[0] = Wq; pw.dst[0] = Wqp;
        pw.src[1] = Wk; pw.dst[1] = Wkp;
        pw.src[2] = Wv; pw.dst[2] = Wvp;
        pw.src[3] = Wo; pw.dst[3] = Wop;
        pw.n = D_ * D_;
        dim3 gw((D_ * D_ / 8 + 255) / 256, 4);
        pack_planes<<<gw, 256>>>(pw);
    }

    // scale = 1/sqrt(DH) * log2(e), folded into Q projection (incl. bias)
    const float qscale = 0.125f * 1.4426950408889634f;

    // ---- batched Q/K/V projections (one launch) ----
    {
        ProjArgs pa;
        pa.A[0] = xQp; pa.W[0] = Wqp; pa.bias[0] = bq; pa.out[0] = Qf; pa.scale[0] = qscale; pa.mode[0] = 0; pa.t3[0] = 0;
        pa.A[1] = xKp; pa.W[1] = Wkp; pa.bias[1] = bk; pa.out[1] = Kf; pa.scale[1] = 1.0f;   pa.mode[1] = 0; pa.t3[1] = 0;
        pa.A[2] = xVp; pa.W[2] = Wvp; pa.bias[2] = bv; pa.out[2] = Vf; pa.scale[2] = 1.0f;   pa.mode[2] = 3; pa.t3[2] = 1;
        dim3 g(D_ / 128, M_ / 128, 3);
        proj_mma<<<g, 512, PJ_SMEM_B>>>(pa);
    }

    dim3 gattn(S_ / 128, H_, B_);
    attn_mma<<<gattn, 256, AT_SMEM>>>(Qf, Kf, Vf, lens, ctxp);

    // ---- final projection (3-term exact) ----
    {
        ProjArgs pa;
        pa.A[0] = ctxp; pa.W[0] = Wop; pa.bias[0] = bo; pa.out[0] = out; pa.scale[0] = 1.0f; pa.mode[0] = 2; pa.t3[0] = 1;
        pa.A[1] = ctxp; pa.W[1] = Wop; pa.bias[1] = bo; pa.out[1] = out; pa.scale[1] = 1.0f; pa.mode[1] = 2; pa.t3[1] = 1;
        pa.A[2] = ctxp; pa.W[2] = Wop; pa.bias[2] = bo; pa.out[2] = out; pa.scale[2] = 1.0f; pa.mode[2] = 2; pa.t3[2] = 1;
        dim3 g(D_ / 128, M_ / 128, 1);
        proj_mma<<<g, 512, PJ_SMEM_B>>>(pa);
    }
}

// round 11
// speedup vs baseline: 3.5026x; 1.0211x over previous
#include <cuda_runtime.h>
#include <cuda_fp16.h>
#include <cstdint>

// Problem constants (fixed by the reference)
#define B_  8
#define S_  2048
#define D_  512
#define H_  8
#define DH_ 64
#define M_  (B_ * S_)          // 16384 rows for all projections

// Scratch (allocation-free rule: __device__ globals)
// Plane-packed fp16: per row of 512 fp32 -> 16 chunks x [32 hi fp16 | 32 lo fp16]
__device__ unsigned short g_xQp[M_ * 1024];
__device__ unsigned short g_xKp[M_ * 1024];
__device__ unsigned short g_xVp[M_ * 1024];
__device__ unsigned short g_Wqp[D_ * 1024];
__device__ unsigned short g_Wkp[D_ * 1024];
__device__ unsigned short g_Wvp[D_ * 1024];
__device__ unsigned short g_Wop[D_ * 1024];
__device__ unsigned short g_ctxp[M_ * 1024];             // fp16 planes (final proj A)
// Attention operands, pure fp16:
__device__ unsigned short g_Qf[B_ * H_ * S_ * DH_];      // [b,h,s,d] fp16
__device__ unsigned short g_Kf[B_ * H_ * S_ * DH_];      // [b,h,s,d] fp16
__device__ unsigned short g_Vf[B_ * H_ * DH_ * S_];      // [b,h,d,s] fp16

__device__ __forceinline__ float ex2f(float x) {
    float y;
    asm("ex2.approx.f32 %0, %1;" : "=f"(y) : "f"(x));
    return y;
}

__device__ __forceinline__ uint32_t smem_u32(const void* p) {
    uint32_t a;
    asm("{ .reg .u64 t; cvta.to.shared.u64 t, %1; cvt.u32.u64 %0, t; }" : "=r"(a) : "l"(p));
    return a;
}

__device__ __forceinline__ void cp16(uint32_t dst, const void* src) {
    asm volatile("cp.async.cg.shared.global [%0], [%1], 16;" :: "r"(dst), "l"(src) : "memory");
}
#define CP_COMMIT() asm volatile("cp.async.commit_group;" ::: "memory")
template <int N>
__device__ __forceinline__ void cp_wait() {
    asm volatile("cp.async.wait_group %0;" :: "n"(N) : "memory");
}

__device__ __forceinline__ void ldmatrix4(uint32_t* r, uint32_t addr) {
    asm volatile("ldmatrix.sync.aligned.m8n8.x4.shared.b16 {%0,%1,%2,%3}, [%4];"
                 : "=r"(r[0]), "=r"(r[1]), "=r"(r[2]), "=r"(r[3]) : "r"(addr));
}

__device__ __forceinline__ void mma_f16(float* d, const uint32_t* a,
                                        uint32_t b0, uint32_t b1) {
    asm volatile(
        "mma.sync.aligned.m16n8k16.row.col.f32.f16.f16.f32 "
        "{%0,%1,%2,%3}, {%4,%5,%6,%7}, {%8,%9}, {%0,%1,%2,%3};"
        : "+f"(d[0]), "+f"(d[1]), "+f"(d[2]), "+f"(d[3])
        : "r"(a[0]), "r"(a[1]), "r"(a[2]), "r"(a[3]), "r"(b0), "r"(b1));
}

// fp32 -> fp16 hi/lo bits (scalar)
__device__ __forceinline__ void hsplit(float f, unsigned short& hi, unsigned short& lo) {
    __half h = __float2half_rn(f);
    float hf = __half2float(h);
    __half l = __float2half_rn(f - hf);
    hi = __half_as_ushort(h);
    lo = __half_as_ushort(l);
}

// two fp32 -> packed fp16x2 hi pair + lo pair
__device__ __forceinline__ void hsplit2(float x, float y, uint32_t& hi2, uint32_t& lo2) {
    __half2 h = __floats2half2_rn(x, y);
    float2 hf = __half22float2(h);
    __half2 l = __floats2half2_rn(x - hf.x, y - hf.y);
    hi2 = *reinterpret_cast<uint32_t*>(&h);
    lo2 = *reinterpret_cast<uint32_t*>(&l);
}

// ============================================================================
// Pack pass: fp32 row-major [rows,512] -> fp16 planes (16 chunks x [32hi|32lo])
// ============================================================================
struct PackArgs {
    const float*    src[4];
    unsigned short* dst[4];
    int n;
};

__global__ __launch_bounds__(256) void pack_planes(PackArgs pa)
{
    const float* src = pa.src[blockIdx.y];
    unsigned short* dst = pa.dst[blockIdx.y];
    int e = (blockIdx.x * 256 + threadIdx.x) * 8;
    if (e >= pa.n) return;

    float4 v0 = *(const float4*)(src + e);
    float4 v1 = *(const float4*)(src + e + 4);
    int row = e >> 9;
    int k = e & 511;
    int c = k >> 5;
    int j = k & 31;
    unsigned short hb[8], lb[8];
    hsplit(v0.x, hb[0], lb[0]); hsplit(v0.y, hb[1], lb[1]);
    hsplit(v0.z, hb[2], lb[2]); hsplit(v0.w, hb[3], lb[3]);
    hsplit(v1.x, hb[4], lb[4]); hsplit(v1.y, hb[5], lb[5]);
    hsplit(v1.z, hb[6], lb[6]); hsplit(v1.w, hb[7], lb[7]);
    unsigned short* base = dst + (size_t)row * 1024 + c * 64 + j;
    *(uint4*)(base)      = *(uint4*)hb;
    *(uint4*)(base + 32) = *(uint4*)lb;
}

// ============================================================================
// Split-fp16 projection GEMM (plane-packed operands, cp.async 4-stage)
//   C = A @ W^T; nterm: 3 = Ah*Wh + Ah*Wl + Al*Wh (exact);
//                 2 = Ah*Wh + Ah*Wl (A fp16-rounded);
//                 1 = Ah*Wh        (both fp16-rounded; for fp16-stored outputs)
//   mode 0: fp16 [b,h,s,d] (Q/K)   mode 2: fp32 [M,512]   mode 3: fp16 [b,h,d,s] (V)
// ============================================================================
struct ProjArgs {
    const unsigned short* A[3];
    const unsigned short* W[3];
    const float* bias[3];
    void* out[3];
    float scale[3];
    int mode[3];
    int nterm[3];
};

#define PJ_STAGE_B 32768                 // A tile 16KB + W tile 16KB (fp16)
#define PJ_SMEM_B  (4 * PJ_STAGE_B)      // 131072 bytes, 4 stages

__global__ __launch_bounds__(512) void proj_mma(ProjArgs pa)
{
    const int z = blockIdx.z;
    const unsigned short* Ap = pa.A[z];
    const unsigned short* Wp = pa.W[z];
    const float* bias = pa.bias[z];
    void* outv = pa.out[z];
    const float scale = pa.scale[z];
    const int mode = pa.mode[z];
    const int nterm = pa.nterm[z];

    extern __shared__ __align__(16) char smem[];
    const uint32_t sbase = smem_u32(smem);

    const int tid = threadIdx.x;
    const int lane = tid & 31;
    const int warp = tid >> 5;
    const int wm = warp >> 2;          // 0..3
    const int wn = warp & 3;           // 0..3
    const int m0 = blockIdx.y * 128;
    const int n0 = blockIdx.x * 128;

    const int lrow = tid >> 2;         // 0..127 (loader row)
    const int ls0  = (tid & 3) * 2;    // first 16B seg (of 8 per 128B chunk-row)

    auto loadc = [&](int c, int st) {
        const unsigned short* As = Ap + (size_t)(m0 + lrow) * 1024 + c * 64;
        const unsigned short* Ws = Wp + (size_t)(n0 + lrow) * 1024 + c * 64;
        const uint32_t base = sbase + st * PJ_STAGE_B + lrow * 128;
        const int rx = lrow & 7;
#pragma unroll
        for (int j = 0; j < 2; ++j) {
            int seg = ls0 + j;
            uint32_t off = 16u * (uint32_t)(seg ^ rx);
            cp16(base + off,         As + seg * 8);
            cp16(base + 16384 + off, Ws + seg * 8);
        }
        CP_COMMIT();
    };

    float d[2][4][4] = {};
    const int r8 = (lane & 7) + ((lane >> 3) & 1) * 8;   // 0..15 row-in-tile
    const int sh = lane >> 4;                            // 0/1 seg offset

    // ---- prologue: 3 chunks in flight ----
    loadc(0, 0);
    loadc(1, 1);
    loadc(2, 2);

    for (int i = 0; i < 16; ++i) {
        if (i < 14) cp_wait<2>();
        else if (i == 14) cp_wait<1>();
        else cp_wait<0>();
        __syncthreads();

        // compute on stage i%4 (chunk = 32 fp32 k: segs 0-3 hi, 4-7 lo)
        {
            const uint32_t aB = sbase + (i & 3) * PJ_STAGE_B;
            const uint32_t bB = aB + 16384;
#pragma unroll
            for (int s = 0; s < 2; ++s) {
                uint32_t ah[2][4], al[2][4], bh[2][4], bl[2][4];
                const int segh = 2 * s + sh;
                const int segl = segh + 4;
#pragma unroll
                for (int mt = 0; mt < 2; ++mt) {
                    int row = wm * 32 + mt * 16 + r8;
                    int rx = row & 7;
                    ldmatrix4(ah[mt], aB + row * 128 + 16 * (segh ^ rx));
                    if (nterm >= 3)
                        ldmatrix4(al[mt], aB + row * 128 + 16 * (segl ^ rx));
                }
#pragma unroll
                for (int g = 0; g < 2; ++g) {
                    int nrow = wn * 32 + g * 16 + r8;
                    int rx = nrow & 7;
                    ldmatrix4(bh[g], bB + nrow * 128 + 16 * (segh ^ rx));
                    if (nterm >= 2)
                        ldmatrix4(bl[g], bB + nrow * 128 + 16 * (segl ^ rx));
                }
#pragma unroll
                for (int g = 0; g < 2; ++g)
#pragma unroll
                    for (int q = 0; q < 2; ++q) {
                        const int nt = g * 2 + q;
                        const uint32_t bh0 = bh[g][q], bh1 = bh[g][q + 2];
#pragma unroll
                        for (int mt = 0; mt < 2; ++mt) {
                            mma_f16(d[mt][nt], ah[mt], bh0, bh1);              // hi*hi
                            if (nterm >= 2)
                                mma_f16(d[mt][nt], ah[mt], bl[g][q], bl[g][q + 2]);  // hi*lo
                            if (nterm >= 3)
                                mma_f16(d[mt][nt], al[mt], bh0, bh1);          // lo*hi
                        }
                    }
            }
        }

        if (i + 3 < 16) loadc(i + 3, (i + 3) & 3);
    }

    // ---- epilogue (C frag: lane row = lane/4 (+8), col = (lane%4)*2 (+1)) ----
    const int rql = lane >> 2;
    const int cql = (lane & 3) * 2;
#pragma unroll
    for (int mt = 0; mt < 2; ++mt) {
        int mbase = m0 + wm * 32 + mt * 16 + rql;
#pragma unroll
        for (int nt = 0; nt < 4; ++nt) {
            int n = n0 + wn * 32 + nt * 8 + cql;
            float2 bv = *(const float2*)&bias[n];
#pragma unroll
            for (int rr = 0; rr < 2; ++rr) {
                int m = mbase + rr * 8;
                float v0 = (d[mt][nt][rr * 2 + 0] + bv.x) * scale;
                float v1 = (d[mt][nt][rr * 2 + 1] + bv.y) * scale;
                int b = m >> 11, s = m & 2047;
                int h = n >> 6, dd = n & 63;
                if (mode == 0) {
                    // Q/K fp16 [b,h,s,d]
                    unsigned short* o16 = (unsigned short*)outv;
                    __half2 hv = __floats2half2_rn(v0, v1);
                    *(uint32_t*)&o16[(((size_t)(b * H_ + h)) * S_ + s) * 64 + dd] =
                        *reinterpret_cast<uint32_t*>(&hv);
                } else if (mode == 3) {
                    // V fp16 [b,h,d,s]
                    unsigned short* o16 = (unsigned short*)outv;
                    size_t rb = (((size_t)(b * H_ + h)) * DH_ + dd) * S_ + s;
                    o16[rb]      = __half_as_ushort(__float2half_rn(v0));
                    o16[rb + S_] = __half_as_ushort(__float2half_rn(v1));
                } else {
                    float2 v = make_float2(v0, v1);
                    *(float2*)&((float*)outv)[(size_t)m * 512 + n] = v;
                }
            }
        }
    }
}

// ============================================================================
// Tensor-core flash attention, fp16 S-phase + (Ph+Pl)*Vh PV phase.
//   CTA: 128q x 64k per tile, 8 warps x 16q.
//   Q,K fp16 [b,h,s,64] rows (128B). V fp16 [b,h,d,2048] rows.
//   Q pre-scaled by (1/sqrt(DH))*log2(e) -> exp == ex2.
// ============================================================================
#define AT_SQ   0
#define AT_SK   16384
#define AT_SV   (16384 + 2 * 8192)
#define AT_SMEM (16384 + 4 * 8192)     // 49152

__global__ __launch_bounds__(256) void attn_mma(
    const unsigned short* __restrict__ Qf, const unsigned short* __restrict__ Kf,
    const unsigned short* __restrict__ Vf, const int* __restrict__ lens,
    unsigned short* __restrict__ ctxp)
{
    extern __shared__ __align__(16) char smem[];
    const uint32_t sb = smem_u32(smem);

    const int tid = threadIdx.x;
    const int lane = tid & 31;
    const int warp = tid >> 5;
    const int q0 = blockIdx.x * 128;
    const int h = blockIdx.y;
    const int b = blockIdx.z;
    const int len = lens[b];

    const size_t bh = (size_t)(b * H_ + h);
    const unsigned short* Qg = Qf + (bh * S_ + q0) * 64;
    const unsigned short* Kg = Kf + bh * S_ * 64;
    const unsigned short* Vg = Vf + bh * (size_t)DH_ * S_;

    const int r8 = (lane & 7) + ((lane >> 3) & 1) * 8;   // 0..15
    const int sh = lane >> 4;                            // 0/1
    const int u2 = (lane & 3) * 2;                       // col pair base
    const int rx = r8 & 7;

    // ---- load Q tile (128 rows x 128B), one commit group ----
#pragma unroll
    for (int j = 0; j < 4; ++j) {
        int idx = j * 256 + tid;
        int row = idx >> 3, seg = idx & 7;
        cp16(sb + AT_SQ + row * 128 + 16 * (seg ^ (row & 7)), Qg + (size_t)row * 64 + seg * 8);
    }
    CP_COMMIT();

    // ---- K/V tile loader (4 cp16/thread, one group) ----
    auto loadKV = [&](int kt0, int buf) {
        const uint32_t dk = sb + AT_SK + buf * 8192;
        const uint32_t dv = sb + AT_SV + buf * 8192;
#pragma unroll
        for (int j = 0; j < 2; ++j) {
            int idx = j * 256 + tid;
            int row = idx >> 3, seg = idx & 7;
            uint32_t off = row * 128 + 16 * (seg ^ (row & 7));
            cp16(dk + off, Kg + ((size_t)(kt0 + row)) * 64 + seg * 8);
            cp16(dv + off, Vg + (size_t)row * S_ + kt0 + seg * 8);
        }
        CP_COMMIT();
    };

    loadKV(0, 0);
    cp_wait<0>();
    __syncthreads();

    // ---- extract Q A-frags (register resident): qa[kg] ----
    uint32_t qa[4][4];
    {
        const int qrow = 16 * warp + r8;
        const uint32_t qb = sb + AT_SQ + qrow * 128;
#pragma unroll
        for (int kg = 0; kg < 4; ++kg)
            ldmatrix4(qa[kg], qb + 16 * ((2 * kg + sh) ^ rx));
    }

    float oacc[8][4] = {};
    float m0 = -1e30f, m1 = -1e30f, l0 = 0.f, l1 = 0.f;

    const int nkt = (len + 63) >> 6;

    for (int t = 0; t < nkt; ++t) {
        if (t + 1 < nkt) loadKV((t + 1) * 64, (t + 1) & 1);

        const uint32_t kb = sb + AT_SK + (t & 1) * 8192;
        const uint32_t vbuf = sb + AT_SV + (t & 1) * 8192;

        // ---- S = Q K^T (pure fp16) ----
        float sacc[8][4] = {};
#pragma unroll
        for (int kg = 0; kg < 4; ++kg) {
            const uint32_t off = 16u * (uint32_t)((2 * kg + sh) ^ rx);
#pragma unroll
            for (int g = 0; g < 4; ++g) {
                uint32_t kh[4];
                ldmatrix4(kh, kb + (16 * g + r8) * 128 + off);
#pragma unroll
                for (int q = 0; q < 2; ++q)
                    mma_f16(sacc[2 * g + q], qa[kg], kh[q], kh[q + 2]);
            }
        }

        // ---- mask tail keys ----
        const int kt0 = t * 64;
        if (kt0 + 64 > len) {
#pragma unroll
            for (int nt = 0; nt < 8; ++nt) {
                int c0 = kt0 + nt * 8 + u2;
                if (c0 >= len)     { sacc[nt][0] = -1e30f; sacc[nt][2] = -1e30f; }
                if (c0 + 1 >= len) { sacc[nt][1] = -1e30f; sacc[nt][3] = -1e30f; }
            }
        }

        // ---- online softmax (rows l/4 and l/4+8; quad shfl reductions) ----
        float mx0 = -1e30f, mx1 = -1e30f;
#pragma unroll
        for (int nt = 0; nt < 8; ++nt) {
            mx0 = fmaxf(mx0, fmaxf(sacc[nt][0], sacc[nt][1]));
            mx1 = fmaxf(mx1, fmaxf(sacc[nt][2], sacc[nt][3]));
        }
        mx0 = fmaxf(mx0, __shfl_xor_sync(0xffffffffu, mx0, 1));
        mx0 = fmaxf(mx0, __shfl_xor_sync(0xffffffffu, mx0, 2));
        mx1 = fmaxf(mx1, __shfl_xor_sync(0xffffffffu, mx1, 1));
        mx1 = fmaxf(mx1, __shfl_xor_sync(0xffffffffu, mx1, 2));

        const float mn0 = fmaxf(m0, mx0), mn1 = fmaxf(m1, mx1);
        const float e0 = ex2f(m0 - mn0), e1 = ex2f(m1 - mn1);
        m0 = mn0; m1 = mn1;

        float s0 = 0.f, s1 = 0.f;
#pragma unroll
        for (int nt = 0; nt < 8; ++nt) {
            float p;
            p = ex2f(sacc[nt][0] - mn0); sacc[nt][0] = p; s0 += p;
            p = ex2f(sacc[nt][1] - mn0); sacc[nt][1] = p; s0 += p;
            p = ex2f(sacc[nt][2] - mn1); sacc[nt][2] = p; s1 += p;
            p = ex2f(sacc[nt][3] - mn1); sacc[nt][3] = p; s1 += p;
        }
        s0 += __shfl_xor_sync(0xffffffffu, s0, 1);
        s0 += __shfl_xor_sync(0xffffffffu, s0, 2);
        s1 += __shfl_xor_sync(0xffffffffu, s1, 1);
        s1 += __shfl_xor_sync(0xffffffffu, s1, 2);
        l0 = l0 * e0 + s0;
        l1 = l1 * e1 + s1;

#pragma unroll
        for (int nt = 0; nt < 8; ++nt) {
            oacc[nt][0] *= e0; oacc[nt][1] *= e0;
            oacc[nt][2] *= e1; oacc[nt][3] *= e1;
        }

        // ---- O += (Ph + Pl) Vh ----
#pragma unroll
        for (int u = 0; u < 4; ++u) {          // k16 subgroup
            const int g0 = 2 * u;
            uint32_t ph[4], pl[4];
            hsplit2(sacc[g0][0],     sacc[g0][1],     ph[0], pl[0]);
            hsplit2(sacc[g0][2],     sacc[g0][3],     ph[1], pl[1]);
            hsplit2(sacc[g0 + 1][0], sacc[g0 + 1][1], ph[2], pl[2]);
            hsplit2(sacc[g0 + 1][2], sacc[g0 + 1][3], ph[3], pl[3]);

            const uint32_t off = 16u * (uint32_t)((2 * u + sh) ^ rx);
#pragma unroll
            for (int dt = 0; dt < 4; ++dt) {
                uint32_t vh[4];
                ldmatrix4(vh, vbuf + (16 * dt + r8) * 128 + off);
#pragma unroll
                for (int q = 0; q < 2; ++q) {
                    const int nt = 2 * dt + q;
                    mma_f16(oacc[nt], ph, vh[q], vh[q + 2]);
                    mma_f16(oacc[nt], pl, vh[q], vh[q + 2]);
                }
            }
        }

        if (t + 1 < nkt) cp_wait<0>();
        __syncthreads();
    }

    // ---- write fp16-plane ctx [b, q, n=h*64+d] ----
    const float inv0 = 1.0f / l0;
    const float inv1 = 1.0f / l1;
    const int qg0 = q0 + 16 * warp + (lane >> 2);
    const int qg1 = qg0 + 8;
    const size_t rb0 = ((size_t)b * S_ + qg0) * 1024;
    const size_t rb1 = ((size_t)b * S_ + qg1) * 1024;
#pragma unroll
    for (int nt = 0; nt < 8; ++nt) {
        int n = h * 64 + nt * 8 + u2;
        int c = n >> 5, j = n & 31;
        uint32_t hi2, lo2;
        hsplit2(oacc[nt][0] * inv0, oacc[nt][1] * inv0, hi2, lo2);
        *(uint32_t*)&ctxp[rb0 + c * 64 + j]      = hi2;
        *(uint32_t*)&ctxp[rb0 + c * 64 + 32 + j] = lo2;
        hsplit2(oacc[nt][2] * inv1, oacc[nt][3] * inv1, hi2, lo2);
        *(uint32_t*)&ctxp[rb1 + c * 64 + j]      = hi2;
        *(uint32_t*)&ctxp[rb1 + c * 64 + 32 + j] = lo2;
    }
}

// ---------------------------------------------------------------------------

extern "C" void kernel_launch(void* const* d_in, const int* in_sizes, int n_in,
                              void* d_out, int out_size)
{
    const float* x_Q = (const float*)d_in[0];
    const float* x_K = (const float*)d_in[1];
    const float* x_V = (const float*)d_in[2];
    const float* Wq  = (const float*)d_in[3];
    const float* bq  = (const float*)d_in[4];
    const float* Wk  = (const float*)d_in[5];
    const float* bk  = (const float*)d_in[6];
    const float* Wv  = (const float*)d_in[7];
    const float* bv  = (const float*)d_in[8];
    const float* Wo  = (const float*)d_in[9];
    const float* bo  = (const float*)d_in[10];
    const int*   lens = (const int*)d_in[11];
    float* out = (float*)d_out;

    unsigned short *xQp, *xKp, *xVp, *Wqp, *Wkp, *Wvp, *Wop, *ctxp, *Qf, *Kf, *Vf;
    cudaGetSymbolAddress((void**)&xQp, g_xQp);
    cudaGetSymbolAddress((void**)&xKp, g_xKp);
    cudaGetSymbolAddress((void**)&xVp, g_xVp);
    cudaGetSymbolAddress((void**)&Wqp, g_Wqp);
    cudaGetSymbolAddress((void**)&Wkp, g_Wkp);
    cudaGetSymbolAddress((void**)&Wvp, g_Wvp);
    cudaGetSymbolAddress((void**)&Wop, g_Wop);
    cudaGetSymbolAddress((void**)&ctxp, g_ctxp);
    cudaGetSymbolAddress((void**)&Qf,  g_Qf);
    cudaGetSymbolAddress((void**)&Kf,  g_Kf);
    cudaGetSymbolAddress((void**)&Vf,  g_Vf);

    cudaFuncSetAttribute(proj_mma, cudaFuncAttributeMaxDynamicSharedMemorySize, PJ_SMEM_B);
    cudaFuncSetAttribute(attn_mma, cudaFuncAttributeMaxDynamicSharedMemorySize, AT_SMEM);

    // ---- pack passes (2 launches) ----
    {
        PackArgs px;
        px.src[0] = x_Q; px.dst[0] = xQp;
        px.src[1] = x_K; px.dst[1] = xKp;
        px.src[2] = x_V; px.dst[2] = xVp;
        px.src[3] = x_Q; px.dst[3] = xQp;   // unused lane
        px.n = M_ * D_;
        dim3 gx((M_ * D_ / 8 + 255) / 256, 3);
        pack_planes<<<gx, 256>>>(px);

        PackArgs pw;
        pw.src[0] = Wq; pw.dst[0] = Wqp;
        pw.src[1] = Wk; pw.dst[1] = Wkp;
        pw.src[2] = Wv; pw.dst[2] = Wvp;
        pw.src[3] = Wo; pw.dst[3] = Wop;
        pw.n = D_ * D_;
        dim3 gw((D_ * D_ / 8 + 255) / 256, 4);
        pack_planes<<<gw, 256>>>(pw);
    }

    // scale = 1/sqrt(DH) * log2(e), folded into Q projection (incl. bias)
    const float qscale = 0.125f * 1.4426950408889634f;

    // ---- batched Q/K/V projections (one launch) ----
    // Q,K: 1-term (outputs stored fp16 anyway); V: 2-term; final: 3-term.
    {
        ProjArgs pa;
        pa.A[0] = xQp; pa.W[0] = Wqp; pa.bias[0] = bq; pa.out[0] = Qf; pa.scale[0] = qscale; pa.mode[0] = 0; pa.nterm[0] = 1;
        pa.A[1] = xKp; pa.W[1] = Wkp; pa.bias[1] = bk; pa.out[1] = Kf; pa.scale[1] = 1.0f;   pa.mode[1] = 0; pa.nterm[1] = 1;
        pa.A[2] = xVp; pa.W[2] = Wvp; pa.bias[2] = bv; pa.out[2] = Vf; pa.scale[2] = 1.0f;   pa.mode[2] = 3; pa.nterm[2] = 2;
        dim3 g(D_ / 128, M_ / 128, 3);
        proj_mma<<<g, 512, PJ_SMEM_B>>>(pa);
    }

    dim3 gattn(S_ / 128, H_, B_);
    attn_mma<<<gattn, 256, AT_SMEM>>>(Qf, Kf, Vf, lens, ctxp);

    // ---- final projection (3-term exact) ----
    {
        ProjArgs pa;
        pa.A[0] = ctxp; pa.W[0] = Wop; pa.bias[0] = bo; pa.out[0] = out; pa.scale[0] = 1.0f; pa.mode[0] = 2; pa.nterm[0] = 3;
        pa.A[1] = ctxp; pa.W[1] = Wop; pa.bias[1] = bo; pa.out[1] = out; pa.scale[1] = 1.0f; pa.mode[1] = 2; pa.nterm[1] = 3;
        pa.A[2] = ctxp; pa.W[2] = Wop; pa.bias[2] = bo; pa.out[2] = out; pa.scale[2] = 1.0f; pa.mode[2] = 2; pa.nterm[2] = 3;
        dim3 g(D_ / 128, M_ / 128, 1);
        proj_mma<<<g, 512, PJ_SMEM_B>>>(pa);
    }
}

// round 12
// speedup vs baseline: 4.0674x; 1.1613x over previous
#include <cuda_runtime.h>
#include <cuda_fp16.h>
#include <cstdint>

// Problem constants (fixed by the reference)
#define B_  8
#define S_  2048
#define D_  512
#define H_  8
#define DH_ 64
#define M_  (B_ * S_)          // 16384 rows for all projections

// Scratch (allocation-free rule: __device__ globals)
// Compact per-plane fp16 streams, row-major [rows, 512]
__device__ unsigned short g_xQh[M_ * D_];
__device__ unsigned short g_xKh[M_ * D_];
__device__ unsigned short g_xVh[M_ * D_];
__device__ unsigned short g_Wqh[D_ * D_];
__device__ unsigned short g_Wkh[D_ * D_];
__device__ unsigned short g_Wvh[D_ * D_];
__device__ unsigned short g_Wvl[D_ * D_];
__device__ unsigned short g_Woh[D_ * D_];
__device__ unsigned short g_Wol[D_ * D_];
__device__ unsigned short g_ctxh[M_ * D_];
__device__ unsigned short g_ctxl[M_ * D_];
// Attention operands, pure fp16:
__device__ unsigned short g_Qf[B_ * H_ * S_ * DH_];      // [b,h,s,d] fp16
__device__ unsigned short g_Kf[B_ * H_ * S_ * DH_];      // [b,h,s,d] fp16
__device__ unsigned short g_Vf[B_ * H_ * DH_ * S_];      // [b,h,d,s] fp16

__device__ __forceinline__ float ex2f(float x) {
    float y;
    asm("ex2.approx.f32 %0, %1;" : "=f"(y) : "f"(x));
    return y;
}

__device__ __forceinline__ uint32_t smem_u32(const void* p) {
    uint32_t a;
    asm("{ .reg .u64 t; cvta.to.shared.u64 t, %1; cvt.u32.u64 %0, t; }" : "=r"(a) : "l"(p));
    return a;
}

__device__ __forceinline__ void cp16(uint32_t dst, const void* src) {
    asm volatile("cp.async.cg.shared.global [%0], [%1], 16;" :: "r"(dst), "l"(src) : "memory");
}
#define CP_COMMIT() asm volatile("cp.async.commit_group;" ::: "memory")
template <int N>
__device__ __forceinline__ void cp_wait() {
    asm volatile("cp.async.wait_group %0;" :: "n"(N) : "memory");
}

__device__ __forceinline__ void ldmatrix4(uint32_t* r, uint32_t addr) {
    asm volatile("ldmatrix.sync.aligned.m8n8.x4.shared.b16 {%0,%1,%2,%3}, [%4];"
                 : "=r"(r[0]), "=r"(r[1]), "=r"(r[2]), "=r"(r[3]) : "r"(addr));
}

__device__ __forceinline__ void mma_f16(float* d, const uint32_t* a,
                                        uint32_t b0, uint32_t b1) {
    asm volatile(
        "mma.sync.aligned.m16n8k16.row.col.f32.f16.f16.f32 "
        "{%0,%1,%2,%3}, {%4,%5,%6,%7}, {%8,%9}, {%0,%1,%2,%3};"
        : "+f"(d[0]), "+f"(d[1]), "+f"(d[2]), "+f"(d[3])
        : "r"(a[0]), "r"(a[1]), "r"(a[2]), "r"(a[3]), "r"(b0), "r"(b1));
}

// fp32 -> fp16 hi/lo bits (scalar)
__device__ __forceinline__ void hsplit(float f, unsigned short& hi, unsigned short& lo) {
    __half h = __float2half_rn(f);
    float hf = __half2float(h);
    __half l = __float2half_rn(f - hf);
    hi = __half_as_ushort(h);
    lo = __half_as_ushort(l);
}

// two fp32 -> packed fp16x2 hi pair + lo pair
__device__ __forceinline__ void hsplit2(float x, float y, uint32_t& hi2, uint32_t& lo2) {
    __half2 h = __floats2half2_rn(x, y);
    float2 hf = __half22float2(h);
    __half2 l = __floats2half2_rn(x - hf.x, y - hf.y);
    hi2 = *reinterpret_cast<uint32_t*>(&h);
    lo2 = *reinterpret_cast<uint32_t*>(&l);
}

// ============================================================================
// Pack pass: fp32 row-major -> compact fp16 hi stream (+ optional lo stream)
// ============================================================================
struct PackArgs {
    const float*    src[4];
    unsigned short* dh[4];
    unsigned short* dl[4];     // null -> skip lo
    int n;
};

__global__ __launch_bounds__(256) void pack_h16(PackArgs pa)
{
    const float* src = pa.src[blockIdx.y];
    unsigned short* dh = pa.dh[blockIdx.y];
    unsigned short* dl = pa.dl[blockIdx.y];
    int e = (blockIdx.x * 256 + threadIdx.x) * 8;
    if (e >= pa.n) return;

    float4 v0 = *(const float4*)(src + e);
    float4 v1 = *(const float4*)(src + e + 4);
    unsigned short hb[8], lb[8];
    hsplit(v0.x, hb[0], lb[0]); hsplit(v0.y, hb[1], lb[1]);
    hsplit(v0.z, hb[2], lb[2]); hsplit(v0.w, hb[3], lb[3]);
    hsplit(v1.x, hb[4], lb[4]); hsplit(v1.y, hb[5], lb[5]);
    hsplit(v1.z, hb[6], lb[6]); hsplit(v1.w, hb[7], lb[7]);
    *(uint4*)(dh + e) = *(uint4*)hb;
    if (dl) *(uint4*)(dl + e) = *(uint4*)lb;
}

// ============================================================================
// Split-fp16 projection GEMM, compact per-plane streams, cp.async 3-stage.
//   C = A @ W^T;  nterm: 1 = Ah*Wh;  2 = +Ah*Wl;  3 = +Al*Wh (exact).
//   Chunk = 64 k (128B compact rows), 8 chunks, streams loaded per nterm.
//   mode 0: fp16 [b,h,s,d] (Q/K)   mode 2: fp32 [M,512]   mode 3: fp16 [b,h,d,s] (V)
// ============================================================================
struct ProjArgs {
    const unsigned short* Ah[3];
    const unsigned short* Al[3];
    const unsigned short* Wh[3];
    const unsigned short* Wl[3];
    const float* bias[3];
    void* out[3];
    float scale[3];
    int mode[3];
    int nterm[3];
};

#define PJ_SMEM_MAX (3 * 65536)   // 3 stages x up to 4 streams x 16KB

__global__ __launch_bounds__(512) void proj_mma(ProjArgs pa, int stage_b)
{
    const int z = blockIdx.z;
    const unsigned short* Ahp = pa.Ah[z];
    const unsigned short* Alp = pa.Al[z];
    const unsigned short* Whp = pa.Wh[z];
    const unsigned short* Wlp = pa.Wl[z];
    const float* bias = pa.bias[z];
    void* outv = pa.out[z];
    const float scale = pa.scale[z];
    const int mode = pa.mode[z];
    const int nterm = pa.nterm[z];

    extern __shared__ __align__(16) char smem[];
    const uint32_t sbase = smem_u32(smem);

    const int tid = threadIdx.x;
    const int lane = tid & 31;
    const int warp = tid >> 5;
    const int wm = warp >> 2;          // 0..3
    const int wn = warp & 3;           // 0..3
    const int m0 = blockIdx.y * 128;
    const int n0 = blockIdx.x * 128;

    const int lrow = tid >> 2;         // 0..127 (loader row)
    const int ls0  = (tid & 3) * 2;    // first 16B seg (of 8 per 128B chunk-row)

    // stream offsets within a stage: [Ah][Wh][Wl][Al]
    auto loadc = [&](int c, int st) {
        const uint32_t base = sbase + st * stage_b + lrow * 128;
        const int rx = lrow & 7;
        const size_t arow = (size_t)(m0 + lrow) * 512 + c * 64;
        const size_t wrow = (size_t)(n0 + lrow) * 512 + c * 64;
#pragma unroll
        for (int j = 0; j < 2; ++j) {
            int seg = ls0 + j;
            uint32_t off = 16u * (uint32_t)(seg ^ rx);
            cp16(base + off,         Ahp + arow + seg * 8);
            cp16(base + 16384 + off, Whp + wrow + seg * 8);
            if (nterm >= 2) cp16(base + 32768 + off, Wlp + wrow + seg * 8);
            if (nterm >= 3) cp16(base + 49152 + off, Alp + arow + seg * 8);
        }
        CP_COMMIT();
    };

    float d[2][4][4] = {};
    const int r8 = (lane & 7) + ((lane >> 3) & 1) * 8;   // 0..15 row-in-tile
    const int sh = lane >> 4;                            // 0/1 seg offset

    // ---- prologue: 2 chunks in flight ----
    loadc(0, 0);
    loadc(1, 1);

    for (int i = 0; i < 8; ++i) {
        if (i < 7) cp_wait<1>(); else cp_wait<0>();
        __syncthreads();

        // compute on stage i%3 (chunk = 64 k = 4 k16 groups)
        {
            const uint32_t aB  = sbase + (i % 3) * stage_b;
            const uint32_t bB  = aB + 16384;
            const uint32_t blB = aB + 32768;
            const uint32_t alB = aB + 49152;
#pragma unroll
            for (int ks = 0; ks < 4; ++ks) {
                uint32_t ah[2][4], al[2][4], bh[2][4], bl[2][4];
                const int seg = 2 * ks + sh;
#pragma unroll
                for (int mt = 0; mt < 2; ++mt) {
                    int row = wm * 32 + mt * 16 + r8;
                    int rx = row & 7;
                    ldmatrix4(ah[mt], aB + row * 128 + 16 * (seg ^ rx));
                    if (nterm >= 3)
                        ldmatrix4(al[mt], alB + row * 128 + 16 * (seg ^ rx));
                }
#pragma unroll
                for (int g = 0; g < 2; ++g) {
                    int nrow = wn * 32 + g * 16 + r8;
                    int rx = nrow & 7;
                    ldmatrix4(bh[g], bB + nrow * 128 + 16 * (seg ^ rx));
                    if (nterm >= 2)
                        ldmatrix4(bl[g], blB + nrow * 128 + 16 * (seg ^ rx));
                }
#pragma unroll
                for (int g = 0; g < 2; ++g)
#pragma unroll
                    for (int q = 0; q < 2; ++q) {
                        const int nt = g * 2 + q;
                        const uint32_t bh0 = bh[g][q], bh1 = bh[g][q + 2];
#pragma unroll
                        for (int mt = 0; mt < 2; ++mt) {
                            mma_f16(d[mt][nt], ah[mt], bh0, bh1);                    // hi*hi
                            if (nterm >= 2)
                                mma_f16(d[mt][nt], ah[mt], bl[g][q], bl[g][q + 2]);  // hi*lo
                            if (nterm >= 3)
                                mma_f16(d[mt][nt], al[mt], bh0, bh1);                // lo*hi
                        }
                    }
            }
        }

        if (i + 2 < 8) loadc(i + 2, (i + 2) % 3);
    }

    // ---- epilogue (C frag: lane row = lane/4 (+8), col = (lane%4)*2 (+1)) ----
    const int rql = lane >> 2;
    const int cql = (lane & 3) * 2;
#pragma unroll
    for (int mt = 0; mt < 2; ++mt) {
        int mbase = m0 + wm * 32 + mt * 16 + rql;
#pragma unroll
        for (int nt = 0; nt < 4; ++nt) {
            int n = n0 + wn * 32 + nt * 8 + cql;
            float2 bv = *(const float2*)&bias[n];
#pragma unroll
            for (int rr = 0; rr < 2; ++rr) {
                int m = mbase + rr * 8;
                float v0 = (d[mt][nt][rr * 2 + 0] + bv.x) * scale;
                float v1 = (d[mt][nt][rr * 2 + 1] + bv.y) * scale;
                int b = m >> 11, s = m & 2047;
                int h = n >> 6, dd = n & 63;
                if (mode == 0) {
                    // Q/K fp16 [b,h,s,d]
                    unsigned short* o16 = (unsigned short*)outv;
                    __half2 hv = __floats2half2_rn(v0, v1);
                    *(uint32_t*)&o16[(((size_t)(b * H_ + h)) * S_ + s) * 64 + dd] =
                        *reinterpret_cast<uint32_t*>(&hv);
                } else if (mode == 3) {
                    // V fp16 [b,h,d,s]
                    unsigned short* o16 = (unsigned short*)outv;
                    size_t rb = (((size_t)(b * H_ + h)) * DH_ + dd) * S_ + s;
                    o16[rb]      = __half_as_ushort(__float2half_rn(v0));
                    o16[rb + S_] = __half_as_ushort(__float2half_rn(v1));
                } else {
                    float2 v = make_float2(v0, v1);
                    *(float2*)&((float*)outv)[(size_t)m * 512 + n] = v;
                }
            }
        }
    }
}

// ============================================================================
// Tensor-core flash attention, fp16 S-phase + Ph*Vh PV phase.
//   CTA: 128q x 64k per tile, 8 warps x 16q.
//   Q,K fp16 [b,h,s,64] rows (128B). V fp16 [b,h,d,2048] rows.
//   Q pre-scaled by (1/sqrt(DH))*log2(e) -> exp == ex2.
// ============================================================================
#define AT_SQ   0
#define AT_SK   16384
#define AT_SV   (16384 + 2 * 8192)
#define AT_SMEM (16384 + 4 * 8192)     // 49152

__global__ __launch_bounds__(256) void attn_mma(
    const unsigned short* __restrict__ Qf, const unsigned short* __restrict__ Kf,
    const unsigned short* __restrict__ Vf, const int* __restrict__ lens,
    unsigned short* __restrict__ ctxh, unsigned short* __restrict__ ctxl)
{
    extern __shared__ __align__(16) char smem[];
    const uint32_t sb = smem_u32(smem);

    const int tid = threadIdx.x;
    const int lane = tid & 31;
    const int warp = tid >> 5;
    const int q0 = blockIdx.x * 128;
    const int h = blockIdx.y;
    const int b = blockIdx.z;
    const int len = lens[b];

    const size_t bh = (size_t)(b * H_ + h);
    const unsigned short* Qg = Qf + (bh * S_ + q0) * 64;
    const unsigned short* Kg = Kf + bh * S_ * 64;
    const unsigned short* Vg = Vf + bh * (size_t)DH_ * S_;

    const int r8 = (lane & 7) + ((lane >> 3) & 1) * 8;   // 0..15
    const int sh = lane >> 4;                            // 0/1
    const int u2 = (lane & 3) * 2;                       // col pair base
    const int rx = r8 & 7;

    // ---- load Q tile (128 rows x 128B), one commit group ----
#pragma unroll
    for (int j = 0; j < 4; ++j) {
        int idx = j * 256 + tid;
        int row = idx >> 3, seg = idx & 7;
        cp16(sb + AT_SQ + row * 128 + 16 * (seg ^ (row & 7)), Qg + (size_t)row * 64 + seg * 8);
    }
    CP_COMMIT();

    // ---- K/V tile loader (4 cp16/thread, one group) ----
    auto loadKV = [&](int kt0, int buf) {
        const uint32_t dk = sb + AT_SK + buf * 8192;
        const uint32_t dv = sb + AT_SV + buf * 8192;
#pragma unroll
        for (int j = 0; j < 2; ++j) {
            int idx = j * 256 + tid;
            int row = idx >> 3, seg = idx & 7;
            uint32_t off = row * 128 + 16 * (seg ^ (row & 7));
            cp16(dk + off, Kg + ((size_t)(kt0 + row)) * 64 + seg * 8);
            cp16(dv + off, Vg + (size_t)row * S_ + kt0 + seg * 8);
        }
        CP_COMMIT();
    };

    loadKV(0, 0);
    cp_wait<0>();
    __syncthreads();

    // ---- extract Q A-frags (register resident): qa[kg] ----
    uint32_t qa[4][4];
    {
        const int qrow = 16 * warp + r8;
        const uint32_t qb = sb + AT_SQ + qrow * 128;
#pragma unroll
        for (int kg = 0; kg < 4; ++kg)
            ldmatrix4(qa[kg], qb + 16 * ((2 * kg + sh) ^ rx));
    }

    float oacc[8][4] = {};
    float m0 = -1e30f, m1 = -1e30f, l0 = 0.f, l1 = 0.f;

    const int nkt = (len + 63) >> 6;

    for (int t = 0; t < nkt; ++t) {
        if (t + 1 < nkt) loadKV((t + 1) * 64, (t + 1) & 1);

        const uint32_t kb = sb + AT_SK + (t & 1) * 8192;
        const uint32_t vbuf = sb + AT_SV + (t & 1) * 8192;

        // ---- S = Q K^T (pure fp16) ----
        float sacc[8][4] = {};
#pragma unroll
        for (int kg = 0; kg < 4; ++kg) {
            const uint32_t off = 16u * (uint32_t)((2 * kg + sh) ^ rx);
#pragma unroll
            for (int g = 0; g < 4; ++g) {
                uint32_t kh[4];
                ldmatrix4(kh, kb + (16 * g + r8) * 128 + off);
#pragma unroll
                for (int q = 0; q < 2; ++q)
                    mma_f16(sacc[2 * g + q], qa[kg], kh[q], kh[q + 2]);
            }
        }

        // ---- mask tail keys ----
        const int kt0 = t * 64;
        if (kt0 + 64 > len) {
#pragma unroll
            for (int nt = 0; nt < 8; ++nt) {
                int c0 = kt0 + nt * 8 + u2;
                if (c0 >= len)     { sacc[nt][0] = -1e30f; sacc[nt][2] = -1e30f; }
                if (c0 + 1 >= len) { sacc[nt][1] = -1e30f; sacc[nt][3] = -1e30f; }
            }
        }

        // ---- online softmax (rows l/4 and l/4+8; quad shfl reductions) ----
        float mx0 = -1e30f, mx1 = -1e30f;
#pragma unroll
        for (int nt = 0; nt < 8; ++nt) {
            mx0 = fmaxf(mx0, fmaxf(sacc[nt][0], sacc[nt][1]));
            mx1 = fmaxf(mx1, fmaxf(sacc[nt][2], sacc[nt][3]));
        }
        mx0 = fmaxf(mx0, __shfl_xor_sync(0xffffffffu, mx0, 1));
        mx0 = fmaxf(mx0, __shfl_xor_sync(0xffffffffu, mx0, 2));
        mx1 = fmaxf(mx1, __shfl_xor_sync(0xffffffffu, mx1, 1));
        mx1 = fmaxf(mx1, __shfl_xor_sync(0xffffffffu, mx1, 2));

        const float mn0 = fmaxf(m0, mx0), mn1 = fmaxf(m1, mx1);
        const float e0 = ex2f(m0 - mn0), e1 = ex2f(m1 - mn1);
        m0 = mn0; m1 = mn1;

        float s0 = 0.f, s1 = 0.f;
#pragma unroll
        for (int nt = 0; nt < 8; ++nt) {
            float p;
            p = ex2f(sacc[nt][0] - mn0); sacc[nt][0] = p; s0 += p;
            p = ex2f(sacc[nt][1] - mn0); sacc[nt][1] = p; s0 += p;
            p = ex2f(sacc[nt][2] - mn1); sacc[nt][2] = p; s1 += p;
            p = ex2f(sacc[nt][3] - mn1); sacc[nt][3] = p; s1 += p;
        }
        s0 += __shfl_xor_sync(0xffffffffu, s0, 1);
        s0 += __shfl_xor_sync(0xffffffffu, s0, 2);
        s1 += __shfl_xor_sync(0xffffffffu, s1, 1);
        s1 += __shfl_xor_sync(0xffffffffu, s1, 2);
        l0 = l0 * e0 + s0;
        l1 = l1 * e1 + s1;

#pragma unroll
        for (int nt = 0; nt < 8; ++nt) {
            oacc[nt][0] *= e0; oacc[nt][1] *= e0;
            oacc[nt][2] *= e1; oacc[nt][3] *= e1;
        }

        // ---- O += Ph Vh (P fp16-rounded; softmax-bounded error) ----
#pragma unroll
        for (int u = 0; u < 4; ++u) {          // k16 subgroup
            const int g0 = 2 * u;
            uint32_t ph[4];
            __half2 t0 = __floats2half2_rn(sacc[g0][0], sacc[g0][1]);
            __half2 t1 = __floats2half2_rn(sacc[g0][2], sacc[g0][3]);
            __half2 t2 = __floats2half2_rn(sacc[g0 + 1][0], sacc[g0 + 1][1]);
            __half2 t3 = __floats2half2_rn(sacc[g0 + 1][2], sacc[g0 + 1][3]);
            ph[0] = *reinterpret_cast<uint32_t*>(&t0);
            ph[1] = *reinterpret_cast<uint32_t*>(&t1);
            ph[2] = *reinterpret_cast<uint32_t*>(&t2);
            ph[3] = *reinterpret_cast<uint32_t*>(&t3);

            const uint32_t off = 16u * (uint32_t)((2 * u + sh) ^ rx);
#pragma unroll
            for (int dt = 0; dt < 4; ++dt) {
                uint32_t vh[4];
                ldmatrix4(vh, vbuf + (16 * dt + r8) * 128 + off);
#pragma unroll
                for (int q = 0; q < 2; ++q)
                    mma_f16(oacc[2 * dt + q], ph, vh[q], vh[q + 2]);
            }
        }

        if (t + 1 < nkt) cp_wait<0>();
        __syncthreads();
    }

    // ---- write compact ctx hi/lo [b*S+q, 512] ----
    const float inv0 = 1.0f / l0;
    const float inv1 = 1.0f / l1;
    const int qg0 = q0 + 16 * warp + (lane >> 2);
    const int qg1 = qg0 + 8;
    const size_t rb0 = ((size_t)b * S_ + qg0) * 512;
    const size_t rb1 = ((size_t)b * S_ + qg1) * 512;
#pragma unroll
    for (int nt = 0; nt < 8; ++nt) {
        int n = h * 64 + nt * 8 + u2;
        uint32_t hi2, lo2;
        hsplit2(oacc[nt][0] * inv0, oacc[nt][1] * inv0, hi2, lo2);
        *(uint32_t*)&ctxh[rb0 + n] = hi2;
        *(uint32_t*)&ctxl[rb0 + n] = lo2;
        hsplit2(oacc[nt][2] * inv1, oacc[nt][3] * inv1, hi2, lo2);
        *(uint32_t*)&ctxh[rb1 + n] = hi2;
        *(uint32_t*)&ctxl[rb1 + n] = lo2;
    }
}

// ---------------------------------------------------------------------------

extern "C" void kernel_launch(void* const* d_in, const int* in_sizes, int n_in,
                              void* d_out, int out_size)
{
    const float* x_Q = (const float*)d_in[0];
    const float* x_K = (const float*)d_in[1];
    const float* x_V = (const float*)d_in[2];
    const float* Wq  = (const float*)d_in[3];
    const float* bq  = (const float*)d_in[4];
    const float* Wk  = (const float*)d_in[5];
    const float* bk  = (const float*)d_in[6];
    const float* Wv  = (const float*)d_in[7];
    const float* bv  = (const float*)d_in[8];
    const float* Wo  = (const float*)d_in[9];
    const float* bo  = (const float*)d_in[10];
    const int*   lens = (const int*)d_in[11];
    float* out = (float*)d_out;

    unsigned short *xQh, *xKh, *xVh, *Wqh, *Wkh, *Wvh, *Wvl, *Woh, *Wol;
    unsigned short *ctxh, *ctxl, *Qf, *Kf, *Vf;
    cudaGetSymbolAddress((void**)&xQh, g_xQh);
    cudaGetSymbolAddress((void**)&xKh, g_xKh);
    cudaGetSymbolAddress((void**)&xVh, g_xVh);
    cudaGetSymbolAddress((void**)&Wqh, g_Wqh);
    cudaGetSymbolAddress((void**)&Wkh, g_Wkh);
    cudaGetSymbolAddress((void**)&Wvh, g_Wvh);
    cudaGetSymbolAddress((void**)&Wvl, g_Wvl);
    cudaGetSymbolAddress((void**)&Woh, g_Woh);
    cudaGetSymbolAddress((void**)&Wol, g_Wol);
    cudaGetSymbolAddress((void**)&ctxh, g_ctxh);
    cudaGetSymbolAddress((void**)&ctxl, g_ctxl);
    cudaGetSymbolAddress((void**)&Qf,  g_Qf);
    cudaGetSymbolAddress((void**)&Kf,  g_Kf);
    cudaGetSymbolAddress((void**)&Vf,  g_Vf);

    cudaFuncSetAttribute(proj_mma, cudaFuncAttributeMaxDynamicSharedMemorySize, PJ_SMEM_MAX);
    cudaFuncSetAttribute(attn_mma, cudaFuncAttributeMaxDynamicSharedMemorySize, AT_SMEM);

    // ---- pack passes (2 launches) ----
    {
        PackArgs px;
        px.src[0] = x_Q; px.dh[0] = xQh; px.dl[0] = nullptr;
        px.src[1] = x_K; px.dh[1] = xKh; px.dl[1] = nullptr;
        px.src[2] = x_V; px.dh[2] = xVh; px.dl[2] = nullptr;
        px.src[3] = x_Q; px.dh[3] = xQh; px.dl[3] = nullptr;   // unused lane
        px.n = M_ * D_;
        dim3 gx((M_ * D_ / 8 + 255) / 256, 3);
        pack_h16<<<gx, 256>>>(px);

        PackArgs pw;
        pw.src[0] = Wq; pw.dh[0] = Wqh; pw.dl[0] = nullptr;
        pw.src[1] = Wk; pw.dh[1] = Wkh; pw.dl[1] = nullptr;
        pw.src[2] = Wv; pw.dh[2] = Wvh; pw.dl[2] = Wvl;
        pw.src[3] = Wo; pw.dh[3] = Woh; pw.dl[3] = Wol;
        pw.n = D_ * D_;
        dim3 gw((D_ * D_ / 8 + 255) / 256, 4);
        pack_h16<<<gw, 256>>>(pw);
    }

    // scale = 1/sqrt(DH) * log2(e), folded into Q projection (incl. bias)
    const float qscale = 0.125f * 1.4426950408889634f;

    // ---- batched Q/K/V projections (one launch, 3 streams max -> 48KB/stage) ----
    {
        ProjArgs pa;
        pa.Ah[0] = xQh; pa.Al[0] = nullptr; pa.Wh[0] = Wqh; pa.Wl[0] = nullptr;
        pa.bias[0] = bq; pa.out[0] = Qf; pa.scale[0] = qscale; pa.mode[0] = 0; pa.nterm[0] = 1;
        pa.Ah[1] = xKh; pa.Al[1] = nullptr; pa.Wh[1] = Wkh; pa.Wl[1] = nullptr;
        pa.bias[1] = bk; pa.out[1] = Kf; pa.scale[1] = 1.0f;   pa.mode[1] = 0; pa.nterm[1] = 1;
        pa.Ah[2] = xVh; pa.Al[2] = nullptr; pa.Wh[2] = Wvh; pa.Wl[2] = Wvl;
        pa.bias[2] = bv; pa.out[2] = Vf; pa.scale[2] = 1.0f;   pa.mode[2] = 3; pa.nterm[2] = 2;
        dim3 g(D_ / 128, M_ / 128, 3);
        proj_mma<<<g, 512, 3 * 49152>>>(pa, 49152);
    }

    dim3 gattn(S_ / 128, H_, B_);
    attn_mma<<<gattn, 256, AT_SMEM>>>(Qf, Kf, Vf, lens, ctxh, ctxl);

    // ---- final projection (3-term exact, 4 streams -> 64KB/stage) ----
    {
        ProjArgs pa;
        pa.Ah[0] = ctxh; pa.Al[0] = ctxl; pa.Wh[0] = Woh; pa.Wl[0] = Wol;
        pa.bias[0] = bo; pa.out[0] = out; pa.scale[0] = 1.0f; pa.mode[0] = 2; pa.nterm[0] = 3;
        pa.Ah[1] = ctxh; pa.Al[1] = ctxl; pa.Wh[1] = Woh; pa.Wl[1] = Wol;
        pa.bias[1] = bo; pa.out[1] = out; pa.scale[1] = 1.0f; pa.mode[1] = 2; pa.nterm[1] = 3;
        pa.Ah[2] = ctxh; pa.Al[2] = ctxl; pa.Wh[2] = Woh; pa.Wl[2] = Wol;
        pa.bias[2] = bo; pa.out[2] = out; pa.scale[2] = 1.0f; pa.mode[2] = 2; pa.nterm[2] = 3;
        dim3 g(D_ / 128, M_ / 128, 1);
        proj_mma<<<g, 512, 3 * 65536>>>(pa, 65536);
    }
}